// round 1
// baseline (speedup 1.0000x reference)
#include <cuda_runtime.h>
#include <math.h>

#define NN 50000
#define EE 800000
#define NHEADS 8
#define HIDD 32
#define FTOT 256   // NHEADS*HIDD, also IN_FEATS

// ---------------- scratch (static device globals; no allocation) ----------------
__device__ __align__(16) float g_feat[(size_t)NN * FTOT];   // 51.2 MB
__device__ __align__(16) float g_h[(size_t)NN * FTOT];      // 51.2 MB
__device__ __align__(16) float g_feat2[(size_t)NN * HIDD];  // 6.4 MB
__device__ __align__(16) float g_el[NN * NHEADS];
__device__ __align__(16) float g_er[NN * NHEADS];
__device__ int g_count[NN];
__device__ int g_off[NN + 1];
__device__ int g_cursor[NN];
__device__ int g_perm[EE];

// ---------------- CSR build ----------------
__global__ void hist_kernel(const int* __restrict__ dst, int* __restrict__ count) {
    int e = blockIdx.x * blockDim.x + threadIdx.x;
    if (e < EE) atomicAdd(&count[dst[e]], 1);
}

__global__ void scan_kernel(const int* __restrict__ count, int* __restrict__ off,
                            int* __restrict__ cursor) {
    __shared__ int carry;
    __shared__ int tmp[1024];
    int t = threadIdx.x;
    if (t == 0) carry = 0;
    __syncthreads();
    for (int base = 0; base < NN; base += 1024) {
        int i = base + t;
        int v = (i < NN) ? count[i] : 0;
        tmp[t] = v;
        __syncthreads();
        #pragma unroll
        for (int d = 1; d < 1024; d <<= 1) {
            int x = (t >= d) ? tmp[t - d] : 0;
            __syncthreads();
            tmp[t] += x;
            __syncthreads();
        }
        int excl = tmp[t] - v;
        int c = carry;                 // stable: last write was before a sync
        if (i < NN) { off[i] = c + excl; cursor[i] = c + excl; }
        int blocksum = tmp[1023];
        __syncthreads();
        if (t == 0) carry = c + blocksum;
        __syncthreads();
    }
    if (t == 0) off[NN] = carry;
}

__global__ void scatter_kernel(const int* __restrict__ dst, int* __restrict__ cursor,
                               int* __restrict__ perm) {
    int e = blockIdx.x * blockDim.x + threadIdx.x;
    if (e < EE) {
        int pos = atomicAdd(&cursor[dst[e]], 1);
        perm[pos] = e;
    }
}

// ---------------- SGEMM (fp32, row-major A[MxK] * B[KxN] -> C[MxN]) ----------------
template <int BM, int BN, int BK, int TM, int TN>
__global__ void __launch_bounds__((BM / TM) * (BN / TN))
sgemm_kernel(const float* __restrict__ A, const float* __restrict__ B,
             float* __restrict__ C, int M, int Nc, int K) {
    constexpr int TCOLS = BN / TN;
    constexpr int TROWS = BM / TM;
    constexpr int NT = TCOLS * TROWS;
    __shared__ float As[BK][BM];
    __shared__ float Bs[BK][BN];
    const int tid = threadIdx.x;
    const int tr = tid / TCOLS;
    const int tc = tid % TCOLS;
    const int rowBase = blockIdx.y * BM;
    const int colBase = blockIdx.x * BN;

    float acc[TM][TN];
    #pragma unroll
    for (int i = 0; i < TM; i++)
        #pragma unroll
        for (int j = 0; j < TN; j++) acc[i][j] = 0.f;

    for (int k0 = 0; k0 < K; k0 += BK) {
        // A tile: BM x BK, float4 loads, transpose into As[k][m]
        #pragma unroll
        for (int i = tid * 4; i < BM * BK; i += NT * 4) {
            int m = i / BK, kk = i % BK;
            int gr = rowBase + m;
            float4 v = make_float4(0.f, 0.f, 0.f, 0.f);
            if (gr < M) v = *(const float4*)(A + (size_t)gr * K + k0 + kk);
            As[kk + 0][m] = v.x; As[kk + 1][m] = v.y;
            As[kk + 2][m] = v.z; As[kk + 3][m] = v.w;
        }
        // B tile: BK x BN
        #pragma unroll
        for (int i = tid * 4; i < BK * BN; i += NT * 4) {
            int kk = i / BN, nn = i % BN;
            float4 v = *(const float4*)(B + (size_t)(k0 + kk) * Nc + colBase + nn);
            *(float4*)&Bs[kk][nn] = v;
        }
        __syncthreads();
        #pragma unroll
        for (int kk = 0; kk < BK; kk++) {
            float a[TM], b[TN];
            #pragma unroll
            for (int i = 0; i < TM / 4; i++)
                *(float4*)&a[i * 4] = *(const float4*)&As[kk][tr * TM + i * 4];
            #pragma unroll
            for (int j = 0; j < TN / 4; j++)
                *(float4*)&b[j * 4] = *(const float4*)&Bs[kk][tc * TN + j * 4];
            #pragma unroll
            for (int i = 0; i < TM; i++)
                #pragma unroll
                for (int j = 0; j < TN; j++) acc[i][j] = fmaf(a[i], b[j], acc[i][j]);
        }
        __syncthreads();
    }
    #pragma unroll
    for (int i = 0; i < TM; i++) {
        int r = rowBase + tr * TM + i;
        if (r < M) {
            #pragma unroll
            for (int j = 0; j < TN / 4; j++)
                *(float4*)(C + (size_t)r * Nc + colBase + tc * TN + j * 4) =
                    *(float4*)&acc[i][j * 4];
        }
    }
}

// ---------------- el/er: per-(node,head) dual dot of feat row with al/ar ----------------
__global__ void elr8_kernel(const float* __restrict__ feat, const float* __restrict__ al,
                            const float* __restrict__ ar, float* __restrict__ el,
                            float* __restrict__ er) {
    int idx = blockIdx.x * blockDim.x + threadIdx.x;  // n*8 + h
    if (idx >= NN * NHEADS) return;
    int hh = idx & 7;
    const float4* f = (const float4*)(feat + (size_t)idx * HIDD);
    const float4* A = (const float4*)(al + hh * HIDD);
    const float4* B = (const float4*)(ar + hh * HIDD);
    float sl = 0.f, sr = 0.f;
    #pragma unroll
    for (int i = 0; i < HIDD / 4; i++) {
        float4 v = f[i], a = A[i], b = B[i];
        sl += v.x * a.x + v.y * a.y + v.z * a.z + v.w * a.w;
        sr += v.x * b.x + v.y * b.y + v.z * b.z + v.w * b.w;
    }
    el[idx] = sl; er[idx] = sr;
}

__global__ void elr1_kernel(const float* __restrict__ feat2, const float* __restrict__ al,
                            const float* __restrict__ ar, float* __restrict__ el,
                            float* __restrict__ er) {
    int n = blockIdx.x * blockDim.x + threadIdx.x;
    if (n >= NN) return;
    const float4* f = (const float4*)(feat2 + (size_t)n * HIDD);
    const float4* A = (const float4*)al;
    const float4* B = (const float4*)ar;
    float sl = 0.f, sr = 0.f;
    #pragma unroll
    for (int i = 0; i < HIDD / 4; i++) {
        float4 v = f[i], a = A[i], b = B[i];
        sl += v.x * a.x + v.y * a.y + v.z * a.z + v.w * a.w;
        sr += v.x * b.x + v.y * b.y + v.z * b.z + v.w * b.w;
    }
    el[n] = sl; er[n] = sr;
}

// ---------------- per-node warp: segment softmax + aggregate (8 heads) ----------------
__global__ void __launch_bounds__(256)
agg8_kernel(const float* __restrict__ feat, const float* __restrict__ el,
            const float* __restrict__ er, const float* __restrict__ bias,
            float* __restrict__ out, const int* __restrict__ off,
            const int* __restrict__ perm, const int* __restrict__ srcArr) {
    int warp = (blockIdx.x * blockDim.x + threadIdx.x) >> 5;
    if (warp >= NN) return;
    const int lane = threadIdx.x & 31;
    const int n = warp;
    const int s = off[n], epnd = off[n + 1];
    const int hl = lane & 7;       // head handled in softmax phases
    const int eslot = lane >> 3;   // 4 edge-lanes per head
    const float er_h = er[n * NHEADS + hl];

    // pass 1: per-head max over incoming edges
    float mx = -INFINITY;
    for (int i = s + eslot; i < epnd; i += 4) {
        int src = srcArr[perm[i]];
        float v = el[src * NHEADS + hl] + er_h;
        v = v > 0.f ? v : 0.2f * v;
        mx = fmaxf(mx, v);
    }
    mx = fmaxf(mx, __shfl_xor_sync(0xffffffffu, mx, 8));
    mx = fmaxf(mx, __shfl_xor_sync(0xffffffffu, mx, 16));

    // pass 2: per-head sum of exp
    float sm = 0.f;
    for (int i = s + eslot; i < epnd; i += 4) {
        int src = srcArr[perm[i]];
        float v = el[src * NHEADS + hl] + er_h;
        v = v > 0.f ? v : 0.2f * v;
        sm += __expf(v - mx);
    }
    sm += __shfl_xor_sync(0xffffffffu, sm, 8);
    sm += __shfl_xor_sync(0xffffffffu, sm, 16);
    const float inv = 1.0f / (sm + 1e-9f);

    // pass 3: aggregate messages. lane owns dim d=lane across all 8 heads.
    float acc[NHEADS];
    #pragma unroll
    for (int h = 0; h < NHEADS; h++) acc[h] = 0.f;
    for (int i = s; i < epnd; i++) {
        int src = srcArr[perm[i]];
        float coef = 0.f;
        if (lane < 8) {  // for lane<8, hl==lane so mx/inv match head=lane
            float v = el[src * NHEADS + lane] + er_h;
            v = v > 0.f ? v : 0.2f * v;
            coef = __expf(v - mx) * inv;
        }
        const float* frow = feat + (size_t)src * FTOT;
        #pragma unroll
        for (int h = 0; h < NHEADS; h++) {
            float a = __shfl_sync(0xffffffffu, coef, h);
            acc[h] = fmaf(a, frow[h * HIDD + lane], acc[h]);
        }
    }
    // epilogue: +bias, ELU, write [n, h*32+lane]
    #pragma unroll
    for (int h = 0; h < NHEADS; h++) {
        float v = acc[h] + bias[h * HIDD + lane];
        v = v > 0.f ? v : expm1f(v);
        out[(size_t)n * FTOT + h * HIDD + lane] = v;
    }
}

// ---------------- per-node warp: final layer (1 head, D=32, no activation) ----------------
__global__ void __launch_bounds__(256)
agg1_kernel(const float* __restrict__ feat2, const float* __restrict__ el,
            const float* __restrict__ er, const float* __restrict__ bias,
            float* __restrict__ out, const int* __restrict__ off,
            const int* __restrict__ perm, const int* __restrict__ srcArr) {
    int warp = (blockIdx.x * blockDim.x + threadIdx.x) >> 5;
    if (warp >= NN) return;
    const int lane = threadIdx.x & 31;
    const int n = warp;
    const int s = off[n], epnd = off[n + 1];
    const float er_n = er[n];

    float mx = -INFINITY;
    for (int i = s + lane; i < epnd; i += 32) {
        int src = srcArr[perm[i]];
        float v = el[src] + er_n;
        v = v > 0.f ? v : 0.2f * v;
        mx = fmaxf(mx, v);
    }
    #pragma unroll
    for (int d = 16; d >= 1; d >>= 1) mx = fmaxf(mx, __shfl_xor_sync(0xffffffffu, mx, d));

    float sm = 0.f;
    for (int i = s + lane; i < epnd; i += 32) {
        int src = srcArr[perm[i]];
        float v = el[src] + er_n;
        v = v > 0.f ? v : 0.2f * v;
        sm += __expf(v - mx);
    }
    #pragma unroll
    for (int d = 16; d >= 1; d >>= 1) sm += __shfl_xor_sync(0xffffffffu, sm, d);
    const float inv = 1.0f / (sm + 1e-9f);

    float acc = 0.f;
    for (int i = s; i < epnd; i++) {
        int src = srcArr[perm[i]];
        float v = el[src] + er_n;       // broadcast load, redundant per lane (cheap)
        v = v > 0.f ? v : 0.2f * v;
        float coef = __expf(v - mx) * inv;
        acc = fmaf(coef, feat2[(size_t)src * HIDD + lane], acc);
    }
    out[(size_t)n * HIDD + lane] = acc + bias[lane];
}

// ---------------- launch ----------------
extern "C" void kernel_launch(void* const* d_in, const int* in_sizes, int n_in,
                              void* d_out, int out_size) {
    const float* features = (const float*)d_in[0];
    const int*   src      = (const int*)d_in[1];
    const int*   dst      = (const int*)d_in[2];
    const float* W0  = (const float*)d_in[3];
    const float* al0 = (const float*)d_in[4];
    const float* ar0 = (const float*)d_in[5];
    const float* b0  = (const float*)d_in[6];
    const float* W1  = (const float*)d_in[7];
    const float* al1 = (const float*)d_in[8];
    const float* ar1 = (const float*)d_in[9];
    const float* b1  = (const float*)d_in[10];
    const float* W2  = (const float*)d_in[11];
    const float* al2 = (const float*)d_in[12];
    const float* ar2 = (const float*)d_in[13];
    const float* b2  = (const float*)d_in[14];
    float* out = (float*)d_out;

    float *feat, *h, *feat2, *el, *er;
    int *count, *off, *cursor, *perm;
    cudaGetSymbolAddress((void**)&feat,   g_feat);
    cudaGetSymbolAddress((void**)&h,      g_h);
    cudaGetSymbolAddress((void**)&feat2,  g_feat2);
    cudaGetSymbolAddress((void**)&el,     g_el);
    cudaGetSymbolAddress((void**)&er,     g_er);
    cudaGetSymbolAddress((void**)&count,  g_count);
    cudaGetSymbolAddress((void**)&off,    g_off);
    cudaGetSymbolAddress((void**)&cursor, g_cursor);
    cudaGetSymbolAddress((void**)&perm,   g_perm);

    // CSR by dst (rebuilt every call; int atomics only)
    cudaMemsetAsync(count, 0, NN * sizeof(int));
    hist_kernel<<<(EE + 255) / 256, 256>>>(dst, count);
    scan_kernel<<<1, 1024>>>(count, off, cursor);
    scatter_kernel<<<(EE + 255) / 256, 256>>>(dst, cursor, perm);

    const int aggBlocks = (NN * 32 + 255) / 256;
    dim3 gemmBig(FTOT / 128, (NN + 127) / 128);
    dim3 gemmSmall(1, (NN + 127) / 128);

    // layer 0
    sgemm_kernel<128, 128, 16, 8, 8><<<gemmBig, 256>>>(features, W0, feat, NN, FTOT, FTOT);
    elr8_kernel<<<(NN * NHEADS + 255) / 256, 256>>>(feat, al0, ar0, el, er);
    agg8_kernel<<<aggBlocks, 256>>>(feat, el, er, b0, h, off, perm, src);

    // layer 1
    sgemm_kernel<128, 128, 16, 8, 8><<<gemmBig, 256>>>(h, W1, feat, NN, FTOT, FTOT);
    elr8_kernel<<<(NN * NHEADS + 255) / 256, 256>>>(feat, al1, ar1, el, er);
    agg8_kernel<<<aggBlocks, 256>>>(feat, el, er, b1, h, off, perm, src);

    // layer 2 (single head, D=32, no activation; mean over 1 head = identity)
    sgemm_kernel<128, 32, 32, 8, 4><<<gemmSmall, 128>>>(h, W2, feat2, NN, HIDD, FTOT);
    elr1_kernel<<<(NN + 255) / 256, 256>>>(feat2, al2, ar2, el, er);
    agg1_kernel<<<aggBlocks, 256>>>(feat2, el, er, b2, out, off, perm, src);
}

// round 4
// speedup vs baseline: 1.2640x; 1.2640x over previous
#include <cuda_runtime.h>
#include <cuda_bf16.h>
#include <math.h>
#include <stdint.h>

#define NN 50000
#define EE 800000
#define NHEADS 8
#define HIDD 32
#define FTOT 256   // NHEADS*HIDD, also IN_FEATS

// ---------------- scratch (static device globals; no allocation) ----------------
__device__ __align__(16) float g_feat[(size_t)NN * FTOT];   // 51.2 MB
__device__ __align__(16) float g_h[(size_t)NN * FTOT];      // 51.2 MB
__device__ __align__(16) float g_feat2[(size_t)NN * HIDD];  // 6.4 MB
__device__ __align__(16) float g_el[NN * NHEADS];
__device__ __align__(16) float g_er[NN * NHEADS];
__device__ int g_count[NN];
__device__ int g_off[NN + 1];
__device__ int g_cursor[NN];
__device__ int g_perm[EE];

// ---------------- helpers ----------------
__device__ __forceinline__ uint32_t smem_u32(const void* p) {
    uint32_t a;
    asm("{ .reg .u64 t; cvta.to.shared.u64 t, %1; cvt.u32.u64 %0, t; }" : "=r"(a) : "l"(p));
    return a;
}
__device__ __forceinline__ void ldsm_x4(uint32_t addr, uint32_t& r0, uint32_t& r1,
                                        uint32_t& r2, uint32_t& r3) {
    asm volatile("ldmatrix.sync.aligned.m8n8.x4.shared.b16 {%0,%1,%2,%3}, [%4];"
                 : "=r"(r0), "=r"(r1), "=r"(r2), "=r"(r3) : "r"(addr));
}
__device__ __forceinline__ void mma_bf16(float* d, const uint32_t* a, const uint32_t* b) {
    asm volatile(
        "mma.sync.aligned.m16n8k16.row.col.f32.bf16.bf16.f32 "
        "{%0,%1,%2,%3}, {%4,%5,%6,%7}, {%8,%9}, {%0,%1,%2,%3};"
        : "+f"(d[0]), "+f"(d[1]), "+f"(d[2]), "+f"(d[3])
        : "r"(a[0]), "r"(a[1]), "r"(a[2]), "r"(a[3]), "r"(b[0]), "r"(b[1]));
}
__device__ __forceinline__ uint32_t pack2bf(float a, float b) {
    __nv_bfloat162 t = __floats2bfloat162_rn(a, b);
    return *(uint32_t*)&t;
}
__device__ __forceinline__ float bf_hi(float x) {
    return __bfloat162float(__float2bfloat16_rn(x));
}

// ---------------- mma.sync split-bf16 GEMM: C[M x 256] = A[M x 256] * W[256 x 256]
// CTA tile 128x128, 8 warps (warp tile 64x32), BK=32 double-buffered.
// SMEM rows padded to 40 halfs (80B) -> ldmatrix conflict-free.
#define SP 40                      // smem row pitch in halfs
#define TILE_H (128 * SP)          // halfs per logical tile
// layout per buffer: As_hi | As_lo | Bs_hi | Bs_lo, each TILE_H halfs
#define BUF_H (4 * TILE_H)
#define GEMM_SMEM (2 * BUF_H * 2)  // bytes

__global__ void __launch_bounds__(256, 1)
mma_gemm_kernel(const float* __restrict__ A, const float* __restrict__ W,
                float* __restrict__ C, int M) {
    extern __shared__ __half2 smem_raw[];
    uint16_t* smem = (uint16_t*)smem_raw;
    const int tid = threadIdx.x;
    const int wid = tid >> 5;
    const int lane = tid & 31;
    const int rowBase = blockIdx.y * 128;
    const int colBase = blockIdx.x * 128;
    const int mbase = (wid >> 2) * 64;   // warpM in {0,1}
    const int nbase = (wid & 3) * 32;    // warpN in {0..3}

    float acc[4][4][4];
    #pragma unroll
    for (int i = 0; i < 4; i++)
        #pragma unroll
        for (int j = 0; j < 4; j++)
            #pragma unroll
            for (int q = 0; q < 4; q++) acc[i][j][q] = 0.f;

    // per-thread load coords
    const int arow = tid >> 1;            // A: 2 threads per row
    const int akq  = (tid & 1) * 4;       // first float4 index of this thread's 4
    const int bn   = tid & 127;           // B: output column within tile
    const int bkh  = (tid >> 7) * 16;     // k-half within chunk

    float4 pfA[4];
    float pfB[16];

    // prefetch chunk 0
    {
        int gr = rowBase + arow;
        const float4 z = make_float4(0.f, 0.f, 0.f, 0.f);
        #pragma unroll
        for (int p = 0; p < 4; p++)
            pfA[p] = (gr < M) ? *(const float4*)(A + (size_t)gr * FTOT + (akq + p) * 4) : z;
        #pragma unroll
        for (int j = 0; j < 16; j++)
            pfB[j] = W[(size_t)(bkh + j) * FTOT + colBase + bn];
    }

    for (int c = 0; c < 8; c++) {
        const int b = c & 1;
        uint16_t* As_hi = smem + b * BUF_H;
        uint16_t* As_lo = As_hi + TILE_H;
        uint16_t* Bs_hi = As_lo + TILE_H;
        uint16_t* Bs_lo = Bs_hi + TILE_H;

        // convert + store prefetched chunk c into buffer b
        {
            #pragma unroll
            for (int p = 0; p < 4; p++) {
                float4 v = pfA[p];
                float h0 = bf_hi(v.x), h1 = bf_hi(v.y), h2 = bf_hi(v.z), h3 = bf_hi(v.w);
                uint32_t* dh = (uint32_t*)(As_hi + arow * SP + (akq + p) * 4);
                uint32_t* dl = (uint32_t*)(As_lo + arow * SP + (akq + p) * 4);
                dh[0] = pack2bf(h0, h1); dh[1] = pack2bf(h2, h3);
                dl[0] = pack2bf(v.x - h0, v.y - h1); dl[1] = pack2bf(v.z - h2, v.w - h3);
            }
            #pragma unroll
            for (int j = 0; j < 8; j++) {
                float x0 = pfB[2 * j], x1 = pfB[2 * j + 1];
                float h0 = bf_hi(x0), h1 = bf_hi(x1);
                *(uint32_t*)(Bs_hi + bn * SP + bkh + 2 * j) = pack2bf(h0, h1);
                *(uint32_t*)(Bs_lo + bn * SP + bkh + 2 * j) = pack2bf(x0 - h0, x1 - h1);
            }
        }
        __syncthreads();

        // prefetch chunk c+1
        if (c < 7) {
            int gr = rowBase + arow;
            const float4 z = make_float4(0.f, 0.f, 0.f, 0.f);
            const float* Ab = A + (size_t)gr * FTOT + (c + 1) * 32;
            #pragma unroll
            for (int p = 0; p < 4; p++)
                pfA[p] = (gr < M) ? *(const float4*)(Ab + (akq + p) * 4) : z;
            #pragma unroll
            for (int j = 0; j < 16; j++)
                pfB[j] = W[(size_t)((c + 1) * 32 + bkh + j) * FTOT + colBase + bn];
        }

        // compute chunk c: two k16 steps
        const uint32_t as_hi = smem_u32(As_hi);
        const uint32_t as_lo = smem_u32(As_lo);
        const uint32_t bs_hi = smem_u32(Bs_hi);
        const uint32_t bs_lo = smem_u32(Bs_lo);
        const int t = lane >> 3, r = lane & 7;
        #pragma unroll
        for (int ks = 0; ks < 2; ks++) {
            uint32_t Ah[4][4], Al[4][4], Bh[4][2], Bl[4][2];
            // A frags: tiles (t&1)->row half, (t>>1)->k half
            const int a_row_off = (t & 1) * 8 + r;
            const int a_col = ks * 16 + (t >> 1) * 8;
            #pragma unroll
            for (int f = 0; f < 4; f++) {
                uint32_t off = ((mbase + f * 16 + a_row_off) * SP + a_col) * 2;
                ldsm_x4(as_hi + off, Ah[f][0], Ah[f][1], Ah[f][2], Ah[f][3]);
                ldsm_x4(as_lo + off, Al[f][0], Al[f][1], Al[f][2], Al[f][3]);
            }
            // B frags: x4 covers two n8 blocks; tiles: (t>>1)->n half, (t&1)->k half
            const int b_row_off = (t >> 1) * 8 + r;
            const int b_col = ks * 16 + (t & 1) * 8;
            #pragma unroll
            for (int g = 0; g < 2; g++) {
                uint32_t off = ((nbase + g * 16 + b_row_off) * SP + b_col) * 2;
                ldsm_x4(bs_hi + off, Bh[2 * g][0], Bh[2 * g][1], Bh[2 * g + 1][0], Bh[2 * g + 1][1]);
                ldsm_x4(bs_lo + off, Bl[2 * g][0], Bl[2 * g][1], Bl[2 * g + 1][0], Bl[2 * g + 1][1]);
            }
            #pragma unroll
            for (int i = 0; i < 4; i++)
                #pragma unroll
                for (int j = 0; j < 4; j++) {
                    mma_bf16(acc[i][j], Ah[i], Bh[j]);
                    mma_bf16(acc[i][j], Al[i], Bh[j]);
                    mma_bf16(acc[i][j], Ah[i], Bl[j]);
                }
        }
        __syncthreads();
    }

    // epilogue: fragment -> global (float2 stores)
    const int rq = lane >> 2;
    const int cq = (lane & 3) * 2;
    #pragma unroll
    for (int i = 0; i < 4; i++) {
        int r0 = rowBase + mbase + i * 16 + rq;
        int r1 = r0 + 8;
        #pragma unroll
        for (int j = 0; j < 4; j++) {
            int cc = colBase + nbase + j * 8 + cq;
            if (r0 < M) *(float2*)(C + (size_t)r0 * FTOT + cc) = make_float2(acc[i][j][0], acc[i][j][1]);
            if (r1 < M) *(float2*)(C + (size_t)r1 * FTOT + cc) = make_float2(acc[i][j][2], acc[i][j][3]);
        }
    }
}

// ---------------- CSR build ----------------
__global__ void hist_kernel(const int* __restrict__ dst, int* __restrict__ count) {
    int e = blockIdx.x * blockDim.x + threadIdx.x;
    if (e < EE) atomicAdd(&count[dst[e]], 1);
}

__global__ void scan_kernel(const int* __restrict__ count, int* __restrict__ off,
                            int* __restrict__ cursor) {
    __shared__ int carry;
    __shared__ int tmp[1024];
    int t = threadIdx.x;
    if (t == 0) carry = 0;
    __syncthreads();
    for (int base = 0; base < NN; base += 1024) {
        int i = base + t;
        int v = (i < NN) ? count[i] : 0;
        tmp[t] = v;
        __syncthreads();
        #pragma unroll
        for (int d = 1; d < 1024; d <<= 1) {
            int x = (t >= d) ? tmp[t - d] : 0;
            __syncthreads();
            tmp[t] += x;
            __syncthreads();
        }
        int excl = tmp[t] - v;
        int c = carry;
        if (i < NN) { off[i] = c + excl; cursor[i] = c + excl; }
        int blocksum = tmp[1023];
        __syncthreads();
        if (t == 0) carry = c + blocksum;
        __syncthreads();
    }
    if (t == 0) off[NN] = carry;
}

__global__ void scatter_kernel(const int* __restrict__ dst, int* __restrict__ cursor,
                               int* __restrict__ perm) {
    int e = blockIdx.x * blockDim.x + threadIdx.x;
    if (e < EE) {
        int pos = atomicAdd(&cursor[dst[e]], 1);
        perm[pos] = e;
    }
}

// ---------------- SGEMM (fp32) for the small final layer ----------------
template <int BM, int BN, int BK, int TM, int TN>
__global__ void __launch_bounds__((BM / TM) * (BN / TN))
sgemm_kernel(const float* __restrict__ A, const float* __restrict__ B,
             float* __restrict__ C, int M, int Nc, int K) {
    constexpr int TCOLS = BN / TN;
    constexpr int NT = (BM / TM) * TCOLS;
    __shared__ float As[BK][BM];
    __shared__ float Bs[BK][BN];
    const int tid = threadIdx.x;
    const int tr = tid / TCOLS;
    const int tc = tid % TCOLS;
    const int rowBase = blockIdx.y * BM;
    const int colBase = blockIdx.x * BN;

    float acc[TM][TN];
    #pragma unroll
    for (int i = 0; i < TM; i++)
        #pragma unroll
        for (int j = 0; j < TN; j++) acc[i][j] = 0.f;

    for (int k0 = 0; k0 < K; k0 += BK) {
        #pragma unroll
        for (int i = tid * 4; i < BM * BK; i += NT * 4) {
            int m = i / BK, kk = i % BK;
            int gr = rowBase + m;
            float4 v = make_float4(0.f, 0.f, 0.f, 0.f);
            if (gr < M) v = *(const float4*)(A + (size_t)gr * K + k0 + kk);
            As[kk + 0][m] = v.x; As[kk + 1][m] = v.y;
            As[kk + 2][m] = v.z; As[kk + 3][m] = v.w;
        }
        #pragma unroll
        for (int i = tid * 4; i < BK * BN; i += NT * 4) {
            int kk = i / BN, nn = i % BN;
            float4 v = *(const float4*)(B + (size_t)(k0 + kk) * Nc + colBase + nn);
            *(float4*)&Bs[kk][nn] = v;
        }
        __syncthreads();
        #pragma unroll
        for (int kk = 0; kk < BK; kk++) {
            float a[TM], b[TN];
            #pragma unroll
            for (int i = 0; i < TM / 4; i++)
                *(float4*)&a[i * 4] = *(const float4*)&As[kk][tr * TM + i * 4];
            #pragma unroll
            for (int j = 0; j < TN / 4; j++)
                *(float4*)&b[j * 4] = *(const float4*)&Bs[kk][tc * TN + j * 4];
            #pragma unroll
            for (int i = 0; i < TM; i++)
                #pragma unroll
                for (int j = 0; j < TN; j++) acc[i][j] = fmaf(a[i], b[j], acc[i][j]);
        }
        __syncthreads();
    }
    #pragma unroll
    for (int i = 0; i < TM; i++) {
        int r = rowBase + tr * TM + i;
        if (r < M) {
            #pragma unroll
            for (int j = 0; j < TN / 4; j++)
                *(float4*)(C + (size_t)r * Nc + colBase + tc * TN + j * 4) =
                    *(float4*)&acc[i][j * 4];
        }
    }
}

// ---------------- el/er dot products ----------------
__global__ void elr8_kernel(const float* __restrict__ feat, const float* __restrict__ al,
                            const float* __restrict__ ar, float* __restrict__ el,
                            float* __restrict__ er) {
    int idx = blockIdx.x * blockDim.x + threadIdx.x;  // n*8 + h
    if (idx >= NN * NHEADS) return;
    int hh = idx & 7;
    const float4* f = (const float4*)(feat + (size_t)idx * HIDD);
    const float4* A = (const float4*)(al + hh * HIDD);
    const float4* B = (const float4*)(ar + hh * HIDD);
    float sl = 0.f, sr = 0.f;
    #pragma unroll
    for (int i = 0; i < HIDD / 4; i++) {
        float4 v = f[i], a = A[i], b = B[i];
        sl += v.x * a.x + v.y * a.y + v.z * a.z + v.w * a.w;
        sr += v.x * b.x + v.y * b.y + v.z * b.z + v.w * b.w;
    }
    el[idx] = sl; er[idx] = sr;
}

__global__ void elr1_kernel(const float* __restrict__ feat2, const float* __restrict__ al,
                            const float* __restrict__ ar, float* __restrict__ el,
                            float* __restrict__ er) {
    int n = blockIdx.x * blockDim.x + threadIdx.x;
    if (n >= NN) return;
    const float4* f = (const float4*)(feat2 + (size_t)n * HIDD);
    const float4* A = (const float4*)al;
    const float4* B = (const float4*)ar;
    float sl = 0.f, sr = 0.f;
    #pragma unroll
    for (int i = 0; i < HIDD / 4; i++) {
        float4 v = f[i], a = A[i], b = B[i];
        sl += v.x * a.x + v.y * a.y + v.z * a.z + v.w * a.w;
        sr += v.x * b.x + v.y * b.y + v.z * b.z + v.w * b.w;
    }
    el[n] = sl; er[n] = sr;
}

// ---------------- per-node warp: segment softmax + aggregate (8 heads) ----------------
__global__ void __launch_bounds__(256)
agg8_kernel(const float* __restrict__ feat, const float* __restrict__ el,
            const float* __restrict__ er, const float* __restrict__ bias,
            float* __restrict__ out, const int* __restrict__ off,
            const int* __restrict__ perm, const int* __restrict__ srcArr) {
    int warp = (blockIdx.x * blockDim.x + threadIdx.x) >> 5;
    if (warp >= NN) return;
    const int lane = threadIdx.x & 31;
    const int n = warp;
    const int s = off[n], epnd = off[n + 1];
    const int hl = lane & 7;
    const int eslot = lane >> 3;
    const float er_h = er[n * NHEADS + hl];

    float mx = -INFINITY;
    for (int i = s + eslot; i < epnd; i += 4) {
        int src = srcArr[perm[i]];
        float v = el[src * NHEADS + hl] + er_h;
        v = v > 0.f ? v : 0.2f * v;
        mx = fmaxf(mx, v);
    }
    mx = fmaxf(mx, __shfl_xor_sync(0xffffffffu, mx, 8));
    mx = fmaxf(mx, __shfl_xor_sync(0xffffffffu, mx, 16));

    float sm = 0.f;
    for (int i = s + eslot; i < epnd; i += 4) {
        int src = srcArr[perm[i]];
        float v = el[src * NHEADS + hl] + er_h;
        v = v > 0.f ? v : 0.2f * v;
        sm += __expf(v - mx);
    }
    sm += __shfl_xor_sync(0xffffffffu, sm, 8);
    sm += __shfl_xor_sync(0xffffffffu, sm, 16);
    const float inv = 1.0f / (sm + 1e-9f);

    float acc[NHEADS];
    #pragma unroll
    for (int h = 0; h < NHEADS; h++) acc[h] = 0.f;
    for (int i = s; i < epnd; i++) {
        int src = srcArr[perm[i]];
        float coef = 0.f;
        if (lane < 8) {
            float v = el[src * NHEADS + lane] + er_h;
            v = v > 0.f ? v : 0.2f * v;
            coef = __expf(v - mx) * inv;
        }
        const float* frow = feat + (size_t)src * FTOT;
        #pragma unroll
        for (int h = 0; h < NHEADS; h++) {
            float a = __shfl_sync(0xffffffffu, coef, h);
            acc[h] = fmaf(a, frow[h * HIDD + lane], acc[h]);
        }
    }
    #pragma unroll
    for (int h = 0; h < NHEADS; h++) {
        float v = acc[h] + bias[h * HIDD + lane];
        v = v > 0.f ? v : expm1f(v);
        out[(size_t)n * FTOT + h * HIDD + lane] = v;
    }
}

// ---------------- final layer aggregate (1 head, D=32) ----------------
__global__ void __launch_bounds__(256)
agg1_kernel(const float* __restrict__ feat2, const float* __restrict__ el,
            const float* __restrict__ er, const float* __restrict__ bias,
            float* __restrict__ out, const int* __restrict__ off,
            const int* __restrict__ perm, const int* __restrict__ srcArr) {
    int warp = (blockIdx.x * blockDim.x + threadIdx.x) >> 5;
    if (warp >= NN) return;
    const int lane = threadIdx.x & 31;
    const int n = warp;
    const int s = off[n], epnd = off[n + 1];
    const float er_n = er[n];

    float mx = -INFINITY;
    for (int i = s + lane; i < epnd; i += 32) {
        int src = srcArr[perm[i]];
        float v = el[src] + er_n;
        v = v > 0.f ? v : 0.2f * v;
        mx = fmaxf(mx, v);
    }
    #pragma unroll
    for (int d = 16; d >= 1; d >>= 1) mx = fmaxf(mx, __shfl_xor_sync(0xffffffffu, mx, d));

    float sm = 0.f;
    for (int i = s + lane; i < epnd; i += 32) {
        int src = srcArr[perm[i]];
        float v = el[src] + er_n;
        v = v > 0.f ? v : 0.2f * v;
        sm += __expf(v - mx);
    }
    #pragma unroll
    for (int d = 16; d >= 1; d >>= 1) sm += __shfl_xor_sync(0xffffffffu, sm, d);
    const float inv = 1.0f / (sm + 1e-9f);

    float acc = 0.f;
    for (int i = s; i < epnd; i++) {
        int src = srcArr[perm[i]];
        float v = el[src] + er_n;
        v = v > 0.f ? v : 0.2f * v;
        float coef = __expf(v - mx) * inv;
        acc = fmaf(coef, feat2[(size_t)src * HIDD + lane], acc);
    }
    out[(size_t)n * HIDD + lane] = acc + bias[lane];
}

// ---------------- launch ----------------
extern "C" void kernel_launch(void* const* d_in, const int* in_sizes, int n_in,
                              void* d_out, int out_size) {
    const float* features = (const float*)d_in[0];
    const int*   src      = (const int*)d_in[1];
    const int*   dst      = (const int*)d_in[2];
    const float* W0  = (const float*)d_in[3];
    const float* al0 = (const float*)d_in[4];
    const float* ar0 = (const float*)d_in[5];
    const float* b0  = (const float*)d_in[6];
    const float* W1  = (const float*)d_in[7];
    const float* al1 = (const float*)d_in[8];
    const float* ar1 = (const float*)d_in[9];
    const float* b1  = (const float*)d_in[10];
    const float* W2  = (const float*)d_in[11];
    const float* al2 = (const float*)d_in[12];
    const float* ar2 = (const float*)d_in[13];
    const float* b2  = (const float*)d_in[14];
    float* out = (float*)d_out;

    float *feat, *h, *feat2, *el, *er;
    int *count, *off, *cursor, *perm;
    cudaGetSymbolAddress((void**)&feat,   g_feat);
    cudaGetSymbolAddress((void**)&h,      g_h);
    cudaGetSymbolAddress((void**)&feat2,  g_feat2);
    cudaGetSymbolAddress((void**)&el,     g_el);
    cudaGetSymbolAddress((void**)&er,     g_er);
    cudaGetSymbolAddress((void**)&count,  g_count);
    cudaGetSymbolAddress((void**)&off,    g_off);
    cudaGetSymbolAddress((void**)&cursor, g_cursor);
    cudaGetSymbolAddress((void**)&perm,   g_perm);

    cudaFuncSetAttribute(mma_gemm_kernel, cudaFuncAttributeMaxDynamicSharedMemorySize,
                         GEMM_SMEM);

    // CSR by dst
    cudaMemsetAsync(count, 0, NN * sizeof(int));
    hist_kernel<<<(EE + 255) / 256, 256>>>(dst, count);
    scan_kernel<<<1, 1024>>>(count, off, cursor);
    scatter_kernel<<<(EE + 255) / 256, 256>>>(dst, cursor, perm);

    const int aggBlocks = (NN * 32 + 255) / 256;
    dim3 gemmGrid(2, (NN + 127) / 128);
    dim3 gemmSmall(1, (NN + 127) / 128);

    // layer 0
    mma_gemm_kernel<<<gemmGrid, 256, GEMM_SMEM>>>(features, W0, feat, NN);
    elr8_kernel<<<(NN * NHEADS + 255) / 256, 256>>>(feat, al0, ar0, el, er);
    agg8_kernel<<<aggBlocks, 256>>>(feat, el, er, b0, h, off, perm, src);

    // layer 1
    mma_gemm_kernel<<<gemmGrid, 256, GEMM_SMEM>>>(h, W1, feat, NN);
    elr8_kernel<<<(NN * NHEADS + 255) / 256, 256>>>(feat, al1, ar1, el, er);
    agg8_kernel<<<aggBlocks, 256>>>(feat, el, er, b1, h, off, perm, src);

    // layer 2 (single head, D=32, no activation)
    sgemm_kernel<128, 32, 32, 8, 4><<<gemmSmall, 128>>>(h, W2, feat2, NN, HIDD, FTOT);
    elr1_kernel<<<(NN + 255) / 256, 256>>>(feat2, al2, ar2, el, er);
    agg1_kernel<<<aggBlocks, 256>>>(feat2, el, er, b2, out, off, perm, src);
}

// round 6
// speedup vs baseline: 1.7595x; 1.3920x over previous
#include <cuda_runtime.h>
#include <cuda_bf16.h>
#include <math.h>
#include <stdint.h>

#define NN 50000
#define EE 800000
#define NHEADS 8
#define HIDD 32
#define FTOT 256   // NHEADS*HIDD, also IN_FEATS

// ---------------- scratch (static device globals; no allocation) ----------------
__device__ __align__(16) float g_feat[(size_t)NN * FTOT];   // 51.2 MB
__device__ __align__(16) float g_h[(size_t)NN * FTOT];      // 51.2 MB
__device__ __align__(16) float g_feat2[(size_t)NN * HIDD];  // 6.4 MB
__device__ __align__(16) float g_el[NN * NHEADS];
__device__ __align__(16) float g_er[NN * NHEADS];
__device__ int g_count[NN];
__device__ int g_off[NN + 1];
__device__ int g_cursor[NN];
__device__ int g_srcs[EE];    // src node of each edge, sorted by dst

// ---------------- helpers ----------------
__device__ __forceinline__ uint32_t smem_u32(const void* p) {
    uint32_t a;
    asm("{ .reg .u64 t; cvta.to.shared.u64 t, %1; cvt.u32.u64 %0, t; }" : "=r"(a) : "l"(p));
    return a;
}
__device__ __forceinline__ void ldsm_x4(uint32_t addr, uint32_t& r0, uint32_t& r1,
                                        uint32_t& r2, uint32_t& r3) {
    asm volatile("ldmatrix.sync.aligned.m8n8.x4.shared.b16 {%0,%1,%2,%3}, [%4];"
                 : "=r"(r0), "=r"(r1), "=r"(r2), "=r"(r3) : "r"(addr));
}
__device__ __forceinline__ void mma_bf16(float* d, const uint32_t* a, const uint32_t* b) {
    asm volatile(
        "mma.sync.aligned.m16n8k16.row.col.f32.bf16.bf16.f32 "
        "{%0,%1,%2,%3}, {%4,%5,%6,%7}, {%8,%9}, {%0,%1,%2,%3};"
        : "+f"(d[0]), "+f"(d[1]), "+f"(d[2]), "+f"(d[3])
        : "r"(a[0]), "r"(a[1]), "r"(a[2]), "r"(a[3]), "r"(b[0]), "r"(b[1]));
}
__device__ __forceinline__ uint32_t pack2bf(float a, float b) {
    __nv_bfloat162 t = __floats2bfloat162_rn(a, b);
    return *(uint32_t*)&t;
}
__device__ __forceinline__ float bf_hi(float x) {
    return __bfloat162float(__float2bfloat16_rn(x));
}
// exp argument guard: fmaxf(NaN, -88) = -88, so (-inf) - (-inf) merges stay finite
__device__ __forceinline__ float safe_exp(float x) {
    return __expf(fmaxf(x, -88.f));
}

// ---------------- mma.sync split-bf16 GEMM: C[M x 256] = A[M x 256] * W[256 x 256]
// CTA tile 128x128, 8 warps (warp tile 64x32 = one head wide), BK=32 double-buffered.
// Single barrier per chunk; global prefetch overlaps MMA. Fused el/er epilogue.
#define SP 40                      // smem row pitch in halfs
#define TILE_H (128 * SP)          // halfs per logical tile
#define BUF_H (4 * TILE_H)         // As_hi | As_lo | Bs_hi | Bs_lo
#define GEMM_SMEM (2 * BUF_H * 2)  // bytes

__global__ void __launch_bounds__(256, 1)
mma_gemm_kernel(const float* __restrict__ A, const float* __restrict__ W,
                float* __restrict__ C, const float* __restrict__ al,
                const float* __restrict__ ar, float* __restrict__ el,
                float* __restrict__ er, int M) {
    extern __shared__ __half2 smem_raw[];
    uint16_t* smem = (uint16_t*)smem_raw;
    const int tid = threadIdx.x;
    const int wid = tid >> 5;
    const int lane = tid & 31;
    const int rowBase = blockIdx.y * 128;
    const int colBase = blockIdx.x * 128;
    const int mbase = (wid >> 2) * 64;   // warpM in {0,1}
    const int nbase = (wid & 3) * 32;    // warpN in {0..3} == head within tile

    float acc[4][4][4];
    #pragma unroll
    for (int i = 0; i < 4; i++)
        #pragma unroll
        for (int j = 0; j < 4; j++)
            #pragma unroll
            for (int q = 0; q < 4; q++) acc[i][j][q] = 0.f;

    // per-thread load coords
    const int arow = tid >> 1;            // A: 2 threads per row
    const int akq  = (tid & 1) * 4;       // first float4 index of this thread's 4
    const int bn   = tid & 127;           // B: output column within tile
    const int bkh  = (tid >> 7) * 16;     // k-half within chunk

    float4 pfA[4];
    float pfB[16];

    // prefetch chunk 0
    {
        int gr = rowBase + arow;
        const float4 z = make_float4(0.f, 0.f, 0.f, 0.f);
        #pragma unroll
        for (int p = 0; p < 4; p++)
            pfA[p] = (gr < M) ? *(const float4*)(A + (size_t)gr * FTOT + (akq + p) * 4) : z;
        #pragma unroll
        for (int j = 0; j < 16; j++)
            pfB[j] = W[(size_t)(bkh + j) * FTOT + colBase + bn];
    }

    for (int c = 0; c < 8; c++) {
        const int b = c & 1;
        uint16_t* As_hi = smem + b * BUF_H;
        uint16_t* As_lo = As_hi + TILE_H;
        uint16_t* Bs_hi = As_lo + TILE_H;
        uint16_t* Bs_lo = Bs_hi + TILE_H;

        // convert + store prefetched chunk c into buffer b
        {
            #pragma unroll
            for (int p = 0; p < 4; p++) {
                float4 v = pfA[p];
                float h0 = bf_hi(v.x), h1 = bf_hi(v.y), h2 = bf_hi(v.z), h3 = bf_hi(v.w);
                uint32_t* dh = (uint32_t*)(As_hi + arow * SP + (akq + p) * 4);
                uint32_t* dl = (uint32_t*)(As_lo + arow * SP + (akq + p) * 4);
                dh[0] = pack2bf(h0, h1); dh[1] = pack2bf(h2, h3);
                dl[0] = pack2bf(v.x - h0, v.y - h1); dl[1] = pack2bf(v.z - h2, v.w - h3);
            }
            #pragma unroll
            for (int j = 0; j < 8; j++) {
                float x0 = pfB[2 * j], x1 = pfB[2 * j + 1];
                float h0 = bf_hi(x0), h1 = bf_hi(x1);
                *(uint32_t*)(Bs_hi + bn * SP + bkh + 2 * j) = pack2bf(h0, h1);
                *(uint32_t*)(Bs_lo + bn * SP + bkh + 2 * j) = pack2bf(x0 - h0, x1 - h1);
            }
        }

        // prefetch chunk c+1 (global loads in flight across the sync + compute)
        if (c < 7) {
            int gr = rowBase + arow;
            const float4 z = make_float4(0.f, 0.f, 0.f, 0.f);
            const float* Ab = A + (size_t)gr * FTOT + (c + 1) * 32;
            #pragma unroll
            for (int p = 0; p < 4; p++)
                pfA[p] = (gr < M) ? *(const float4*)(Ab + (akq + p) * 4) : z;
            #pragma unroll
            for (int j = 0; j < 16; j++)
                pfB[j] = W[(size_t)((c + 1) * 32 + bkh + j) * FTOT + colBase + bn];
        }
        __syncthreads();
        // single barrier per chunk: with double buffering, a warp storing chunk c+2
        // into buffer b has passed sync(c+1), which required all warps to finish
        // compute(c) -- the last readers of buffer b.

        // compute chunk c: two k16 steps
        const uint32_t as_hi = smem_u32(As_hi);
        const uint32_t as_lo = smem_u32(As_lo);
        const uint32_t bs_hi = smem_u32(Bs_hi);
        const uint32_t bs_lo = smem_u32(Bs_lo);
        const int t = lane >> 3, r = lane & 7;
        #pragma unroll
        for (int ks = 0; ks < 2; ks++) {
            uint32_t Ah[4][4], Al[4][4], Bh[4][2], Bl[4][2];
            const int a_row_off = (t & 1) * 8 + r;
            const int a_col = ks * 16 + (t >> 1) * 8;
            #pragma unroll
            for (int f = 0; f < 4; f++) {
                uint32_t off = ((mbase + f * 16 + a_row_off) * SP + a_col) * 2;
                ldsm_x4(as_hi + off, Ah[f][0], Ah[f][1], Ah[f][2], Ah[f][3]);
                ldsm_x4(as_lo + off, Al[f][0], Al[f][1], Al[f][2], Al[f][3]);
            }
            const int b_row_off = (t >> 1) * 8 + r;
            const int b_col = ks * 16 + (t & 1) * 8;
            #pragma unroll
            for (int g = 0; g < 2; g++) {
                uint32_t off = ((nbase + g * 16 + b_row_off) * SP + b_col) * 2;
                ldsm_x4(bs_hi + off, Bh[2 * g][0], Bh[2 * g][1], Bh[2 * g + 1][0], Bh[2 * g + 1][1]);
                ldsm_x4(bs_lo + off, Bl[2 * g][0], Bl[2 * g][1], Bl[2 * g + 1][0], Bl[2 * g + 1][1]);
            }
            #pragma unroll
            for (int i = 0; i < 4; i++)
                #pragma unroll
                for (int j = 0; j < 4; j++) {
                    mma_bf16(acc[i][j], Ah[i], Bh[j]);
                    mma_bf16(acc[i][j], Al[i], Bh[j]);
                    mma_bf16(acc[i][j], Ah[i], Bl[j]);
                }
        }
    }

    // epilogue: store C + fused el/er for this warp's head
    const int rq = lane >> 2;
    const int cq = (lane & 3) * 2;
    const int hIdx = (colBase >> 5) + (wid & 3);      // global head index 0..7
    float alv[4][2], arv[4][2];
    #pragma unroll
    for (int j = 0; j < 4; j++) {
        int d0 = hIdx * HIDD + j * 8 + cq;
        alv[j][0] = al[d0]; alv[j][1] = al[d0 + 1];
        arv[j][0] = ar[d0]; arv[j][1] = ar[d0 + 1];
    }
    #pragma unroll
    for (int i = 0; i < 4; i++) {
        int r0 = rowBase + mbase + i * 16 + rq;
        int r1 = r0 + 8;
        float sl0 = 0.f, sr0 = 0.f, sl1 = 0.f, sr1 = 0.f;
        #pragma unroll
        for (int j = 0; j < 4; j++) {
            int cc = colBase + nbase + j * 8 + cq;
            if (r0 < M) *(float2*)(C + (size_t)r0 * FTOT + cc) = make_float2(acc[i][j][0], acc[i][j][1]);
            if (r1 < M) *(float2*)(C + (size_t)r1 * FTOT + cc) = make_float2(acc[i][j][2], acc[i][j][3]);
            sl0 = fmaf(acc[i][j][0], alv[j][0], fmaf(acc[i][j][1], alv[j][1], sl0));
            sr0 = fmaf(acc[i][j][0], arv[j][0], fmaf(acc[i][j][1], arv[j][1], sr0));
            sl1 = fmaf(acc[i][j][2], alv[j][0], fmaf(acc[i][j][3], alv[j][1], sl1));
            sr1 = fmaf(acc[i][j][2], arv[j][0], fmaf(acc[i][j][3], arv[j][1], sr1));
        }
        #pragma unroll
        for (int d = 1; d <= 2; d <<= 1) {
            sl0 += __shfl_xor_sync(0xffffffffu, sl0, d);
            sr0 += __shfl_xor_sync(0xffffffffu, sr0, d);
            sl1 += __shfl_xor_sync(0xffffffffu, sl1, d);
            sr1 += __shfl_xor_sync(0xffffffffu, sr1, d);
        }
        if ((lane & 3) == 0) {
            if (r0 < M) { el[r0 * NHEADS + hIdx] = sl0; er[r0 * NHEADS + hIdx] = sr0; }
            if (r1 < M) { el[r1 * NHEADS + hIdx] = sl1; er[r1 * NHEADS + hIdx] = sr1; }
        }
    }
}

// ---------------- CSR build ----------------
__global__ void hist_kernel(const int* __restrict__ dst, int* __restrict__ count) {
    int e = blockIdx.x * blockDim.x + threadIdx.x;
    if (e < EE) atomicAdd(&count[dst[e]], 1);
}

__global__ void scan_kernel(const int* __restrict__ count, int* __restrict__ off,
                            int* __restrict__ cursor) {
    __shared__ int wsum[32];
    __shared__ int carry;
    const int t = threadIdx.x;
    const int w = t >> 5, lane = t & 31;
    if (t == 0) carry = 0;
    __syncthreads();
    for (int base = 0; base < NN; base += 1024) {
        int i = base + t;
        int v = (i < NN) ? count[i] : 0;
        int incl = v;
        #pragma unroll
        for (int d = 1; d < 32; d <<= 1) {
            int x = __shfl_up_sync(0xffffffffu, incl, d);
            if (lane >= d) incl += x;
        }
        if (lane == 31) wsum[w] = incl;
        __syncthreads();
        if (w == 0) {
            int s = wsum[lane];
            #pragma unroll
            for (int d = 1; d < 32; d <<= 1) {
                int x = __shfl_up_sync(0xffffffffu, s, d);
                if (lane >= d) s += x;
            }
            wsum[lane] = s;
        }
        __syncthreads();
        int wpre = (w > 0) ? wsum[w - 1] : 0;
        int excl = carry + wpre + incl - v;
        if (i < NN) { off[i] = excl; cursor[i] = excl; }
        int total = wsum[31];
        __syncthreads();
        if (t == 0) carry += total;
        __syncthreads();
    }
    if (t == 0) off[NN] = carry;
}

__global__ void scatter_kernel(const int* __restrict__ dst, const int* __restrict__ srcArr,
                               int* __restrict__ cursor, int* __restrict__ srcs) {
    int e = blockIdx.x * blockDim.x + threadIdx.x;
    if (e < EE) {
        int pos = atomicAdd(&cursor[dst[e]], 1);
        srcs[pos] = srcArr[e];
    }
}

// ---------------- SGEMM (fp32) for the small final layer ----------------
template <int BM, int BN, int BK, int TM, int TN>
__global__ void __launch_bounds__((BM / TM) * (BN / TN))
sgemm_kernel(const float* __restrict__ A, const float* __restrict__ B,
             float* __restrict__ C, int M, int Nc, int K) {
    constexpr int TCOLS = BN / TN;
    constexpr int NT = (BM / TM) * TCOLS;
    __shared__ float As[BK][BM];
    __shared__ float Bs[BK][BN];
    const int tid = threadIdx.x;
    const int tr = tid / TCOLS;
    const int tc = tid % TCOLS;
    const int rowBase = blockIdx.y * BM;
    const int colBase = blockIdx.x * BN;

    float acc[TM][TN];
    #pragma unroll
    for (int i = 0; i < TM; i++)
        #pragma unroll
        for (int j = 0; j < TN; j++) acc[i][j] = 0.f;

    for (int k0 = 0; k0 < K; k0 += BK) {
        #pragma unroll
        for (int i = tid * 4; i < BM * BK; i += NT * 4) {
            int m = i / BK, kk = i % BK;
            int gr = rowBase + m;
            float4 v = make_float4(0.f, 0.f, 0.f, 0.f);
            if (gr < M) v = *(const float4*)(A + (size_t)gr * K + k0 + kk);
            As[kk + 0][m] = v.x; As[kk + 1][m] = v.y;
            As[kk + 2][m] = v.z; As[kk + 3][m] = v.w;
        }
        #pragma unroll
        for (int i = tid * 4; i < BK * BN; i += NT * 4) {
            int kk = i / BN, nn = i % BN;
            float4 v = *(const float4*)(B + (size_t)(k0 + kk) * Nc + colBase + nn);
            *(float4*)&Bs[kk][nn] = v;
        }
        __syncthreads();
        #pragma unroll
        for (int kk = 0; kk < BK; kk++) {
            float a[TM], b[TN];
            #pragma unroll
            for (int i = 0; i < TM / 4; i++)
                *(float4*)&a[i * 4] = *(const float4*)&As[kk][tr * TM + i * 4];
            #pragma unroll
            for (int j = 0; j < TN / 4; j++)
                *(float4*)&b[j * 4] = *(const float4*)&Bs[kk][tc * TN + j * 4];
            #pragma unroll
            for (int i = 0; i < TM; i++)
                #pragma unroll
                for (int j = 0; j < TN; j++) acc[i][j] = fmaf(a[i], b[j], acc[i][j]);
        }
        __syncthreads();
    }
    #pragma unroll
    for (int i = 0; i < TM; i++) {
        int r = rowBase + tr * TM + i;
        if (r < M) {
            #pragma unroll
            for (int j = 0; j < TN / 4; j++)
                *(float4*)(C + (size_t)r * Nc + colBase + tc * TN + j * 4) =
                    *(float4*)&acc[i][j * 4];
        }
    }
}

// ---------------- el/er for final layer (1 head) ----------------
__global__ void elr1_kernel(const float* __restrict__ feat2, const float* __restrict__ al,
                            const float* __restrict__ ar, float* __restrict__ el,
                            float* __restrict__ er) {
    int n = blockIdx.x * blockDim.x + threadIdx.x;
    if (n >= NN) return;
    const float4* f = (const float4*)(feat2 + (size_t)n * HIDD);
    const float4* A = (const float4*)al;
    const float4* B = (const float4*)ar;
    float sl = 0.f, sr = 0.f;
    #pragma unroll
    for (int i = 0; i < HIDD / 4; i++) {
        float4 v = f[i], a = A[i], b = B[i];
        sl += v.x * a.x + v.y * a.y + v.z * a.z + v.w * a.w;
        sr += v.x * b.x + v.y * b.y + v.z * b.z + v.w * b.w;
    }
    el[n] = sl; er[n] = sr;
}

// ---------------- per-node warp: segment softmax + aggregate (8 heads) ----------------
__global__ void __launch_bounds__(256)
agg8_kernel(const float* __restrict__ feat, const float* __restrict__ el,
            const float* __restrict__ er, const float* __restrict__ bias,
            float* __restrict__ out, const int* __restrict__ off,
            const int* __restrict__ srcs) {
    int warp = (blockIdx.x * blockDim.x + threadIdx.x) >> 5;
    if (warp >= NN) return;
    const int lane = threadIdx.x & 31;
    const int n = warp;
    const int s = off[n], epnd = off[n + 1];
    const int hl = lane & 7;
    const int eslot = lane >> 3;
    const float er_h = er[n * NHEADS + hl];

    // single pass: online max + sum of exp (safe_exp guards -inf minus -inf)
    float mx = -INFINITY, sm = 0.f;
    for (int i = s + eslot; i < epnd; i += 4) {
        int src = srcs[i];
        float v = el[src * NHEADS + hl] + er_h;
        v = v > 0.f ? v : 0.2f * v;
        float m2 = fmaxf(mx, v);
        sm = sm * safe_exp(mx - m2) + safe_exp(v - m2);
        mx = m2;
    }
    #pragma unroll
    for (int d = 8; d <= 16; d <<= 1) {
        float om = __shfl_xor_sync(0xffffffffu, mx, d);
        float os = __shfl_xor_sync(0xffffffffu, sm, d);
        float m2 = fmaxf(mx, om);
        sm = sm * safe_exp(mx - m2) + os * safe_exp(om - m2);
        mx = m2;
    }
    const float inv = 1.0f / (sm + 1e-9f);

    // aggregate: lane owns dim d=lane across all 8 heads
    float acc[NHEADS];
    #pragma unroll
    for (int h = 0; h < NHEADS; h++) acc[h] = 0.f;
    for (int i = s; i < epnd; i++) {
        int src = srcs[i];
        float coef = 0.f;
        if (lane < 8) {
            float v = el[src * NHEADS + lane] + er_h;
            v = v > 0.f ? v : 0.2f * v;
            coef = safe_exp(v - mx) * inv;
        }
        const float* frow = feat + (size_t)src * FTOT;
        #pragma unroll
        for (int h = 0; h < NHEADS; h++) {
            float a = __shfl_sync(0xffffffffu, coef, h);
            acc[h] = fmaf(a, frow[h * HIDD + lane], acc[h]);
        }
    }
    #pragma unroll
    for (int h = 0; h < NHEADS; h++) {
        float v = acc[h] + bias[h * HIDD + lane];
        v = v > 0.f ? v : expm1f(v);
        out[(size_t)n * FTOT + h * HIDD + lane] = v;
    }
}

// ---------------- final layer aggregate (1 head, D=32) ----------------
__global__ void __launch_bounds__(256)
agg1_kernel(const float* __restrict__ feat2, const float* __restrict__ el,
            const float* __restrict__ er, const float* __restrict__ bias,
            float* __restrict__ out, const int* __restrict__ off,
            const int* __restrict__ srcs) {
    int warp = (blockIdx.x * blockDim.x + threadIdx.x) >> 5;
    if (warp >= NN) return;
    const int lane = threadIdx.x & 31;
    const int n = warp;
    const int s = off[n], epnd = off[n + 1];
    const float er_n = er[n];

    float mx = -INFINITY, sm = 0.f;
    for (int i = s + lane; i < epnd; i += 32) {
        int src = srcs[i];
        float v = el[src] + er_n;
        v = v > 0.f ? v : 0.2f * v;
        float m2 = fmaxf(mx, v);
        sm = sm * safe_exp(mx - m2) + safe_exp(v - m2);
        mx = m2;
    }
    #pragma unroll
    for (int d = 16; d >= 1; d >>= 1) {
        float om = __shfl_xor_sync(0xffffffffu, mx, d);
        float os = __shfl_xor_sync(0xffffffffu, sm, d);
        float m2 = fmaxf(mx, om);
        sm = sm * safe_exp(mx - m2) + os * safe_exp(om - m2);
        mx = m2;
    }
    const float inv = 1.0f / (sm + 1e-9f);

    float acc = 0.f;
    for (int i = s; i < epnd; i++) {
        int src = srcs[i];
        float v = el[src] + er_n;
        v = v > 0.f ? v : 0.2f * v;
        float coef = safe_exp(v - mx) * inv;
        acc = fmaf(coef, feat2[(size_t)src * HIDD + lane], acc);
    }
    out[(size_t)n * HIDD + lane] = acc + bias[lane];
}

// ---------------- launch ----------------
extern "C" void kernel_launch(void* const* d_in, const int* in_sizes, int n_in,
                              void* d_out, int out_size) {
    const float* features = (const float*)d_in[0];
    const int*   src      = (const int*)d_in[1];
    const int*   dst      = (const int*)d_in[2];
    const float* W0  = (const float*)d_in[3];
    const float* al0 = (const float*)d_in[4];
    const float* ar0 = (const float*)d_in[5];
    const float* b0  = (const float*)d_in[6];
    const float* W1  = (const float*)d_in[7];
    const float* al1 = (const float*)d_in[8];
    const float* ar1 = (const float*)d_in[9];
    const float* b1  = (const float*)d_in[10];
    const float* W2  = (const float*)d_in[11];
    const float* al2 = (const float*)d_in[12];
    const float* ar2 = (const float*)d_in[13];
    const float* b2  = (const float*)d_in[14];
    float* out = (float*)d_out;

    float *feat, *h, *feat2, *el, *er;
    int *count, *off, *cursor, *srcs;
    cudaGetSymbolAddress((void**)&feat,   g_feat);
    cudaGetSymbolAddress((void**)&h,      g_h);
    cudaGetSymbolAddress((void**)&feat2,  g_feat2);
    cudaGetSymbolAddress((void**)&el,     g_el);
    cudaGetSymbolAddress((void**)&er,     g_er);
    cudaGetSymbolAddress((void**)&count,  g_count);
    cudaGetSymbolAddress((void**)&off,    g_off);
    cudaGetSymbolAddress((void**)&cursor, g_cursor);
    cudaGetSymbolAddress((void**)&srcs,   g_srcs);

    cudaFuncSetAttribute(mma_gemm_kernel, cudaFuncAttributeMaxDynamicSharedMemorySize,
                         GEMM_SMEM);

    // CSR by dst (src values scattered directly)
    cudaMemsetAsync(count, 0, NN * sizeof(int));
    hist_kernel<<<(EE + 255) / 256, 256>>>(dst, count);
    scan_kernel<<<1, 1024>>>(count, off, cursor);
    scatter_kernel<<<(EE + 255) / 256, 256>>>(dst, src, cursor, srcs);

    const int aggBlocks = (NN * 32 + 255) / 256;
    dim3 gemmGrid(2, (NN + 127) / 128);
    dim3 gemmSmall(1, (NN + 127) / 128);

    // layer 0 (GEMM + fused el/er)
    mma_gemm_kernel<<<gemmGrid, 256, GEMM_SMEM>>>(features, W0, feat, al0, ar0, el, er, NN);
    agg8_kernel<<<aggBlocks, 256>>>(feat, el, er, b0, h, off, srcs);

    // layer 1
    mma_gemm_kernel<<<gemmGrid, 256, GEMM_SMEM>>>(h, W1, feat, al1, ar1, el, er, NN);
    agg8_kernel<<<aggBlocks, 256>>>(feat, el, er, b1, h, off, srcs);

    // layer 2 (single head, D=32, no activation)
    sgemm_kernel<128, 32, 32, 8, 4><<<gemmSmall, 128>>>(h, W2, feat2, NN, HIDD, FTOT);
    elr1_kernel<<<(NN + 255) / 256, 256>>>(feat2, al2, ar2, el, er);
    agg1_kernel<<<aggBlocks, 256>>>(feat2, el, er, b2, out, off, srcs);
}

// round 7
// speedup vs baseline: 2.0677x; 1.1752x over previous
#include <cuda_runtime.h>
#include <cuda_fp16.h>
#include <math.h>
#include <stdint.h>

#define NN 50000
#define EE 800000
#define NHEADS 8
#define HIDD 32
#define FTOT 256   // NHEADS*HIDD, also IN_FEATS

// ---------------- scratch (static device globals; no allocation) ----------------
__device__ __align__(16) __half g_featH[(size_t)NN * FTOT];  // 25.6 MB (GEMM out, fp16)
__device__ __align__(16) float g_h[(size_t)NN * FTOT];       // 51.2 MB
__device__ __align__(16) float g_feat2[(size_t)NN * HIDD];   // 6.4 MB
__device__ __align__(16) float g_el[NN * NHEADS];
__device__ __align__(16) float g_er[NN * NHEADS];
__device__ int g_count[NN];
__device__ int g_off[NN + 1];
__device__ int g_cursor[NN];
__device__ int g_srcs[EE];    // src node of each edge, sorted by dst

// ---------------- helpers ----------------
__device__ __forceinline__ uint32_t smem_u32(const void* p) {
    uint32_t a;
    asm("{ .reg .u64 t; cvta.to.shared.u64 t, %1; cvt.u32.u64 %0, t; }" : "=r"(a) : "l"(p));
    return a;
}
__device__ __forceinline__ void ldsm_x4(uint32_t addr, uint32_t& r0, uint32_t& r1,
                                        uint32_t& r2, uint32_t& r3) {
    asm volatile("ldmatrix.sync.aligned.m8n8.x4.shared.b16 {%0,%1,%2,%3}, [%4];"
                 : "=r"(r0), "=r"(r1), "=r"(r2), "=r"(r3) : "r"(addr));
}
__device__ __forceinline__ void mma_f16(float* d, const uint32_t* a, const uint32_t* b) {
    asm volatile(
        "mma.sync.aligned.m16n8k16.row.col.f32.f16.f16.f32 "
        "{%0,%1,%2,%3}, {%4,%5,%6,%7}, {%8,%9}, {%0,%1,%2,%3};"
        : "+f"(d[0]), "+f"(d[1]), "+f"(d[2]), "+f"(d[3])
        : "r"(a[0]), "r"(a[1]), "r"(a[2]), "r"(a[3]), "r"(b[0]), "r"(b[1]));
}
__device__ __forceinline__ uint32_t pack2h(float a, float b) {
    __half2 t = __floats2half2_rn(a, b);
    return *(uint32_t*)&t;
}
// exp argument guard: fmaxf(NaN, -88) = -88, so (-inf) - (-inf) merges stay finite
__device__ __forceinline__ float safe_exp(float x) {
    return __expf(fmaxf(x, -88.f));
}

// ---------------- mma.sync fp16 GEMM: C[M x 256] = A[M x 256] * W[256 x 256]
// CTA tile 128x128, 8 warps (warp tile 64x32 = one head wide), BK=32 double-buffered.
// Single product (fp16 mantissa suffices for 1e-3 gate). 40KB smem -> 2 CTAs/SM.
// Fused el/er epilogue; C stored as fp16 (only consumer is the edge gather).
#define SP 40                      // smem row pitch in halfs
#define TILE_H (128 * SP)          // halfs per logical tile
#define BUF_H (2 * TILE_H)         // As | Bs
#define GEMM_SMEM (2 * BUF_H * 2)  // 40960 bytes

__global__ void __launch_bounds__(256, 2)
mma_gemm_kernel(const float* __restrict__ A, const float* __restrict__ W,
                __half* __restrict__ C, const float* __restrict__ al,
                const float* __restrict__ ar, float* __restrict__ el,
                float* __restrict__ er, int M) {
    extern __shared__ __half2 smem_raw[];
    uint16_t* smem = (uint16_t*)smem_raw;
    const int tid = threadIdx.x;
    const int wid = tid >> 5;
    const int lane = tid & 31;
    const int rowBase = blockIdx.y * 128;
    const int colBase = blockIdx.x * 128;
    const int mbase = (wid >> 2) * 64;   // warpM in {0,1}
    const int nbase = (wid & 3) * 32;    // warpN in {0..3} == head within tile

    float acc[4][4][4];
    #pragma unroll
    for (int i = 0; i < 4; i++)
        #pragma unroll
        for (int j = 0; j < 4; j++)
            #pragma unroll
            for (int q = 0; q < 4; q++) acc[i][j][q] = 0.f;

    // per-thread load coords
    const int arow = tid >> 1;            // A: 2 threads per row
    const int akq  = (tid & 1) * 4;       // first float4 index of this thread's 4
    const int bn   = tid & 127;           // B: output column within tile
    const int bkh  = (tid >> 7) * 16;     // k-half within chunk

    float4 pfA[4];
    float pfB[16];

    // prefetch chunk 0
    {
        int gr = rowBase + arow;
        const float4 z = make_float4(0.f, 0.f, 0.f, 0.f);
        #pragma unroll
        for (int p = 0; p < 4; p++)
            pfA[p] = (gr < M) ? *(const float4*)(A + (size_t)gr * FTOT + (akq + p) * 4) : z;
        #pragma unroll
        for (int j = 0; j < 16; j++)
            pfB[j] = W[(size_t)(bkh + j) * FTOT + colBase + bn];
    }

    for (int c = 0; c < 8; c++) {
        const int b = c & 1;
        uint16_t* As = smem + b * BUF_H;
        uint16_t* Bs = As + TILE_H;

        // convert + store prefetched chunk c into buffer b
        {
            #pragma unroll
            for (int p = 0; p < 4; p++) {
                float4 v = pfA[p];
                uint32_t* dh = (uint32_t*)(As + arow * SP + (akq + p) * 4);
                dh[0] = pack2h(v.x, v.y); dh[1] = pack2h(v.z, v.w);
            }
            #pragma unroll
            for (int j = 0; j < 8; j++)
                *(uint32_t*)(Bs + bn * SP + bkh + 2 * j) = pack2h(pfB[2 * j], pfB[2 * j + 1]);
        }

        // prefetch chunk c+1 (global loads in flight across the sync + compute)
        if (c < 7) {
            int gr = rowBase + arow;
            const float4 z = make_float4(0.f, 0.f, 0.f, 0.f);
            const float* Ab = A + (size_t)gr * FTOT + (c + 1) * 32;
            #pragma unroll
            for (int p = 0; p < 4; p++)
                pfA[p] = (gr < M) ? *(const float4*)(Ab + (akq + p) * 4) : z;
            #pragma unroll
            for (int j = 0; j < 16; j++)
                pfB[j] = W[(size_t)((c + 1) * 32 + bkh + j) * FTOT + colBase + bn];
        }
        __syncthreads();
        // single barrier per chunk: with double buffering, a warp storing chunk c+2
        // into buffer b has passed sync(c+1), which required all warps to finish
        // compute(c) -- the last readers of buffer b.

        // compute chunk c: two k16 steps
        const uint32_t as = smem_u32(As);
        const uint32_t bs = smem_u32(Bs);
        const int t = lane >> 3, r = lane & 7;
        #pragma unroll
        for (int ks = 0; ks < 2; ks++) {
            uint32_t Ah[4][4], Bh[4][2];
            const int a_row_off = (t & 1) * 8 + r;
            const int a_col = ks * 16 + (t >> 1) * 8;
            #pragma unroll
            for (int f = 0; f < 4; f++) {
                uint32_t off = ((mbase + f * 16 + a_row_off) * SP + a_col) * 2;
                ldsm_x4(as + off, Ah[f][0], Ah[f][1], Ah[f][2], Ah[f][3]);
            }
            const int b_row_off = (t >> 1) * 8 + r;
            const int b_col = ks * 16 + (t & 1) * 8;
            #pragma unroll
            for (int g = 0; g < 2; g++) {
                uint32_t off = ((nbase + g * 16 + b_row_off) * SP + b_col) * 2;
                ldsm_x4(bs + off, Bh[2 * g][0], Bh[2 * g][1], Bh[2 * g + 1][0], Bh[2 * g + 1][1]);
            }
            #pragma unroll
            for (int i = 0; i < 4; i++)
                #pragma unroll
                for (int j = 0; j < 4; j++)
                    mma_f16(acc[i][j], Ah[i], Bh[j]);
        }
    }

    // epilogue: store C (fp16) + fused el/er for this warp's head
    const int rq = lane >> 2;
    const int cq = (lane & 3) * 2;
    const int hIdx = (colBase >> 5) + (wid & 3);      // global head index 0..7
    float alv[4][2], arv[4][2];
    #pragma unroll
    for (int j = 0; j < 4; j++) {
        int d0 = hIdx * HIDD + j * 8 + cq;
        alv[j][0] = al[d0]; alv[j][1] = al[d0 + 1];
        arv[j][0] = ar[d0]; arv[j][1] = ar[d0 + 1];
    }
    #pragma unroll
    for (int i = 0; i < 4; i++) {
        int r0 = rowBase + mbase + i * 16 + rq;
        int r1 = r0 + 8;
        float sl0 = 0.f, sr0 = 0.f, sl1 = 0.f, sr1 = 0.f;
        #pragma unroll
        for (int j = 0; j < 4; j++) {
            int cc = colBase + nbase + j * 8 + cq;
            if (r0 < M) *(uint32_t*)(C + (size_t)r0 * FTOT + cc) = pack2h(acc[i][j][0], acc[i][j][1]);
            if (r1 < M) *(uint32_t*)(C + (size_t)r1 * FTOT + cc) = pack2h(acc[i][j][2], acc[i][j][3]);
            sl0 = fmaf(acc[i][j][0], alv[j][0], fmaf(acc[i][j][1], alv[j][1], sl0));
            sr0 = fmaf(acc[i][j][0], arv[j][0], fmaf(acc[i][j][1], arv[j][1], sr0));
            sl1 = fmaf(acc[i][j][2], alv[j][0], fmaf(acc[i][j][3], alv[j][1], sl1));
            sr1 = fmaf(acc[i][j][2], arv[j][0], fmaf(acc[i][j][3], arv[j][1], sr1));
        }
        #pragma unroll
        for (int d = 1; d <= 2; d <<= 1) {
            sl0 += __shfl_xor_sync(0xffffffffu, sl0, d);
            sr0 += __shfl_xor_sync(0xffffffffu, sr0, d);
            sl1 += __shfl_xor_sync(0xffffffffu, sl1, d);
            sr1 += __shfl_xor_sync(0xffffffffu, sr1, d);
        }
        if ((lane & 3) == 0) {
            if (r0 < M) { el[r0 * NHEADS + hIdx] = sl0; er[r0 * NHEADS + hIdx] = sr0; }
            if (r1 < M) { el[r1 * NHEADS + hIdx] = sl1; er[r1 * NHEADS + hIdx] = sr1; }
        }
    }
}

// ---------------- CSR build ----------------
__global__ void hist_kernel(const int* __restrict__ dst, int* __restrict__ count) {
    int e = blockIdx.x * blockDim.x + threadIdx.x;
    if (e < EE) atomicAdd(&count[dst[e]], 1);
}

__global__ void scan_kernel(const int* __restrict__ count, int* __restrict__ off,
                            int* __restrict__ cursor) {
    __shared__ int wsum[32];
    __shared__ int carry;
    const int t = threadIdx.x;
    const int w = t >> 5, lane = t & 31;
    if (t == 0) carry = 0;
    __syncthreads();
    for (int base = 0; base < NN; base += 1024) {
        int i = base + t;
        int v = (i < NN) ? count[i] : 0;
        int incl = v;
        #pragma unroll
        for (int d = 1; d < 32; d <<= 1) {
            int x = __shfl_up_sync(0xffffffffu, incl, d);
            if (lane >= d) incl += x;
        }
        if (lane == 31) wsum[w] = incl;
        __syncthreads();
        if (w == 0) {
            int s = wsum[lane];
            #pragma unroll
            for (int d = 1; d < 32; d <<= 1) {
                int x = __shfl_up_sync(0xffffffffu, s, d);
                if (lane >= d) s += x;
            }
            wsum[lane] = s;
        }
        __syncthreads();
        int wpre = (w > 0) ? wsum[w - 1] : 0;
        int excl = carry + wpre + incl - v;
        if (i < NN) { off[i] = excl; cursor[i] = excl; }
        int total = wsum[31];
        __syncthreads();
        if (t == 0) carry += total;
        __syncthreads();
    }
    if (t == 0) off[NN] = carry;
}

__global__ void scatter_kernel(const int* __restrict__ dst, const int* __restrict__ srcArr,
                               int* __restrict__ cursor, int* __restrict__ srcs) {
    int e = blockIdx.x * blockDim.x + threadIdx.x;
    if (e < EE) {
        int pos = atomicAdd(&cursor[dst[e]], 1);
        srcs[pos] = srcArr[e];
    }
}

// ---------------- final-layer SGEMM (fp32) with fused el/er epilogue ----------------
// C[M x 32] = A[M x 256] * B[256 x 32]; BM=128 BN=32 BK=32 TM=8 TN=4, 128 threads.
__global__ void __launch_bounds__(128)
sgemm_final_kernel(const float* __restrict__ A, const float* __restrict__ B,
                   float* __restrict__ C, const float* __restrict__ al,
                   const float* __restrict__ ar, float* __restrict__ el,
                   float* __restrict__ er, int M) {
    constexpr int BM = 128, BN = 32, BK = 32, TM = 8, TN = 4;
    constexpr int TCOLS = BN / TN;   // 8
    constexpr int NT = 128;
    __shared__ float As[BK][BM];
    __shared__ float Bs[BK][BN];
    const int tid = threadIdx.x;
    const int tr = tid / TCOLS;
    const int tc = tid % TCOLS;
    const int rowBase = blockIdx.y * BM;

    float acc[TM][TN];
    #pragma unroll
    for (int i = 0; i < TM; i++)
        #pragma unroll
        for (int j = 0; j < TN; j++) acc[i][j] = 0.f;

    for (int k0 = 0; k0 < FTOT; k0 += BK) {
        #pragma unroll
        for (int i = tid * 4; i < BM * BK; i += NT * 4) {
            int m = i / BK, kk = i % BK;
            int gr = rowBase + m;
            float4 v = make_float4(0.f, 0.f, 0.f, 0.f);
            if (gr < M) v = *(const float4*)(A + (size_t)gr * FTOT + k0 + kk);
            As[kk + 0][m] = v.x; As[kk + 1][m] = v.y;
            As[kk + 2][m] = v.z; As[kk + 3][m] = v.w;
        }
        #pragma unroll
        for (int i = tid * 4; i < BK * BN; i += NT * 4) {
            int kk = i / BN, nn = i % BN;
            float4 v = *(const float4*)(B + (size_t)(k0 + kk) * BN + nn);
            *(float4*)&Bs[kk][nn] = v;
        }
        __syncthreads();
        #pragma unroll
        for (int kk = 0; kk < BK; kk++) {
            float a[TM], b[TN];
            #pragma unroll
            for (int i = 0; i < TM / 4; i++)
                *(float4*)&a[i * 4] = *(const float4*)&As[kk][tr * TM + i * 4];
            *(float4*)&b[0] = *(const float4*)&Bs[kk][tc * TN];
            #pragma unroll
            for (int i = 0; i < TM; i++)
                #pragma unroll
                for (int j = 0; j < TN; j++) acc[i][j] = fmaf(a[i], b[j], acc[i][j]);
        }
        __syncthreads();
    }
    float alv[TN], arv[TN];
    #pragma unroll
    for (int j = 0; j < TN; j++) { alv[j] = al[tc * TN + j]; arv[j] = ar[tc * TN + j]; }
    #pragma unroll
    for (int i = 0; i < TM; i++) {
        int r = rowBase + tr * TM + i;
        float pl = 0.f, pr = 0.f;
        #pragma unroll
        for (int j = 0; j < TN; j++) {
            pl = fmaf(acc[i][j], alv[j], pl);
            pr = fmaf(acc[i][j], arv[j], pr);
        }
        #pragma unroll
        for (int d = 1; d <= 4; d <<= 1) {
            pl += __shfl_xor_sync(0xffffffffu, pl, d);
            pr += __shfl_xor_sync(0xffffffffu, pr, d);
        }
        if (r < M) {
            *(float4*)(C + (size_t)r * BN + tc * TN) = *(float4*)&acc[i][0];
            if (tc == 0) { el[r] = pl; er[r] = pr; }
        }
    }
}

// ---------------- per-node warp: segment softmax + aggregate (8 heads, fp16 feat) ----
__global__ void __launch_bounds__(256)
agg8_kernel(const __half* __restrict__ feat, const float* __restrict__ el,
            const float* __restrict__ er, const float* __restrict__ bias,
            float* __restrict__ out, const int* __restrict__ off,
            const int* __restrict__ srcs) {
    int warp = (blockIdx.x * blockDim.x + threadIdx.x) >> 5;
    if (warp >= NN) return;
    const int lane = threadIdx.x & 31;
    const int n = warp;
    const int s = off[n], epnd = off[n + 1];
    const int hl = lane & 7;
    const int eslot = lane >> 3;
    const float er_h = er[n * NHEADS + hl];

    // single pass: online max + sum of exp (safe_exp guards -inf minus -inf)
    float mx = -INFINITY, sm = 0.f;
    for (int i = s + eslot; i < epnd; i += 4) {
        int src = srcs[i];
        float v = el[src * NHEADS + hl] + er_h;
        v = v > 0.f ? v : 0.2f * v;
        float m2 = fmaxf(mx, v);
        sm = sm * safe_exp(mx - m2) + safe_exp(v - m2);
        mx = m2;
    }
    #pragma unroll
    for (int d = 8; d <= 16; d <<= 1) {
        float om = __shfl_xor_sync(0xffffffffu, mx, d);
        float os = __shfl_xor_sync(0xffffffffu, sm, d);
        float m2 = fmaxf(mx, om);
        sm = sm * safe_exp(mx - m2) + os * safe_exp(om - m2);
        mx = m2;
    }
    const float inv = 1.0f / (sm + 1e-9f);

    // aggregate: lane owns dim d=lane across all 8 heads
    float acc[NHEADS];
    #pragma unroll
    for (int h = 0; h < NHEADS; h++) acc[h] = 0.f;
    for (int i = s; i < epnd; i++) {
        int src = srcs[i];
        float coef = 0.f;
        if (lane < 8) {
            float v = el[src * NHEADS + lane] + er_h;
            v = v > 0.f ? v : 0.2f * v;
            coef = safe_exp(v - mx) * inv;
        }
        const __half* frow = feat + (size_t)src * FTOT;
        #pragma unroll
        for (int h = 0; h < NHEADS; h++) {
            float a = __shfl_sync(0xffffffffu, coef, h);
            acc[h] = fmaf(a, __half2float(frow[h * HIDD + lane]), acc[h]);
        }
    }
    #pragma unroll
    for (int h = 0; h < NHEADS; h++) {
        float v = acc[h] + bias[h * HIDD + lane];
        v = v > 0.f ? v : expm1f(v);
        out[(size_t)n * FTOT + h * HIDD + lane] = v;
    }
}

// ---------------- final layer aggregate (1 head, D=32) ----------------
__global__ void __launch_bounds__(256)
agg1_kernel(const float* __restrict__ feat2, const float* __restrict__ el,
            const float* __restrict__ er, const float* __restrict__ bias,
            float* __restrict__ out, const int* __restrict__ off,
            const int* __restrict__ srcs) {
    int warp = (blockIdx.x * blockDim.x + threadIdx.x) >> 5;
    if (warp >= NN) return;
    const int lane = threadIdx.x & 31;
    const int n = warp;
    const int s = off[n], epnd = off[n + 1];
    const float er_n = er[n];

    float mx = -INFINITY, sm = 0.f;
    for (int i = s + lane; i < epnd; i += 32) {
        int src = srcs[i];
        float v = el[src] + er_n;
        v = v > 0.f ? v : 0.2f * v;
        float m2 = fmaxf(mx, v);
        sm = sm * safe_exp(mx - m2) + safe_exp(v - m2);
        mx = m2;
    }
    #pragma unroll
    for (int d = 16; d >= 1; d >>= 1) {
        float om = __shfl_xor_sync(0xffffffffu, mx, d);
        float os = __shfl_xor_sync(0xffffffffu, sm, d);
        float m2 = fmaxf(mx, om);
        sm = sm * safe_exp(mx - m2) + os * safe_exp(om - m2);
        mx = m2;
    }
    const float inv = 1.0f / (sm + 1e-9f);

    float acc = 0.f;
    for (int i = s; i < epnd; i++) {
        int src = srcs[i];
        float v = el[src] + er_n;
        v = v > 0.f ? v : 0.2f * v;
        float coef = safe_exp(v - mx) * inv;
        acc = fmaf(coef, feat2[(size_t)src * HIDD + lane], acc);
    }
    out[(size_t)n * HIDD + lane] = acc + bias[lane];
}

// ---------------- launch ----------------
extern "C" void kernel_launch(void* const* d_in, const int* in_sizes, int n_in,
                              void* d_out, int out_size) {
    const float* features = (const float*)d_in[0];
    const int*   src      = (const int*)d_in[1];
    const int*   dst      = (const int*)d_in[2];
    const float* W0  = (const float*)d_in[3];
    const float* al0 = (const float*)d_in[4];
    const float* ar0 = (const float*)d_in[5];
    const float* b0  = (const float*)d_in[6];
    const float* W1  = (const float*)d_in[7];
    const float* al1 = (const float*)d_in[8];
    const float* ar1 = (const float*)d_in[9];
    const float* b1  = (const float*)d_in[10];
    const float* W2  = (const float*)d_in[11];
    const float* al2 = (const float*)d_in[12];
    const float* ar2 = (const float*)d_in[13];
    const float* b2  = (const float*)d_in[14];
    float* out = (float*)d_out;

    __half* featH;
    float *h, *feat2, *el, *er;
    int *count, *off, *cursor, *srcs;
    cudaGetSymbolAddress((void**)&featH,  g_featH);
    cudaGetSymbolAddress((void**)&h,      g_h);
    cudaGetSymbolAddress((void**)&feat2,  g_feat2);
    cudaGetSymbolAddress((void**)&el,     g_el);
    cudaGetSymbolAddress((void**)&er,     g_er);
    cudaGetSymbolAddress((void**)&count,  g_count);
    cudaGetSymbolAddress((void**)&off,    g_off);
    cudaGetSymbolAddress((void**)&cursor, g_cursor);
    cudaGetSymbolAddress((void**)&srcs,   g_srcs);

    cudaFuncSetAttribute(mma_gemm_kernel, cudaFuncAttributeMaxDynamicSharedMemorySize,
                         GEMM_SMEM);

    // CSR by dst (src values scattered directly)
    cudaMemsetAsync(count, 0, NN * sizeof(int));
    hist_kernel<<<(EE + 255) / 256, 256>>>(dst, count);
    scan_kernel<<<1, 1024>>>(count, off, cursor);
    scatter_kernel<<<(EE + 255) / 256, 256>>>(dst, src, cursor, srcs);

    const int aggBlocks = (NN * 32 + 255) / 256;
    dim3 gemmGrid(2, (NN + 127) / 128);
    dim3 gemmFinal(1, (NN + 127) / 128);

    // layer 0 (GEMM + fused el/er, fp16 out)
    mma_gemm_kernel<<<gemmGrid, 256, GEMM_SMEM>>>(features, W0, featH, al0, ar0, el, er, NN);
    agg8_kernel<<<aggBlocks, 256>>>(featH, el, er, b0, h, off, srcs);

    // layer 1
    mma_gemm_kernel<<<gemmGrid, 256, GEMM_SMEM>>>(h, W1, featH, al1, ar1, el, er, NN);
    agg8_kernel<<<aggBlocks, 256>>>(featH, el, er, b1, h, off, srcs);

    // layer 2 (single head, D=32, no activation; fused el/er)
    sgemm_final_kernel<<<gemmFinal, 128>>>(h, W2, feat2, al2, ar2, el, er, NN);
    agg1_kernel<<<aggBlocks, 256>>>(feat2, el, er, b2, out, off, srcs);
}

// round 8
// speedup vs baseline: 2.3546x; 1.1387x over previous
#include <cuda_runtime.h>
#include <cuda_fp16.h>
#include <math.h>
#include <stdint.h>

#define NN 50000
#define EE 800000
#define NHEADS 8
#define HIDD 32
#define FTOT 256   // NHEADS*HIDD, also IN_FEATS

// ---------------- scratch (static device globals; no allocation) ----------------
__device__ __align__(16) __half g_featH[(size_t)NN * FTOT];  // 25.6 MB (GEMM out, fp16)
__device__ __align__(16) float g_h[(size_t)NN * FTOT];       // 51.2 MB
__device__ __align__(16) float g_feat2[(size_t)NN * HIDD];   // 6.4 MB
__device__ __align__(16) float g_el[NN * NHEADS];
__device__ __align__(16) float g_er[NN * NHEADS];
__device__ int g_count[NN];
__device__ int g_off[NN + 1];
__device__ int g_cursor[NN];
__device__ int g_srcs[EE];    // src node of each edge, sorted by dst

// ---------------- helpers ----------------
__device__ __forceinline__ uint32_t smem_u32(const void* p) {
    uint32_t a;
    asm("{ .reg .u64 t; cvta.to.shared.u64 t, %1; cvt.u32.u64 %0, t; }" : "=r"(a) : "l"(p));
    return a;
}
__device__ __forceinline__ void ldsm_x4(uint32_t addr, uint32_t& r0, uint32_t& r1,
                                        uint32_t& r2, uint32_t& r3) {
    asm volatile("ldmatrix.sync.aligned.m8n8.x4.shared.b16 {%0,%1,%2,%3}, [%4];"
                 : "=r"(r0), "=r"(r1), "=r"(r2), "=r"(r3) : "r"(addr));
}
__device__ __forceinline__ void mma_f16(float* d, const uint32_t* a, const uint32_t* b) {
    asm volatile(
        "mma.sync.aligned.m16n8k16.row.col.f32.f16.f16.f32 "
        "{%0,%1,%2,%3}, {%4,%5,%6,%7}, {%8,%9}, {%0,%1,%2,%3};"
        : "+f"(d[0]), "+f"(d[1]), "+f"(d[2]), "+f"(d[3])
        : "r"(a[0]), "r"(a[1]), "r"(a[2]), "r"(a[3]), "r"(b[0]), "r"(b[1]));
}
__device__ __forceinline__ uint32_t pack2h(float a, float b) {
    __half2 t = __floats2half2_rn(a, b);
    return *(uint32_t*)&t;
}
// exp argument guard: fmaxf(NaN, -88) = -88, so (-inf) - (-inf) merges stay finite
__device__ __forceinline__ float safe_exp(float x) {
    return __expf(fmaxf(x, -88.f));
}

// ---------------- mma.sync fp16 GEMM: C[M x 256] = A[M x 256] * W[256 x 256]
#define SP 40                      // smem row pitch in halfs
#define TILE_H (128 * SP)          // halfs per logical tile
#define BUF_H (2 * TILE_H)         // As | Bs
#define GEMM_SMEM (2 * BUF_H * 2)  // 40960 bytes

__global__ void __launch_bounds__(256, 2)
mma_gemm_kernel(const float* __restrict__ A, const float* __restrict__ W,
                __half* __restrict__ C, const float* __restrict__ al,
                const float* __restrict__ ar, float* __restrict__ el,
                float* __restrict__ er, int M) {
    extern __shared__ __half2 smem_raw[];
    uint16_t* smem = (uint16_t*)smem_raw;
    const int tid = threadIdx.x;
    const int wid = tid >> 5;
    const int lane = tid & 31;
    const int rowBase = blockIdx.y * 128;
    const int colBase = blockIdx.x * 128;
    const int mbase = (wid >> 2) * 64;   // warpM in {0,1}
    const int nbase = (wid & 3) * 32;    // warpN in {0..3} == head within tile

    float acc[4][4][4];
    #pragma unroll
    for (int i = 0; i < 4; i++)
        #pragma unroll
        for (int j = 0; j < 4; j++)
            #pragma unroll
            for (int q = 0; q < 4; q++) acc[i][j][q] = 0.f;

    const int arow = tid >> 1;
    const int akq  = (tid & 1) * 4;
    const int bn   = tid & 127;
    const int bkh  = (tid >> 7) * 16;

    float4 pfA[4];
    float pfB[16];

    {
        int gr = rowBase + arow;
        const float4 z = make_float4(0.f, 0.f, 0.f, 0.f);
        #pragma unroll
        for (int p = 0; p < 4; p++)
            pfA[p] = (gr < M) ? *(const float4*)(A + (size_t)gr * FTOT + (akq + p) * 4) : z;
        #pragma unroll
        for (int j = 0; j < 16; j++)
            pfB[j] = W[(size_t)(bkh + j) * FTOT + colBase + bn];
    }

    for (int c = 0; c < 8; c++) {
        const int b = c & 1;
        uint16_t* As = smem + b * BUF_H;
        uint16_t* Bs = As + TILE_H;

        {
            #pragma unroll
            for (int p = 0; p < 4; p++) {
                float4 v = pfA[p];
                uint32_t* dh = (uint32_t*)(As + arow * SP + (akq + p) * 4);
                dh[0] = pack2h(v.x, v.y); dh[1] = pack2h(v.z, v.w);
            }
            #pragma unroll
            for (int j = 0; j < 8; j++)
                *(uint32_t*)(Bs + bn * SP + bkh + 2 * j) = pack2h(pfB[2 * j], pfB[2 * j + 1]);
        }

        if (c < 7) {
            int gr = rowBase + arow;
            const float4 z = make_float4(0.f, 0.f, 0.f, 0.f);
            const float* Ab = A + (size_t)gr * FTOT + (c + 1) * 32;
            #pragma unroll
            for (int p = 0; p < 4; p++)
                pfA[p] = (gr < M) ? *(const float4*)(Ab + (akq + p) * 4) : z;
            #pragma unroll
            for (int j = 0; j < 16; j++)
                pfB[j] = W[(size_t)((c + 1) * 32 + bkh + j) * FTOT + colBase + bn];
        }
        __syncthreads();

        const uint32_t as = smem_u32(As);
        const uint32_t bs = smem_u32(Bs);
        const int t = lane >> 3, r = lane & 7;
        #pragma unroll
        for (int ks = 0; ks < 2; ks++) {
            uint32_t Ah[4][4], Bh[4][2];
            const int a_row_off = (t & 1) * 8 + r;
            const int a_col = ks * 16 + (t >> 1) * 8;
            #pragma unroll
            for (int f = 0; f < 4; f++) {
                uint32_t off = ((mbase + f * 16 + a_row_off) * SP + a_col) * 2;
                ldsm_x4(as + off, Ah[f][0], Ah[f][1], Ah[f][2], Ah[f][3]);
            }
            const int b_row_off = (t >> 1) * 8 + r;
            const int b_col = ks * 16 + (t & 1) * 8;
            #pragma unroll
            for (int g = 0; g < 2; g++) {
                uint32_t off = ((nbase + g * 16 + b_row_off) * SP + b_col) * 2;
                ldsm_x4(bs + off, Bh[2 * g][0], Bh[2 * g][1], Bh[2 * g + 1][0], Bh[2 * g + 1][1]);
            }
            #pragma unroll
            for (int i = 0; i < 4; i++)
                #pragma unroll
                for (int j = 0; j < 4; j++)
                    mma_f16(acc[i][j], Ah[i], Bh[j]);
        }
    }

    // epilogue: store C (fp16) + fused el/er for this warp's head
    const int rq = lane >> 2;
    const int cq = (lane & 3) * 2;
    const int hIdx = (colBase >> 5) + (wid & 3);
    float alv[4][2], arv[4][2];
    #pragma unroll
    for (int j = 0; j < 4; j++) {
        int d0 = hIdx * HIDD + j * 8 + cq;
        alv[j][0] = al[d0]; alv[j][1] = al[d0 + 1];
        arv[j][0] = ar[d0]; arv[j][1] = ar[d0 + 1];
    }
    #pragma unroll
    for (int i = 0; i < 4; i++) {
        int r0 = rowBase + mbase + i * 16 + rq;
        int r1 = r0 + 8;
        float sl0 = 0.f, sr0 = 0.f, sl1 = 0.f, sr1 = 0.f;
        #pragma unroll
        for (int j = 0; j < 4; j++) {
            int cc = colBase + nbase + j * 8 + cq;
            if (r0 < M) *(uint32_t*)(C + (size_t)r0 * FTOT + cc) = pack2h(acc[i][j][0], acc[i][j][1]);
            if (r1 < M) *(uint32_t*)(C + (size_t)r1 * FTOT + cc) = pack2h(acc[i][j][2], acc[i][j][3]);
            sl0 = fmaf(acc[i][j][0], alv[j][0], fmaf(acc[i][j][1], alv[j][1], sl0));
            sr0 = fmaf(acc[i][j][0], arv[j][0], fmaf(acc[i][j][1], arv[j][1], sr0));
            sl1 = fmaf(acc[i][j][2], alv[j][0], fmaf(acc[i][j][3], alv[j][1], sl1));
            sr1 = fmaf(acc[i][j][2], arv[j][0], fmaf(acc[i][j][3], arv[j][1], sr1));
        }
        #pragma unroll
        for (int d = 1; d <= 2; d <<= 1) {
            sl0 += __shfl_xor_sync(0xffffffffu, sl0, d);
            sr0 += __shfl_xor_sync(0xffffffffu, sr0, d);
            sl1 += __shfl_xor_sync(0xffffffffu, sl1, d);
            sr1 += __shfl_xor_sync(0xffffffffu, sr1, d);
        }
        if ((lane & 3) == 0) {
            if (r0 < M) { el[r0 * NHEADS + hIdx] = sl0; er[r0 * NHEADS + hIdx] = sr0; }
            if (r1 < M) { el[r1 * NHEADS + hIdx] = sl1; er[r1 * NHEADS + hIdx] = sr1; }
        }
    }
}

// ---------------- CSR build ----------------
__global__ void hist_kernel(const int* __restrict__ dst, int* __restrict__ count) {
    int e = blockIdx.x * blockDim.x + threadIdx.x;
    if (e < EE) atomicAdd(&count[dst[e]], 1);
}

__global__ void scan_kernel(const int* __restrict__ count, int* __restrict__ off,
                            int* __restrict__ cursor) {
    __shared__ int wsum[32];
    __shared__ int carry;
    const int t = threadIdx.x;
    const int w = t >> 5, lane = t & 31;
    if (t == 0) carry = 0;
    __syncthreads();
    for (int base = 0; base < NN; base += 1024) {
        int i = base + t;
        int v = (i < NN) ? count[i] : 0;
        int incl = v;
        #pragma unroll
        for (int d = 1; d < 32; d <<= 1) {
            int x = __shfl_up_sync(0xffffffffu, incl, d);
            if (lane >= d) incl += x;
        }
        if (lane == 31) wsum[w] = incl;
        __syncthreads();
        if (w == 0) {
            int s = wsum[lane];
            #pragma unroll
            for (int d = 1; d < 32; d <<= 1) {
                int x = __shfl_up_sync(0xffffffffu, s, d);
                if (lane >= d) s += x;
            }
            wsum[lane] = s;
        }
        __syncthreads();
        int wpre = (w > 0) ? wsum[w - 1] : 0;
        int excl = carry + wpre + incl - v;
        if (i < NN) { off[i] = excl; cursor[i] = excl; }
        int total = wsum[31];
        __syncthreads();
        if (t == 0) carry += total;
        __syncthreads();
    }
    if (t == 0) off[NN] = carry;
}

__global__ void scatter_kernel(const int* __restrict__ dst, const int* __restrict__ srcArr,
                               int* __restrict__ cursor, int* __restrict__ srcs) {
    int e = blockIdx.x * blockDim.x + threadIdx.x;
    if (e < EE) {
        int pos = atomicAdd(&cursor[dst[e]], 1);
        srcs[pos] = srcArr[e];
    }
}

// ---------------- final-layer SGEMM (fp32) with fused el/er epilogue ----------------
__global__ void __launch_bounds__(128)
sgemm_final_kernel(const float* __restrict__ A, const float* __restrict__ B,
                   float* __restrict__ C, const float* __restrict__ al,
                   const float* __restrict__ ar, float* __restrict__ el,
                   float* __restrict__ er, int M) {
    constexpr int BM = 128, BN = 32, BK = 32, TM = 8, TN = 4;
    constexpr int TCOLS = BN / TN;   // 8
    constexpr int NT = 128;
    __shared__ float As[BK][BM];
    __shared__ float Bs[BK][BN];
    const int tid = threadIdx.x;
    const int tr = tid / TCOLS;
    const int tc = tid % TCOLS;
    const int rowBase = blockIdx.y * BM;

    float acc[TM][TN];
    #pragma unroll
    for (int i = 0; i < TM; i++)
        #pragma unroll
        for (int j = 0; j < TN; j++) acc[i][j] = 0.f;

    for (int k0 = 0; k0 < FTOT; k0 += BK) {
        #pragma unroll
        for (int i = tid * 4; i < BM * BK; i += NT * 4) {
            int m = i / BK, kk = i % BK;
            int gr = rowBase + m;
            float4 v = make_float4(0.f, 0.f, 0.f, 0.f);
            if (gr < M) v = *(const float4*)(A + (size_t)gr * FTOT + k0 + kk);
            As[kk + 0][m] = v.x; As[kk + 1][m] = v.y;
            As[kk + 2][m] = v.z; As[kk + 3][m] = v.w;
        }
        #pragma unroll
        for (int i = tid * 4; i < BK * BN; i += NT * 4) {
            int kk = i / BN, nn = i % BN;
            float4 v = *(const float4*)(B + (size_t)(k0 + kk) * BN + nn);
            *(float4*)&Bs[kk][nn] = v;
        }
        __syncthreads();
        #pragma unroll
        for (int kk = 0; kk < BK; kk++) {
            float a[TM], b[TN];
            #pragma unroll
            for (int i = 0; i < TM / 4; i++)
                *(float4*)&a[i * 4] = *(const float4*)&As[kk][tr * TM + i * 4];
            *(float4*)&b[0] = *(const float4*)&Bs[kk][tc * TN];
            #pragma unroll
            for (int i = 0; i < TM; i++)
                #pragma unroll
                for (int j = 0; j < TN; j++) acc[i][j] = fmaf(a[i], b[j], acc[i][j]);
        }
        __syncthreads();
    }
    float alv[TN], arv[TN];
    #pragma unroll
    for (int j = 0; j < TN; j++) { alv[j] = al[tc * TN + j]; arv[j] = ar[tc * TN + j]; }
    #pragma unroll
    for (int i = 0; i < TM; i++) {
        int r = rowBase + tr * TM + i;
        float pl = 0.f, pr = 0.f;
        #pragma unroll
        for (int j = 0; j < TN; j++) {
            pl = fmaf(acc[i][j], alv[j], pl);
            pr = fmaf(acc[i][j], arv[j], pr);
        }
        #pragma unroll
        for (int d = 1; d <= 4; d <<= 1) {
            pl += __shfl_xor_sync(0xffffffffu, pl, d);
            pr += __shfl_xor_sync(0xffffffffu, pr, d);
        }
        if (r < M) {
            *(float4*)(C + (size_t)r * BN + tc * TN) = *(float4*)&acc[i][0];
            if (tc == 0) { el[r] = pl; er[r] = pr; }
        }
    }
}

// ---------------- per-node warp: segment softmax + aggregate (8 heads, fp16 feat)
// Aggregate phase: lane l owns dims [8l, 8l+8) of the 256-dim row (head l>>2).
// One uint4 LDG per edge per warp (512B coalesced) instead of 8 scattered LDGs.
__global__ void __launch_bounds__(256)
agg8_kernel(const __half* __restrict__ feat, const float* __restrict__ el,
            const float* __restrict__ er, const float* __restrict__ bias,
            float* __restrict__ out, const int* __restrict__ off,
            const int* __restrict__ srcs) {
    int warp = (blockIdx.x * blockDim.x + threadIdx.x) >> 5;
    if (warp >= NN) return;
    const int lane = threadIdx.x & 31;
    const int n = warp;
    const int s = off[n], epnd = off[n + 1];
    const int hl = lane & 7;
    const int eslot = lane >> 3;
    const float er_h = er[n * NHEADS + hl];

    // single pass: online max + sum of exp (safe_exp guards -inf minus -inf)
    float mx = -INFINITY, sm = 0.f;
    for (int i = s + eslot; i < epnd; i += 4) {
        int src = srcs[i];
        float v = el[src * NHEADS + hl] + er_h;
        v = v > 0.f ? v : 0.2f * v;
        float m2 = fmaxf(mx, v);
        sm = sm * safe_exp(mx - m2) + safe_exp(v - m2);
        mx = m2;
    }
    #pragma unroll
    for (int d = 8; d <= 16; d <<= 1) {
        float om = __shfl_xor_sync(0xffffffffu, mx, d);
        float os = __shfl_xor_sync(0xffffffffu, sm, d);
        float m2 = fmaxf(mx, om);
        sm = sm * safe_exp(mx - m2) + os * safe_exp(om - m2);
        mx = m2;
    }
    const float inv = 1.0f / (sm + 1e-9f);

    // aggregate: lane owns dims [8*lane, 8*lane+8), all within head (lane>>2)
    const int myh = lane >> 2;
    float acc[8];
    #pragma unroll
    for (int q = 0; q < 8; q++) acc[q] = 0.f;
    const __half* fbase = feat + lane * 8;
    #pragma unroll 2
    for (int i = s; i < epnd; i++) {
        int src = srcs[i];
        float coef = 0.f;
        if (lane < 8) {   // lane == head index; mx/inv on this lane match head=lane
            float v = el[src * NHEADS + lane] + er_h;
            v = v > 0.f ? v : 0.2f * v;
            coef = safe_exp(v - mx) * inv;
        }
        float c = __shfl_sync(0xffffffffu, coef, myh);
        uint4 raw = *(const uint4*)(fbase + (size_t)src * FTOT);
        const __half2* hp = (const __half2*)&raw;
        #pragma unroll
        for (int q = 0; q < 4; q++) {
            float2 f = __half22float2(hp[q]);
            acc[q * 2]     = fmaf(c, f.x, acc[q * 2]);
            acc[q * 2 + 1] = fmaf(c, f.y, acc[q * 2 + 1]);
        }
    }
    // epilogue: +bias, ELU, two float4 stores (coalesced 1KB/row)
    float4 b0 = *(const float4*)(bias + lane * 8);
    float4 b1 = *(const float4*)(bias + lane * 8 + 4);
    float o[8];
    o[0] = acc[0] + b0.x; o[1] = acc[1] + b0.y; o[2] = acc[2] + b0.z; o[3] = acc[3] + b0.w;
    o[4] = acc[4] + b1.x; o[5] = acc[5] + b1.y; o[6] = acc[6] + b1.z; o[7] = acc[7] + b1.w;
    #pragma unroll
    for (int q = 0; q < 8; q++) o[q] = o[q] > 0.f ? o[q] : expm1f(o[q]);
    float* orow = out + (size_t)n * FTOT + lane * 8;
    *(float4*)(orow)     = make_float4(o[0], o[1], o[2], o[3]);
    *(float4*)(orow + 4) = make_float4(o[4], o[5], o[6], o[7]);
}

// ---------------- final layer aggregate (1 head, D=32) ----------------
__global__ void __launch_bounds__(256)
agg1_kernel(const float* __restrict__ feat2, const float* __restrict__ el,
            const float* __restrict__ er, const float* __restrict__ bias,
            float* __restrict__ out, const int* __restrict__ off,
            const int* __restrict__ srcs) {
    int warp = (blockIdx.x * blockDim.x + threadIdx.x) >> 5;
    if (warp >= NN) return;
    const int lane = threadIdx.x & 31;
    const int n = warp;
    const int s = off[n], epnd = off[n + 1];
    const float er_n = er[n];

    float mx = -INFINITY, sm = 0.f;
    for (int i = s + lane; i < epnd; i += 32) {
        int src = srcs[i];
        float v = el[src] + er_n;
        v = v > 0.f ? v : 0.2f * v;
        float m2 = fmaxf(mx, v);
        sm = sm * safe_exp(mx - m2) + safe_exp(v - m2);
        mx = m2;
    }
    #pragma unroll
    for (int d = 16; d >= 1; d >>= 1) {
        float om = __shfl_xor_sync(0xffffffffu, mx, d);
        float os = __shfl_xor_sync(0xffffffffu, sm, d);
        float m2 = fmaxf(mx, om);
        sm = sm * safe_exp(mx - m2) + os * safe_exp(om - m2);
        mx = m2;
    }
    const float inv = 1.0f / (sm + 1e-9f);

    float acc = 0.f;
    for (int i = s; i < epnd; i++) {
        int src = srcs[i];
        float v = el[src] + er_n;
        v = v > 0.f ? v : 0.2f * v;
        float coef = safe_exp(v - mx) * inv;
        acc = fmaf(coef, feat2[(size_t)src * HIDD + lane], acc);
    }
    out[(size_t)n * HIDD + lane] = acc + bias[lane];
}

// ---------------- launch ----------------
extern "C" void kernel_launch(void* const* d_in, const int* in_sizes, int n_in,
                              void* d_out, int out_size) {
    const float* features = (const float*)d_in[0];
    const int*   src      = (const int*)d_in[1];
    const int*   dst      = (const int*)d_in[2];
    const float* W0  = (const float*)d_in[3];
    const float* al0 = (const float*)d_in[4];
    const float* ar0 = (const float*)d_in[5];
    const float* b0  = (const float*)d_in[6];
    const float* W1  = (const float*)d_in[7];
    const float* al1 = (const float*)d_in[8];
    const float* ar1 = (const float*)d_in[9];
    const float* b1  = (const float*)d_in[10];
    const float* W2  = (const float*)d_in[11];
    const float* al2 = (const float*)d_in[12];
    const float* ar2 = (const float*)d_in[13];
    const float* b2  = (const float*)d_in[14];
    float* out = (float*)d_out;

    __half* featH;
    float *h, *feat2, *el, *er;
    int *count, *off, *cursor, *srcs;
    cudaGetSymbolAddress((void**)&featH,  g_featH);
    cudaGetSymbolAddress((void**)&h,      g_h);
    cudaGetSymbolAddress((void**)&feat2,  g_feat2);
    cudaGetSymbolAddress((void**)&el,     g_el);
    cudaGetSymbolAddress((void**)&er,     g_er);
    cudaGetSymbolAddress((void**)&count,  g_count);
    cudaGetSymbolAddress((void**)&off,    g_off);
    cudaGetSymbolAddress((void**)&cursor, g_cursor);
    cudaGetSymbolAddress((void**)&srcs,   g_srcs);

    cudaFuncSetAttribute(mma_gemm_kernel, cudaFuncAttributeMaxDynamicSharedMemorySize,
                         GEMM_SMEM);

    // CSR by dst (src values scattered directly)
    cudaMemsetAsync(count, 0, NN * sizeof(int));
    hist_kernel<<<(EE + 255) / 256, 256>>>(dst, count);
    scan_kernel<<<1, 1024>>>(count, off, cursor);
    scatter_kernel<<<(EE + 255) / 256, 256>>>(dst, src, cursor, srcs);

    const int aggBlocks = (NN * 32 + 255) / 256;
    dim3 gemmGrid(2, (NN + 127) / 128);
    dim3 gemmFinal(1, (NN + 127) / 128);

    // layer 0 (GEMM + fused el/er, fp16 out)
    mma_gemm_kernel<<<gemmGrid, 256, GEMM_SMEM>>>(features, W0, featH, al0, ar0, el, er, NN);
    agg8_kernel<<<aggBlocks, 256>>>(featH, el, er, b0, h, off, srcs);

    // layer 1
    mma_gemm_kernel<<<gemmGrid, 256, GEMM_SMEM>>>(h, W1, featH, al1, ar1, el, er, NN);
    agg8_kernel<<<aggBlocks, 256>>>(featH, el, er, b1, h, off, srcs);

    // layer 2 (single head, D=32, no activation; fused el/er)
    sgemm_final_kernel<<<gemmFinal, 128>>>(h, W2, feat2, al2, ar2, el, er, NN);
    agg1_kernel<<<aggBlocks, 256>>>(feat2, el, er, b2, out, off, srcs);
}

// round 10
// speedup vs baseline: 2.5837x; 1.0973x over previous
#include <cuda_runtime.h>
#include <cuda_fp16.h>
#include <math.h>
#include <stdint.h>

#define NN 50000
#define EE 800000
#define NHEADS 8
#define HIDD 32
#define FTOT 256   // NHEADS*HIDD, also IN_FEATS

// ---------------- scratch (static device globals; no allocation) ----------------
__device__ __align__(16) __half g_featH[(size_t)NN * FTOT];  // 25.6 MB (GEMM out, fp16)
__device__ __align__(16) __half g_hH[(size_t)NN * FTOT];     // 25.6 MB (agg8 out, fp16)
__device__ __align__(16) float g_feat2[(size_t)NN * HIDD];   // 6.4 MB
__device__ __align__(16) float g_el[NN * NHEADS];
__device__ __align__(16) float g_er[NN * NHEADS];
__device__ int g_count[NN];
__device__ int g_off[NN + 1];
__device__ int g_cursor[NN];
__device__ int g_srcs[EE];    // src node of each edge, sorted by dst

// ---------------- helpers ----------------
__device__ __forceinline__ uint32_t smem_u32(const void* p) {
    uint32_t a;
    asm("{ .reg .u64 t; cvta.to.shared.u64 t, %1; cvt.u32.u64 %0, t; }" : "=r"(a) : "l"(p));
    return a;
}
__device__ __forceinline__ void ldsm_x4(uint32_t addr, uint32_t& r0, uint32_t& r1,
                                        uint32_t& r2, uint32_t& r3) {
    asm volatile("ldmatrix.sync.aligned.m8n8.x4.shared.b16 {%0,%1,%2,%3}, [%4];"
                 : "=r"(r0), "=r"(r1), "=r"(r2), "=r"(r3) : "r"(addr));
}
__device__ __forceinline__ void mma_f16(float* d, const uint32_t* a, const uint32_t* b) {
    asm volatile(
        "mma.sync.aligned.m16n8k16.row.col.f32.f16.f16.f32 "
        "{%0,%1,%2,%3}, {%4,%5,%6,%7}, {%8,%9}, {%0,%1,%2,%3};"
        : "+f"(d[0]), "+f"(d[1]), "+f"(d[2]), "+f"(d[3])
        : "r"(a[0]), "r"(a[1]), "r"(a[2]), "r"(a[3]), "r"(b[0]), "r"(b[1]));
}
__device__ __forceinline__ uint32_t pack2h(float a, float b) {
    __half2 t = __floats2half2_rn(a, b);
    return *(uint32_t*)&t;
}
// exp argument guard: fmaxf(NaN, -88) = -88, so (-inf) - (-inf) merges stay finite
__device__ __forceinline__ float safe_exp(float x) {
    return __expf(fmaxf(x, -88.f));
}

// A-tile loaders: 16 contiguous elements -> 8 packed fp16 pairs
__device__ __forceinline__ void loadA16(const float* p, uint32_t* d) {
    const float4* q = (const float4*)p;
    #pragma unroll
    for (int i = 0; i < 4; i++) {
        float4 v = q[i];
        d[2 * i]     = pack2h(v.x, v.y);
        d[2 * i + 1] = pack2h(v.z, v.w);
    }
}
__device__ __forceinline__ void loadA16(const __half* p, uint32_t* d) {
    uint4 a = ((const uint4*)p)[0];
    uint4 b = ((const uint4*)p)[1];
    d[0] = a.x; d[1] = a.y; d[2] = a.z; d[3] = a.w;
    d[4] = b.x; d[5] = b.y; d[6] = b.z; d[7] = b.w;
}
__device__ __forceinline__ void zeroA16(uint32_t* d) {
    #pragma unroll
    for (int q = 0; q < 8; q++) d[q] = 0u;
}

// ---------------- mma.sync fp16 GEMM: C[M x 256] = A[M x 256] * W[256 x 256]
#define SP 40                      // smem row pitch in halfs
#define TILE_H (128 * SP)          // halfs per logical tile
#define BUF_H (2 * TILE_H)         // As | Bs
#define GEMM_SMEM (2 * BUF_H * 2)  // 40960 bytes

template <typename TA>
__global__ void __launch_bounds__(256, 2)
mma_gemm_kernel(const TA* __restrict__ A, const float* __restrict__ W,
                __half* __restrict__ C, const float* __restrict__ al,
                const float* __restrict__ ar, float* __restrict__ el,
                float* __restrict__ er, int M) {
    extern __shared__ __half2 smem_raw[];
    uint16_t* smem = (uint16_t*)smem_raw;
    const int tid = threadIdx.x;
    const int wid = tid >> 5;
    const int lane = tid & 31;
    const int rowBase = blockIdx.y * 128;
    const int colBase = blockIdx.x * 128;
    const int mbase = (wid >> 2) * 64;   // warpM in {0,1}
    const int nbase = (wid & 3) * 32;    // warpN in {0..3} == head within tile

    float acc[4][4][4];
    #pragma unroll
    for (int i = 0; i < 4; i++)
        #pragma unroll
        for (int j = 0; j < 4; j++)
            #pragma unroll
            for (int q = 0; q < 4; q++) acc[i][j][q] = 0.f;

    const int arow = tid >> 1;            // A: 2 threads per row
    const int akq  = (tid & 1) * 4;       // first float4-equivalent index
    const int bn   = tid & 127;
    const int bkh  = (tid >> 7) * 16;

    uint32_t praw[8];
    float pfB[16];

    {
        int gr = rowBase + arow;
        if (gr < M) loadA16(A + (size_t)gr * FTOT + akq * 4, praw);
        else zeroA16(praw);
        #pragma unroll
        for (int j = 0; j < 16; j++)
            pfB[j] = W[(size_t)(bkh + j) * FTOT + colBase + bn];
    }

    for (int c = 0; c < 8; c++) {
        const int b = c & 1;
        uint16_t* As = smem + b * BUF_H;
        uint16_t* Bs = As + TILE_H;

        {
            uint4* dh = (uint4*)(As + arow * SP + akq * 4);
            dh[0] = make_uint4(praw[0], praw[1], praw[2], praw[3]);
            dh[1] = make_uint4(praw[4], praw[5], praw[6], praw[7]);
            #pragma unroll
            for (int j = 0; j < 8; j++)
                *(uint32_t*)(Bs + bn * SP + bkh + 2 * j) = pack2h(pfB[2 * j], pfB[2 * j + 1]);
        }

        if (c < 7) {
            int gr = rowBase + arow;
            if (gr < M) loadA16(A + (size_t)gr * FTOT + (c + 1) * 32 + akq * 4, praw);
            else zeroA16(praw);
            #pragma unroll
            for (int j = 0; j < 16; j++)
                pfB[j] = W[(size_t)((c + 1) * 32 + bkh + j) * FTOT + colBase + bn];
        }
        __syncthreads();

        const uint32_t as = smem_u32(As);
        const uint32_t bs = smem_u32(Bs);
        const int t = lane >> 3, r = lane & 7;
        #pragma unroll
        for (int ks = 0; ks < 2; ks++) {
            uint32_t Ah[4][4], Bh[4][2];
            const int a_row_off = (t & 1) * 8 + r;
            const int a_col = ks * 16 + (t >> 1) * 8;
            #pragma unroll
            for (int f = 0; f < 4; f++) {
                uint32_t off = ((mbase + f * 16 + a_row_off) * SP + a_col) * 2;
                ldsm_x4(as + off, Ah[f][0], Ah[f][1], Ah[f][2], Ah[f][3]);
            }
            const int b_row_off = (t >> 1) * 8 + r;
            const int b_col = ks * 16 + (t & 1) * 8;
            #pragma unroll
            for (int g = 0; g < 2; g++) {
                uint32_t off = ((nbase + g * 16 + b_row_off) * SP + b_col) * 2;
                ldsm_x4(bs + off, Bh[2 * g][0], Bh[2 * g][1], Bh[2 * g + 1][0], Bh[2 * g + 1][1]);
            }
            #pragma unroll
            for (int i = 0; i < 4; i++)
                #pragma unroll
                for (int j = 0; j < 4; j++)
                    mma_f16(acc[i][j], Ah[i], Bh[j]);
        }
    }

    // epilogue: store C (fp16) + fused el/er for this warp's head
    const int rq = lane >> 2;
    const int cq = (lane & 3) * 2;
    const int hIdx = (colBase >> 5) + (wid & 3);
    float alv[4][2], arv[4][2];
    #pragma unroll
    for (int j = 0; j < 4; j++) {
        int d0 = hIdx * HIDD + j * 8 + cq;
        alv[j][0] = al[d0]; alv[j][1] = al[d0 + 1];
        arv[j][0] = ar[d0]; arv[j][1] = ar[d0 + 1];
    }
    #pragma unroll
    for (int i = 0; i < 4; i++) {
        int r0 = rowBase + mbase + i * 16 + rq;
        int r1 = r0 + 8;
        float sl0 = 0.f, sr0 = 0.f, sl1 = 0.f, sr1 = 0.f;
        #pragma unroll
        for (int j = 0; j < 4; j++) {
            int cc = colBase + nbase + j * 8 + cq;
            if (r0 < M) *(uint32_t*)(C + (size_t)r0 * FTOT + cc) = pack2h(acc[i][j][0], acc[i][j][1]);
            if (r1 < M) *(uint32_t*)(C + (size_t)r1 * FTOT + cc) = pack2h(acc[i][j][2], acc[i][j][3]);
            sl0 = fmaf(acc[i][j][0], alv[j][0], fmaf(acc[i][j][1], alv[j][1], sl0));
            sr0 = fmaf(acc[i][j][0], arv[j][0], fmaf(acc[i][j][1], arv[j][1], sr0));
            sl1 = fmaf(acc[i][j][2], alv[j][0], fmaf(acc[i][j][3], alv[j][1], sl1));
            sr1 = fmaf(acc[i][j][2], arv[j][0], fmaf(acc[i][j][3], arv[j][1], sr1));
        }
        #pragma unroll
        for (int d = 1; d <= 2; d <<= 1) {
            sl0 += __shfl_xor_sync(0xffffffffu, sl0, d);
            sr0 += __shfl_xor_sync(0xffffffffu, sr0, d);
            sl1 += __shfl_xor_sync(0xffffffffu, sl1, d);
            sr1 += __shfl_xor_sync(0xffffffffu, sr1, d);
        }
        if ((lane & 3) == 0) {
            if (r0 < M) { el[r0 * NHEADS + hIdx] = sl0; er[r0 * NHEADS + hIdx] = sr0; }
            if (r1 < M) { el[r1 * NHEADS + hIdx] = sl1; er[r1 * NHEADS + hIdx] = sr1; }
        }
    }
}

// ---------------- CSR build ----------------
__global__ void hist_kernel(const int* __restrict__ dst, int* __restrict__ count) {
    int e = blockIdx.x * blockDim.x + threadIdx.x;
    if (e < EE) atomicAdd(&count[dst[e]], 1);
}

__global__ void scan_kernel(const int* __restrict__ count, int* __restrict__ off,
                            int* __restrict__ cursor) {
    __shared__ int wsum[32];
    __shared__ int carry;
    const int t = threadIdx.x;
    const int w = t >> 5, lane = t & 31;
    if (t == 0) carry = 0;
    __syncthreads();
    for (int base = 0; base < NN; base += 1024) {
        int i = base + t;
        int v = (i < NN) ? count[i] : 0;
        int incl = v;
        #pragma unroll
        for (int d = 1; d < 32; d <<= 1) {
            int x = __shfl_up_sync(0xffffffffu, incl, d);
            if (lane >= d) incl += x;
        }
        if (lane == 31) wsum[w] = incl;
        __syncthreads();
        if (w == 0) {
            int s = wsum[lane];
            #pragma unroll
            for (int d = 1; d < 32; d <<= 1) {
                int x = __shfl_up_sync(0xffffffffu, s, d);
                if (lane >= d) s += x;
            }
            wsum[lane] = s;
        }
        __syncthreads();
        int wpre = (w > 0) ? wsum[w - 1] : 0;
        int excl = carry + wpre + incl - v;
        if (i < NN) { off[i] = excl; cursor[i] = excl; }
        int total = wsum[31];
        __syncthreads();
        if (t == 0) carry += total;
        __syncthreads();
    }
    if (t == 0) off[NN] = carry;
}

__global__ void scatter_kernel(const int* __restrict__ dst, const int* __restrict__ srcArr,
                               int* __restrict__ cursor, int* __restrict__ srcs) {
    int e = blockIdx.x * blockDim.x + threadIdx.x;
    if (e < EE) {
        int pos = atomicAdd(&cursor[dst[e]], 1);
        srcs[pos] = srcArr[e];
    }
}

// ---------------- final-layer SGEMM (fp16 A, fp32 math) with fused el/er ----------------
__global__ void __launch_bounds__(128)
sgemm_final_kernel(const __half* __restrict__ A, const float* __restrict__ B,
                   float* __restrict__ C, const float* __restrict__ al,
                   const float* __restrict__ ar, float* __restrict__ el,
                   float* __restrict__ er, int M) {
    constexpr int BM = 128, BN = 32, BK = 32, TM = 8, TN = 4;
    constexpr int TCOLS = BN / TN;   // 8
    constexpr int NT = 128;
    __shared__ float As[BK][BM];
    __shared__ float Bs[BK][BN];
    const int tid = threadIdx.x;
    const int tr = tid / TCOLS;
    const int tc = tid % TCOLS;
    const int rowBase = blockIdx.y * BM;

    float acc[TM][TN];
    #pragma unroll
    for (int i = 0; i < TM; i++)
        #pragma unroll
        for (int j = 0; j < TN; j++) acc[i][j] = 0.f;

    for (int k0 = 0; k0 < FTOT; k0 += BK) {
        #pragma unroll
        for (int i = tid * 4; i < BM * BK; i += NT * 4) {
            int m = i / BK, kk = i % BK;
            int gr = rowBase + m;
            float4 v = make_float4(0.f, 0.f, 0.f, 0.f);
            if (gr < M) {
                uint2 hraw = *(const uint2*)(A + (size_t)gr * FTOT + k0 + kk);
                float2 f0 = __half22float2(*(const __half2*)&hraw.x);
                float2 f1 = __half22float2(*(const __half2*)&hraw.y);
                v = make_float4(f0.x, f0.y, f1.x, f1.y);
            }
            As[kk + 0][m] = v.x; As[kk + 1][m] = v.y;
            As[kk + 2][m] = v.z; As[kk + 3][m] = v.w;
        }
        #pragma unroll
        for (int i = tid * 4; i < BK * BN; i += NT * 4) {
            int kk = i / BN, nn = i % BN;
            float4 v = *(const float4*)(B + (size_t)(k0 + kk) * BN + nn);
            *(float4*)&Bs[kk][nn] = v;
        }
        __syncthreads();
        #pragma unroll
        for (int kk = 0; kk < BK; kk++) {
            float a[TM], b[TN];
            #pragma unroll
            for (int i = 0; i < TM / 4; i++)
                *(float4*)&a[i * 4] = *(const float4*)&As[kk][tr * TM + i * 4];
            *(float4*)&b[0] = *(const float4*)&Bs[kk][tc * TN];
            #pragma unroll
            for (int i = 0; i < TM; i++)
                #pragma unroll
                for (int j = 0; j < TN; j++) acc[i][j] = fmaf(a[i], b[j], acc[i][j]);
        }
        __syncthreads();
    }
    float alv[TN], arv[TN];
    #pragma unroll
    for (int j = 0; j < TN; j++) { alv[j] = al[tc * TN + j]; arv[j] = ar[tc * TN + j]; }
    #pragma unroll
    for (int i = 0; i < TM; i++) {
        int r = rowBase + tr * TM + i;
        float pl = 0.f, pr = 0.f;
        #pragma unroll
        for (int j = 0; j < TN; j++) {
            pl = fmaf(acc[i][j], alv[j], pl);
            pr = fmaf(acc[i][j], arv[j], pr);
        }
        #pragma unroll
        for (int d = 1; d <= 4; d <<= 1) {
            pl += __shfl_xor_sync(0xffffffffu, pl, d);
            pr += __shfl_xor_sync(0xffffffffu, pr, d);
        }
        if (r < M) {
            *(float4*)(C + (size_t)r * BN + tc * TN) = *(float4*)&acc[i][0];
            if (tc == 0) { el[r] = pl; er[r] = pr; }
        }
    }
}

// ---------------- per-node warp: segment softmax + aggregate (8 heads, fp16 feat)
// Aggregate: lane l owns dims [8l, 8l+8) (head l>>2). Main loop batches 4 edges:
// each lane computes the coefficient for (edge lane>>3, head lane&7), then 4
// independent uint4 feat loads are issued (MLP 4). Output stored fp16.
__global__ void __launch_bounds__(256)
agg8_kernel(const __half* __restrict__ feat, const float* __restrict__ el,
            const float* __restrict__ er, const float* __restrict__ bias,
            __half* __restrict__ out, const int* __restrict__ off,
            const int* __restrict__ srcs) {
    int warp = (blockIdx.x * blockDim.x + threadIdx.x) >> 5;
    if (warp >= NN) return;
    const int lane = threadIdx.x & 31;
    const int n = warp;
    const int s = off[n], epnd = off[n + 1];
    const int hl = lane & 7;
    const int eslot = lane >> 3;
    const float er_h = er[n * NHEADS + hl];

    // pass 1: online max + sum of exp (safe_exp guards -inf minus -inf)
    float mx = -INFINITY, sm = 0.f;
    for (int i = s + eslot; i < epnd; i += 4) {
        int src = srcs[i];
        float v = el[src * NHEADS + hl] + er_h;
        v = v > 0.f ? v : 0.2f * v;
        float m2 = fmaxf(mx, v);
        sm = sm * safe_exp(mx - m2) + safe_exp(v - m2);
        mx = m2;
    }
    #pragma unroll
    for (int d = 8; d <= 16; d <<= 1) {
        float om = __shfl_xor_sync(0xffffffffu, mx, d);
        float os = __shfl_xor_sync(0xffffffffu, sm, d);
        float m2 = fmaxf(mx, om);
        sm = sm * safe_exp(mx - m2) + os * safe_exp(om - m2);
        mx = m2;
    }
    const float inv = 1.0f / (sm + 1e-9f);
    // after the head-reduce, every lane's mx/inv are those of head hl = lane&7

    const int myh = lane >> 2;
    float acc[8];
    #pragma unroll
    for (int q = 0; q < 8; q++) acc[q] = 0.f;
    const __half* fbase = feat + lane * 8;

    int i = s;
    // batched: 4 edges per iteration
    for (; i + 4 <= epnd; i += 4) {
        int esrc = srcs[i + eslot];                       // edge (lane>>3)
        float v = el[esrc * NHEADS + hl] + er_h;          // head (lane&7)
        v = v > 0.f ? v : 0.2f * v;
        float coef = safe_exp(v - mx) * inv;
        float c[4]; int se[4];
        #pragma unroll
        for (int e = 0; e < 4; e++) {
            c[e]  = __shfl_sync(0xffffffffu, coef, e * 8 + myh);
            se[e] = __shfl_sync(0xffffffffu, esrc, e * 8);
        }
        uint4 raw[4];
        #pragma unroll
        for (int e = 0; e < 4; e++)
            raw[e] = *(const uint4*)(fbase + (size_t)se[e] * FTOT);
        #pragma unroll
        for (int e = 0; e < 4; e++) {
            const __half2* hp = (const __half2*)&raw[e];
            #pragma unroll
            for (int q = 0; q < 4; q++) {
                float2 f = __half22float2(hp[q]);
                acc[q * 2]     = fmaf(c[e], f.x, acc[q * 2]);
                acc[q * 2 + 1] = fmaf(c[e], f.y, acc[q * 2 + 1]);
            }
        }
    }
    // tail
    for (; i < epnd; i++) {
        int src = srcs[i];
        float coef = 0.f;
        if (lane < 8) {
            float v = el[src * NHEADS + lane] + er_h;
            v = v > 0.f ? v : 0.2f * v;
            coef = safe_exp(v - mx) * inv;
        }
        float c = __shfl_sync(0xffffffffu, coef, myh);
        uint4 raw = *(const uint4*)(fbase + (size_t)src * FTOT);
        const __half2* hp = (const __half2*)&raw;
        #pragma unroll
        for (int q = 0; q < 4; q++) {
            float2 f = __half22float2(hp[q]);
            acc[q * 2]     = fmaf(c, f.x, acc[q * 2]);
            acc[q * 2 + 1] = fmaf(c, f.y, acc[q * 2 + 1]);
        }
    }
    // epilogue: +bias, ELU, fp16 pack, one uint4 store (coalesced 512B/row)
    float4 b0 = *(const float4*)(bias + lane * 8);
    float4 b1 = *(const float4*)(bias + lane * 8 + 4);
    float o[8];
    o[0] = acc[0] + b0.x; o[1] = acc[1] + b0.y; o[2] = acc[2] + b0.z; o[3] = acc[3] + b0.w;
    o[4] = acc[4] + b1.x; o[5] = acc[5] + b1.y; o[6] = acc[6] + b1.z; o[7] = acc[7] + b1.w;
    #pragma unroll
    for (int q = 0; q < 8; q++) o[q] = o[q] > 0.f ? o[q] : expm1f(o[q]);
    uint4 packed = make_uint4(pack2h(o[0], o[1]), pack2h(o[2], o[3]),
                              pack2h(o[4], o[5]), pack2h(o[6], o[7]));
    *(uint4*)(out + (size_t)n * FTOT + lane * 8) = packed;
}

// ---------------- final layer aggregate (1 head, D=32) ----------------
__global__ void __launch_bounds__(256)
agg1_kernel(const float* __restrict__ feat2, const float* __restrict__ el,
            const float* __restrict__ er, const float* __restrict__ bias,
            float* __restrict__ out, const int* __restrict__ off,
            const int* __restrict__ srcs) {
    int warp = (blockIdx.x * blockDim.x + threadIdx.x) >> 5;
    if (warp >= NN) return;
    const int lane = threadIdx.x & 31;
    const int n = warp;
    const int s = off[n], epnd = off[n + 1];
    const float er_n = er[n];

    float mx = -INFINITY, sm = 0.f;
    for (int i = s + lane; i < epnd; i += 32) {
        int src = srcs[i];
        float v = el[src] + er_n;
        v = v > 0.f ? v : 0.2f * v;
        float m2 = fmaxf(mx, v);
        sm = sm * safe_exp(mx - m2) + safe_exp(v - m2);
        mx = m2;
    }
    #pragma unroll
    for (int d = 16; d >= 1; d >>= 1) {
        float om = __shfl_xor_sync(0xffffffffu, mx, d);
        float os = __shfl_xor_sync(0xffffffffu, sm, d);
        float m2 = fmaxf(mx, om);
        sm = sm * safe_exp(mx - m2) + os * safe_exp(om - m2);
        mx = m2;
    }
    const float inv = 1.0f / (sm + 1e-9f);

    float acc = 0.f;
    for (int i = s; i < epnd; i++) {
        int src = srcs[i];
        float v = el[src] + er_n;
        v = v > 0.f ? v : 0.2f * v;
        float coef = safe_exp(v - mx) * inv;
        acc = fmaf(coef, feat2[(size_t)src * HIDD + lane], acc);
    }
    out[(size_t)n * HIDD + lane] = acc + bias[lane];
}

// ---------------- launch ----------------
extern "C" void kernel_launch(void* const* d_in, const int* in_sizes, int n_in,
                              void* d_out, int out_size) {
    const float* features = (const float*)d_in[0];
    const int*   src      = (const int*)d_in[1];
    const int*   dst      = (const int*)d_in[2];
    const float* W0  = (const float*)d_in[3];
    const float* al0 = (const float*)d_in[4];
    const float* ar0 = (const float*)d_in[5];
    const float* b0  = (const float*)d_in[6];
    const float* W1  = (const float*)d_in[7];
    const float* al1 = (const float*)d_in[8];
    const float* ar1 = (const float*)d_in[9];
    const float* b1  = (const float*)d_in[10];
    const float* W2  = (const float*)d_in[11];
    const float* al2 = (const float*)d_in[12];
    const float* ar2 = (const float*)d_in[13];
    const float* b2  = (const float*)d_in[14];
    float* out = (float*)d_out;

    __half *featH, *hH;
    float *feat2, *el, *er;
    int *count, *off, *cursor, *srcs;
    cudaGetSymbolAddress((void**)&featH,  g_featH);
    cudaGetSymbolAddress((void**)&hH,     g_hH);
    cudaGetSymbolAddress((void**)&feat2,  g_feat2);
    cudaGetSymbolAddress((void**)&el,     g_el);
    cudaGetSymbolAddress((void**)&er,     g_er);
    cudaGetSymbolAddress((void**)&count,  g_count);
    cudaGetSymbolAddress((void**)&off,    g_off);
    cudaGetSymbolAddress((void**)&cursor, g_cursor);
    cudaGetSymbolAddress((void**)&srcs,   g_srcs);

    cudaFuncSetAttribute(mma_gemm_kernel<float>,
                         cudaFuncAttributeMaxDynamicSharedMemorySize, GEMM_SMEM);
    cudaFuncSetAttribute(mma_gemm_kernel<__half>,
                         cudaFuncAttributeMaxDynamicSharedMemorySize, GEMM_SMEM);

    // CSR by dst (src values scattered directly)
    cudaMemsetAsync(count, 0, NN * sizeof(int));
    hist_kernel<<<(EE + 255) / 256, 256>>>(dst, count);
    scan_kernel<<<1, 1024>>>(count, off, cursor);
    scatter_kernel<<<(EE + 255) / 256, 256>>>(dst, src, cursor, srcs);

    const int aggBlocks = (NN * 32 + 255) / 256;
    dim3 gemmGrid(2, (NN + 127) / 128);
    dim3 gemmFinal(1, (NN + 127) / 128);

    // layer 0 (GEMM fp32-in + fused el/er, fp16 out)
    mma_gemm_kernel<float><<<gemmGrid, 256, GEMM_SMEM>>>(features, W0, featH, al0, ar0, el, er, NN);
    agg8_kernel<<<aggBlocks, 256>>>(featH, el, er, b0, hH, off, srcs);

    // layer 1 (GEMM fp16-in)
    mma_gemm_kernel<__half><<<gemmGrid, 256, GEMM_SMEM>>>(hH, W1, featH, al1, ar1, el, er, NN);
    agg8_kernel<<<aggBlocks, 256>>>(featH, el, er, b1, hH, off, srcs);

    // layer 2 (single head, D=32, no activation; fused el/er)
    sgemm_final_kernel<<<gemmFinal, 128>>>(hH, W2, feat2, al2, ar2, el, er, NN);
    agg1_kernel<<<aggBlocks, 256>>>(feat2, el, er, b2, out, off, srcs);
}

// round 11
// speedup vs baseline: 2.6176x; 1.0131x over previous
#include <cuda_runtime.h>
#include <cuda_fp16.h>
#include <math.h>
#include <stdint.h>

#define NN 50000
#define EE 800000
#define NHEADS 8
#define HIDD 32
#define FTOT 256   // NHEADS*HIDD, also IN_FEATS

// ---------------- scratch (static device globals; no allocation) ----------------
__device__ __align__(16) __half g_featH[(size_t)NN * FTOT];  // 25.6 MB (GEMM out, fp16)
__device__ __align__(16) __half g_hH[(size_t)NN * FTOT];     // 25.6 MB (agg8 out, fp16)
__device__ __align__(16) float g_feat2[(size_t)NN * HIDD];   // 6.4 MB
__device__ __align__(16) float g_el[NN * NHEADS];
__device__ __align__(16) float g_er[NN * NHEADS];
__device__ int g_count[NN];
__device__ int g_off[NN + 1];
__device__ int g_cursor[NN];
__device__ int g_srcs[EE];    // src node of each edge, sorted by dst

// ---------------- helpers ----------------
__device__ __forceinline__ uint32_t smem_u32(const void* p) {
    uint32_t a;
    asm("{ .reg .u64 t; cvta.to.shared.u64 t, %1; cvt.u32.u64 %0, t; }" : "=r"(a) : "l"(p));
    return a;
}
__device__ __forceinline__ void ldsm_x4(uint32_t addr, uint32_t& r0, uint32_t& r1,
                                        uint32_t& r2, uint32_t& r3) {
    asm volatile("ldmatrix.sync.aligned.m8n8.x4.shared.b16 {%0,%1,%2,%3}, [%4];"
                 : "=r"(r0), "=r"(r1), "=r"(r2), "=r"(r3) : "r"(addr));
}
__device__ __forceinline__ void mma_f16(float* d, const uint32_t* a, const uint32_t* b) {
    asm volatile(
        "mma.sync.aligned.m16n8k16.row.col.f32.f16.f16.f32 "
        "{%0,%1,%2,%3}, {%4,%5,%6,%7}, {%8,%9}, {%0,%1,%2,%3};"
        : "+f"(d[0]), "+f"(d[1]), "+f"(d[2]), "+f"(d[3])
        : "r"(a[0]), "r"(a[1]), "r"(a[2]), "r"(a[3]), "r"(b[0]), "r"(b[1]));
}
__device__ __forceinline__ uint32_t pack2h(float a, float b) {
    __half2 t = __floats2half2_rn(a, b);
    return *(uint32_t*)&t;
}
// exp argument guard: fmaxf(NaN, -88) = -88, so (-inf) - (-inf) merges stay finite
__device__ __forceinline__ float safe_exp(float x) {
    return __expf(fmaxf(x, -88.f));
}

// A-tile loaders: 16 contiguous elements -> 8 packed fp16 pairs
__device__ __forceinline__ void loadA16(const float* p, uint32_t* d) {
    const float4* q = (const float4*)p;
    #pragma unroll
    for (int i = 0; i < 4; i++) {
        float4 v = q[i];
        d[2 * i]     = pack2h(v.x, v.y);
        d[2 * i + 1] = pack2h(v.z, v.w);
    }
}
__device__ __forceinline__ void loadA16(const __half* p, uint32_t* d) {
    uint4 a = ((const uint4*)p)[0];
    uint4 b = ((const uint4*)p)[1];
    d[0] = a.x; d[1] = a.y; d[2] = a.z; d[3] = a.w;
    d[4] = b.x; d[5] = b.y; d[6] = b.z; d[7] = b.w;
}
__device__ __forceinline__ void zeroA16(uint32_t* d) {
    #pragma unroll
    for (int q = 0; q < 8; q++) d[q] = 0u;
}

// ---------------- mma.sync fp16 GEMM: C[M x 256] = A[M x 256] * W[256 x 256]
#define SP 40                      // smem row pitch in halfs
#define TILE_H (128 * SP)          // halfs per logical tile
#define BUF_H (2 * TILE_H)         // As | Bs
#define GEMM_SMEM (2 * BUF_H * 2)  // 40960 bytes

template <typename TA>
__global__ void __launch_bounds__(256, 2)
mma_gemm_kernel(const TA* __restrict__ A, const float* __restrict__ W,
                __half* __restrict__ C, const float* __restrict__ al,
                const float* __restrict__ ar, float* __restrict__ el,
                float* __restrict__ er, int M) {
    extern __shared__ __half2 smem_raw[];
    uint16_t* smem = (uint16_t*)smem_raw;
    const int tid = threadIdx.x;
    const int wid = tid >> 5;
    const int lane = tid & 31;
    const int rowBase = blockIdx.y * 128;
    const int colBase = blockIdx.x * 128;
    const int mbase = (wid >> 2) * 64;   // warpM in {0,1}
    const int nbase = (wid & 3) * 32;    // warpN in {0..3} == head within tile

    float acc[4][4][4];
    #pragma unroll
    for (int i = 0; i < 4; i++)
        #pragma unroll
        for (int j = 0; j < 4; j++)
            #pragma unroll
            for (int q = 0; q < 4; q++) acc[i][j][q] = 0.f;

    const int arow = tid >> 1;            // A: 2 threads per row
    const int akq  = (tid & 1) * 4;       // first float4-equivalent index
    const int bn   = tid & 127;
    const int bkh  = (tid >> 7) * 16;

    uint32_t praw[8];
    float pfB[16];

    {
        int gr = rowBase + arow;
        if (gr < M) loadA16(A + (size_t)gr * FTOT + akq * 4, praw);
        else zeroA16(praw);
        #pragma unroll
        for (int j = 0; j < 16; j++)
            pfB[j] = W[(size_t)(bkh + j) * FTOT + colBase + bn];
    }

    for (int c = 0; c < 8; c++) {
        const int b = c & 1;
        uint16_t* As = smem + b * BUF_H;
        uint16_t* Bs = As + TILE_H;

        {
            uint4* dh = (uint4*)(As + arow * SP + akq * 4);
            dh[0] = make_uint4(praw[0], praw[1], praw[2], praw[3]);
            dh[1] = make_uint4(praw[4], praw[5], praw[6], praw[7]);
            #pragma unroll
            for (int j = 0; j < 8; j++)
                *(uint32_t*)(Bs + bn * SP + bkh + 2 * j) = pack2h(pfB[2 * j], pfB[2 * j + 1]);
        }

        if (c < 7) {
            int gr = rowBase + arow;
            if (gr < M) loadA16(A + (size_t)gr * FTOT + (c + 1) * 32 + akq * 4, praw);
            else zeroA16(praw);
            #pragma unroll
            for (int j = 0; j < 16; j++)
                pfB[j] = W[(size_t)((c + 1) * 32 + bkh + j) * FTOT + colBase + bn];
        }
        __syncthreads();

        const uint32_t as = smem_u32(As);
        const uint32_t bs = smem_u32(Bs);
        const int t = lane >> 3, r = lane & 7;
        #pragma unroll
        for (int ks = 0; ks < 2; ks++) {
            uint32_t Ah[4][4], Bh[4][2];
            const int a_row_off = (t & 1) * 8 + r;
            const int a_col = ks * 16 + (t >> 1) * 8;
            #pragma unroll
            for (int f = 0; f < 4; f++) {
                uint32_t off = ((mbase + f * 16 + a_row_off) * SP + a_col) * 2;
                ldsm_x4(as + off, Ah[f][0], Ah[f][1], Ah[f][2], Ah[f][3]);
            }
            const int b_row_off = (t >> 1) * 8 + r;
            const int b_col = ks * 16 + (t & 1) * 8;
            #pragma unroll
            for (int g = 0; g < 2; g++) {
                uint32_t off = ((nbase + g * 16 + b_row_off) * SP + b_col) * 2;
                ldsm_x4(bs + off, Bh[2 * g][0], Bh[2 * g][1], Bh[2 * g + 1][0], Bh[2 * g + 1][1]);
            }
            #pragma unroll
            for (int i = 0; i < 4; i++)
                #pragma unroll
                for (int j = 0; j < 4; j++)
                    mma_f16(acc[i][j], Ah[i], Bh[j]);
        }
    }

    // epilogue: store C (fp16) + fused el/er for this warp's head
    const int rq = lane >> 2;
    const int cq = (lane & 3) * 2;
    const int hIdx = (colBase >> 5) + (wid & 3);
    float alv[4][2], arv[4][2];
    #pragma unroll
    for (int j = 0; j < 4; j++) {
        int d0 = hIdx * HIDD + j * 8 + cq;
        alv[j][0] = al[d0]; alv[j][1] = al[d0 + 1];
        arv[j][0] = ar[d0]; arv[j][1] = ar[d0 + 1];
    }
    #pragma unroll
    for (int i = 0; i < 4; i++) {
        int r0 = rowBase + mbase + i * 16 + rq;
        int r1 = r0 + 8;
        float sl0 = 0.f, sr0 = 0.f, sl1 = 0.f, sr1 = 0.f;
        #pragma unroll
        for (int j = 0; j < 4; j++) {
            int cc = colBase + nbase + j * 8 + cq;
            if (r0 < M) *(uint32_t*)(C + (size_t)r0 * FTOT + cc) = pack2h(acc[i][j][0], acc[i][j][1]);
            if (r1 < M) *(uint32_t*)(C + (size_t)r1 * FTOT + cc) = pack2h(acc[i][j][2], acc[i][j][3]);
            sl0 = fmaf(acc[i][j][0], alv[j][0], fmaf(acc[i][j][1], alv[j][1], sl0));
            sr0 = fmaf(acc[i][j][0], arv[j][0], fmaf(acc[i][j][1], arv[j][1], sr0));
            sl1 = fmaf(acc[i][j][2], alv[j][0], fmaf(acc[i][j][3], alv[j][1], sl1));
            sr1 = fmaf(acc[i][j][2], arv[j][0], fmaf(acc[i][j][3], arv[j][1], sr1));
        }
        #pragma unroll
        for (int d = 1; d <= 2; d <<= 1) {
            sl0 += __shfl_xor_sync(0xffffffffu, sl0, d);
            sr0 += __shfl_xor_sync(0xffffffffu, sr0, d);
            sl1 += __shfl_xor_sync(0xffffffffu, sl1, d);
            sr1 += __shfl_xor_sync(0xffffffffu, sr1, d);
        }
        if ((lane & 3) == 0) {
            if (r0 < M) { el[r0 * NHEADS + hIdx] = sl0; er[r0 * NHEADS + hIdx] = sr0; }
            if (r1 < M) { el[r1 * NHEADS + hIdx] = sl1; er[r1 * NHEADS + hIdx] = sr1; }
        }
    }
}

// ---------------- CSR build ----------------
__global__ void hist_kernel(const int* __restrict__ dst, int* __restrict__ count) {
    int e = blockIdx.x * blockDim.x + threadIdx.x;
    if (e < EE) atomicAdd(&count[dst[e]], 1);
}

__global__ void scan_kernel(const int* __restrict__ count, int* __restrict__ off,
                            int* __restrict__ cursor) {
    __shared__ int wsum[32];
    __shared__ int carry;
    const int t = threadIdx.x;
    const int w = t >> 5, lane = t & 31;
    if (t == 0) carry = 0;
    __syncthreads();
    for (int base = 0; base < NN; base += 1024) {
        int i = base + t;
        int v = (i < NN) ? count[i] : 0;
        int incl = v;
        #pragma unroll
        for (int d = 1; d < 32; d <<= 1) {
            int x = __shfl_up_sync(0xffffffffu, incl, d);
            if (lane >= d) incl += x;
        }
        if (lane == 31) wsum[w] = incl;
        __syncthreads();
        if (w == 0) {
            int s = wsum[lane];
            #pragma unroll
            for (int d = 1; d < 32; d <<= 1) {
                int x = __shfl_up_sync(0xffffffffu, s, d);
                if (lane >= d) s += x;
            }
            wsum[lane] = s;
        }
        __syncthreads();
        int wpre = (w > 0) ? wsum[w - 1] : 0;
        int excl = carry + wpre + incl - v;
        if (i < NN) { off[i] = excl; cursor[i] = excl; }
        int total = wsum[31];
        __syncthreads();
        if (t == 0) carry += total;
        __syncthreads();
    }
    if (t == 0) off[NN] = carry;
}

__global__ void scatter_kernel(const int* __restrict__ dst, const int* __restrict__ srcArr,
                               int* __restrict__ cursor, int* __restrict__ srcs) {
    int e = blockIdx.x * blockDim.x + threadIdx.x;
    if (e < EE) {
        int pos = atomicAdd(&cursor[dst[e]], 1);
        srcs[pos] = srcArr[e];
    }
}

// ---------------- final-layer SGEMM (fp16 A, fp32 math) with fused el/er ----------------
__global__ void __launch_bounds__(128)
sgemm_final_kernel(const __half* __restrict__ A, const float* __restrict__ B,
                   float* __restrict__ C, const float* __restrict__ al,
                   const float* __restrict__ ar, float* __restrict__ el,
                   float* __restrict__ er, int M) {
    constexpr int BM = 128, BN = 32, BK = 32, TM = 8, TN = 4;
    constexpr int TCOLS = BN / TN;   // 8
    constexpr int NT = 128;
    __shared__ float As[BK][BM];
    __shared__ float Bs[BK][BN];
    const int tid = threadIdx.x;
    const int tr = tid / TCOLS;
    const int tc = tid % TCOLS;
    const int rowBase = blockIdx.y * BM;

    float acc[TM][TN];
    #pragma unroll
    for (int i = 0; i < TM; i++)
        #pragma unroll
        for (int j = 0; j < TN; j++) acc[i][j] = 0.f;

    for (int k0 = 0; k0 < FTOT; k0 += BK) {
        #pragma unroll
        for (int i = tid * 4; i < BM * BK; i += NT * 4) {
            int m = i / BK, kk = i % BK;
            int gr = rowBase + m;
            float4 v = make_float4(0.f, 0.f, 0.f, 0.f);
            if (gr < M) {
                uint2 hraw = *(const uint2*)(A + (size_t)gr * FTOT + k0 + kk);
                float2 f0 = __half22float2(*(const __half2*)&hraw.x);
                float2 f1 = __half22float2(*(const __half2*)&hraw.y);
                v = make_float4(f0.x, f0.y, f1.x, f1.y);
            }
            As[kk + 0][m] = v.x; As[kk + 1][m] = v.y;
            As[kk + 2][m] = v.z; As[kk + 3][m] = v.w;
        }
        #pragma unroll
        for (int i = tid * 4; i < BK * BN; i += NT * 4) {
            int kk = i / BN, nn = i % BN;
            float4 v = *(const float4*)(B + (size_t)(k0 + kk) * BN + nn);
            *(float4*)&Bs[kk][nn] = v;
        }
        __syncthreads();
        #pragma unroll
        for (int kk = 0; kk < BK; kk++) {
            float a[TM], b[TN];
            #pragma unroll
            for (int i = 0; i < TM / 4; i++)
                *(float4*)&a[i * 4] = *(const float4*)&As[kk][tr * TM + i * 4];
            *(float4*)&b[0] = *(const float4*)&Bs[kk][tc * TN];
            #pragma unroll
            for (int i = 0; i < TM; i++)
                #pragma unroll
                for (int j = 0; j < TN; j++) acc[i][j] = fmaf(a[i], b[j], acc[i][j]);
        }
        __syncthreads();
    }
    float alv[TN], arv[TN];
    #pragma unroll
    for (int j = 0; j < TN; j++) { alv[j] = al[tc * TN + j]; arv[j] = ar[tc * TN + j]; }
    #pragma unroll
    for (int i = 0; i < TM; i++) {
        int r = rowBase + tr * TM + i;
        float pl = 0.f, pr = 0.f;
        #pragma unroll
        for (int j = 0; j < TN; j++) {
            pl = fmaf(acc[i][j], alv[j], pl);
            pr = fmaf(acc[i][j], arv[j], pr);
        }
        #pragma unroll
        for (int d = 1; d <= 4; d <<= 1) {
            pl += __shfl_xor_sync(0xffffffffu, pl, d);
            pr += __shfl_xor_sync(0xffffffffu, pr, d);
        }
        if (r < M) {
            *(float4*)(C + (size_t)r * BN + tc * TN) = *(float4*)&acc[i][0];
            if (tc == 0) { el[r] = pl; er[r] = pr; }
        }
    }
}

// ---------------- per-node warp: SINGLE-PASS flash-style softmax + aggregate
// Lane (eslot=lane>>3, hl=lane&7) computes edge logits; lane l owns dims
// [8l, 8l+8) of the output (head myh=l>>2). Online (mx, sm) per head with
// accumulator rescaling -- one pass over the edge list instead of two.
__global__ void __launch_bounds__(256)
agg8_kernel(const __half* __restrict__ feat, const float* __restrict__ el,
            const float* __restrict__ er, const float* __restrict__ bias,
            __half* __restrict__ out, const int* __restrict__ off,
            const int* __restrict__ srcs) {
    int warp = (blockIdx.x * blockDim.x + threadIdx.x) >> 5;
    if (warp >= NN) return;
    const int lane = threadIdx.x & 31;
    const int n = warp;
    const int s = off[n], epnd = off[n + 1];
    const int hl = lane & 7;
    const int eslot = lane >> 3;
    const int myh = lane >> 2;
    const float er_h = er[n * NHEADS + hl];
    const __half* fbase = feat + lane * 8;

    float mx = -INFINITY;   // running max for head hl (uniform across eslot)
    float sm = 0.f;         // partial sum for head hl (this eslot's edges)
    float acc[8];
    #pragma unroll
    for (int q = 0; q < 8; q++) acc[q] = 0.f;

    int i = s;
    // main loop: 4 edges per iteration
    for (; i + 4 <= epnd; i += 4) {
        int esrc = srcs[i + eslot];                       // edge (lane>>3)
        float v = el[esrc * NHEADS + hl] + er_h;          // head (lane&7)
        v = v > 0.f ? v : 0.2f * v;
        // per-head max over the 4 batched edges (lanes with same hl)
        float bm = v;
        bm = fmaxf(bm, __shfl_xor_sync(0xffffffffu, bm, 8));
        bm = fmaxf(bm, __shfl_xor_sync(0xffffffffu, bm, 16));
        float m2 = fmaxf(mx, bm);
        float scale = safe_exp(mx - m2);   // first iter: exp(-inf)=0 via clamp
        float coef = safe_exp(v - m2);
        sm = sm * scale + coef;
        mx = m2;
        // broadcast rescale + coefficients for head myh
        float cs = __shfl_sync(0xffffffffu, scale, myh);
        float c[4]; int se[4];
        #pragma unroll
        for (int e = 0; e < 4; e++) {
            c[e]  = __shfl_sync(0xffffffffu, coef, e * 8 + myh);
            se[e] = __shfl_sync(0xffffffffu, esrc, e * 8);
        }
        uint4 raw[4];
        #pragma unroll
        for (int e = 0; e < 4; e++)
            raw[e] = *(const uint4*)(fbase + (size_t)se[e] * FTOT);
        #pragma unroll
        for (int q = 0; q < 8; q++) acc[q] *= cs;
        #pragma unroll
        for (int e = 0; e < 4; e++) {
            const __half2* hp = (const __half2*)&raw[e];
            #pragma unroll
            for (int q = 0; q < 4; q++) {
                float2 f = __half22float2(hp[q]);
                acc[q * 2]     = fmaf(c[e], f.x, acc[q * 2]);
                acc[q * 2 + 1] = fmaf(c[e], f.y, acc[q * 2 + 1]);
            }
        }
    }
    // tail: one edge at a time (v uniform across eslot; only eslot 0 adds to sm)
    for (; i < epnd; i++) {
        int srcT = srcs[i];
        float v = el[srcT * NHEADS + hl] + er_h;
        v = v > 0.f ? v : 0.2f * v;
        float m2 = fmaxf(mx, v);
        float scale = safe_exp(mx - m2);
        float coef = safe_exp(v - m2);
        sm = sm * scale + (eslot == 0 ? coef : 0.f);
        mx = m2;
        float cs = __shfl_sync(0xffffffffu, scale, myh);
        float c  = __shfl_sync(0xffffffffu, coef, myh);
        uint4 raw = *(const uint4*)(fbase + (size_t)srcT * FTOT);
        const __half2* hp = (const __half2*)&raw;
        #pragma unroll
        for (int q = 0; q < 8; q++) acc[q] *= cs;
        #pragma unroll
        for (int q = 0; q < 4; q++) {
            float2 f = __half22float2(hp[q]);
            acc[q * 2]     = fmaf(c, f.x, acc[q * 2]);
            acc[q * 2 + 1] = fmaf(c, f.y, acc[q * 2 + 1]);
        }
    }
    // finalize: reduce sm over the 4 eslots (same mx everywhere), normalize
    sm += __shfl_xor_sync(0xffffffffu, sm, 8);
    sm += __shfl_xor_sync(0xffffffffu, sm, 16);
    float inv = 1.0f / (sm + 1e-9f);
    float cinv = __shfl_sync(0xffffffffu, inv, myh);
    // epilogue: normalize, +bias, ELU, fp16 pack, one uint4 store
    float4 b0 = *(const float4*)(bias + lane * 8);
    float4 b1 = *(const float4*)(bias + lane * 8 + 4);
    float o[8];
    o[0] = acc[0] * cinv + b0.x; o[1] = acc[1] * cinv + b0.y;
    o[2] = acc[2] * cinv + b0.z; o[3] = acc[3] * cinv + b0.w;
    o[4] = acc[4] * cinv + b1.x; o[5] = acc[5] * cinv + b1.y;
    o[6] = acc[6] * cinv + b1.z; o[7] = acc[7] * cinv + b1.w;
    #pragma unroll
    for (int q = 0; q < 8; q++) o[q] = o[q] > 0.f ? o[q] : expm1f(o[q]);
    uint4 packed = make_uint4(pack2h(o[0], o[1]), pack2h(o[2], o[3]),
                              pack2h(o[4], o[5]), pack2h(o[6], o[7]));
    *(uint4*)(out + (size_t)n * FTOT + lane * 8) = packed;
}

// ---------------- final layer aggregate (1 head, D=32) ----------------
__global__ void __launch_bounds__(256)
agg1_kernel(const float* __restrict__ feat2, const float* __restrict__ el,
            const float* __restrict__ er, const float* __restrict__ bias,
            float* __restrict__ out, const int* __restrict__ off,
            const int* __restrict__ srcs) {
    int warp = (blockIdx.x * blockDim.x + threadIdx.x) >> 5;
    if (warp >= NN) return;
    const int lane = threadIdx.x & 31;
    const int n = warp;
    const int s = off[n], epnd = off[n + 1];
    const float er_n = er[n];

    float mx = -INFINITY, sm = 0.f;
    for (int i = s + lane; i < epnd; i += 32) {
        int src = srcs[i];
        float v = el[src] + er_n;
        v = v > 0.f ? v : 0.2f * v;
        float m2 = fmaxf(mx, v);
        sm = sm * safe_exp(mx - m2) + safe_exp(v - m2);
        mx = m2;
    }
    #pragma unroll
    for (int d = 16; d >= 1; d >>= 1) {
        float om = __shfl_xor_sync(0xffffffffu, mx, d);
        float os = __shfl_xor_sync(0xffffffffu, sm, d);
        float m2 = fmaxf(mx, om);
        sm = sm * safe_exp(mx - m2) + os * safe_exp(om - m2);
        mx = m2;
    }
    const float inv = 1.0f / (sm + 1e-9f);

    float acc = 0.f;
    for (int i = s; i < epnd; i++) {
        int src = srcs[i];
        float v = el[src] + er_n;
        v = v > 0.f ? v : 0.2f * v;
        float coef = safe_exp(v - mx) * inv;
        acc = fmaf(coef, feat2[(size_t)src * HIDD + lane], acc);
    }
    out[(size_t)n * HIDD + lane] = acc + bias[lane];
}

// ---------------- launch ----------------
extern "C" void kernel_launch(void* const* d_in, const int* in_sizes, int n_in,
                              void* d_out, int out_size) {
    const float* features = (const float*)d_in[0];
    const int*   src      = (const int*)d_in[1];
    const int*   dst      = (const int*)d_in[2];
    const float* W0  = (const float*)d_in[3];
    const float* al0 = (const float*)d_in[4];
    const float* ar0 = (const float*)d_in[5];
    const float* b0  = (const float*)d_in[6];
    const float* W1  = (const float*)d_in[7];
    const float* al1 = (const float*)d_in[8];
    const float* ar1 = (const float*)d_in[9];
    const float* b1  = (const float*)d_in[10];
    const float* W2  = (const float*)d_in[11];
    const float* al2 = (const float*)d_in[12];
    const float* ar2 = (const float*)d_in[13];
    const float* b2  = (const float*)d_in[14];
    float* out = (float*)d_out;

    __half *featH, *hH;
    float *feat2, *el, *er;
    int *count, *off, *cursor, *srcs;
    cudaGetSymbolAddress((void**)&featH,  g_featH);
    cudaGetSymbolAddress((void**)&hH,     g_hH);
    cudaGetSymbolAddress((void**)&feat2,  g_feat2);
    cudaGetSymbolAddress((void**)&el,     g_el);
    cudaGetSymbolAddress((void**)&er,     g_er);
    cudaGetSymbolAddress((void**)&count,  g_count);
    cudaGetSymbolAddress((void**)&off,    g_off);
    cudaGetSymbolAddress((void**)&cursor, g_cursor);
    cudaGetSymbolAddress((void**)&srcs,   g_srcs);

    cudaFuncSetAttribute(mma_gemm_kernel<float>,
                         cudaFuncAttributeMaxDynamicSharedMemorySize, GEMM_SMEM);
    cudaFuncSetAttribute(mma_gemm_kernel<__half>,
                         cudaFuncAttributeMaxDynamicSharedMemorySize, GEMM_SMEM);

    // CSR by dst (src values scattered directly)
    cudaMemsetAsync(count, 0, NN * sizeof(int));
    hist_kernel<<<(EE + 255) / 256, 256>>>(dst, count);
    scan_kernel<<<1, 1024>>>(count, off, cursor);
    scatter_kernel<<<(EE + 255) / 256, 256>>>(dst, src, cursor, srcs);

    const int aggBlocks = (NN * 32 + 255) / 256;
    dim3 gemmGrid(2, (NN + 127) / 128);
    dim3 gemmFinal(1, (NN + 127) / 128);

    // layer 0 (GEMM fp32-in + fused el/er, fp16 out)
    mma_gemm_kernel<float><<<gemmGrid, 256, GEMM_SMEM>>>(features, W0, featH, al0, ar0, el, er, NN);
    agg8_kernel<<<aggBlocks, 256>>>(featH, el, er, b0, hH, off, srcs);

    // layer 1 (GEMM fp16-in)
    mma_gemm_kernel<__half><<<gemmGrid, 256, GEMM_SMEM>>>(hH, W1, featH, al1, ar1, el, er, NN);
    agg8_kernel<<<aggBlocks, 256>>>(featH, el, er, b1, hH, off, srcs);

    // layer 2 (single head, D=32, no activation; fused el/er)
    sgemm_final_kernel<<<gemmFinal, 128>>>(hH, W2, feat2, al2, ar2, el, er, NN);
    agg1_kernel<<<aggBlocks, 256>>>(feat2, el, er, b2, out, off, srcs);
}

// round 12
// speedup vs baseline: 2.9064x; 1.1103x over previous
#include <cuda_runtime.h>
#include <cuda_fp16.h>
#include <math.h>
#include <stdint.h>

#define NN 50000
#define EE 800000
#define NHEADS 8
#define HIDD 32
#define FTOT 256   // NHEADS*HIDD, also IN_FEATS
#define NB 49      // scan blocks: 49*1024 >= NN

// ---------------- scratch (static device globals; no allocation) ----------------
__device__ __align__(16) __half g_featH[(size_t)NN * FTOT];  // 25.6 MB (GEMM out, fp16)
__device__ __align__(16) __half g_hH[(size_t)NN * FTOT];     // 25.6 MB (agg8 out, fp16)
__device__ __align__(16) __half g_WH[2][FTOT * FTOT];        // W0/W1 transposed fp16
__device__ __align__(16) float g_feat2[(size_t)NN * HIDD];   // 6.4 MB
__device__ __align__(16) float g_el[NN * NHEADS];
__device__ __align__(16) float g_er[NN * NHEADS];
__device__ int g_count[NN];
__device__ int g_off[NN + 1];
__device__ int g_cursor[NN];
__device__ int g_srcs[EE];    // src node of each edge, sorted by dst
__device__ int g_bsum[64];
__device__ int g_boff[64];

// ---------------- helpers ----------------
__device__ __forceinline__ uint32_t smem_u32(const void* p) {
    uint32_t a;
    asm("{ .reg .u64 t; cvta.to.shared.u64 t, %1; cvt.u32.u64 %0, t; }" : "=r"(a) : "l"(p));
    return a;
}
__device__ __forceinline__ void ldsm_x4(uint32_t addr, uint32_t& r0, uint32_t& r1,
                                        uint32_t& r2, uint32_t& r3) {
    asm volatile("ldmatrix.sync.aligned.m8n8.x4.shared.b16 {%0,%1,%2,%3}, [%4];"
                 : "=r"(r0), "=r"(r1), "=r"(r2), "=r"(r3) : "r"(addr));
}
__device__ __forceinline__ void mma_f16(float* d, const uint32_t* a, const uint32_t* b) {
    asm volatile(
        "mma.sync.aligned.m16n8k16.row.col.f32.f16.f16.f32 "
        "{%0,%1,%2,%3}, {%4,%5,%6,%7}, {%8,%9}, {%0,%1,%2,%3};"
        : "+f"(d[0]), "+f"(d[1]), "+f"(d[2]), "+f"(d[3])
        : "r"(a[0]), "r"(a[1]), "r"(a[2]), "r"(a[3]), "r"(b[0]), "r"(b[1]));
}
__device__ __forceinline__ uint32_t pack2h(float a, float b) {
    __half2 t = __floats2half2_rn(a, b);
    return *(uint32_t*)&t;
}
// exp argument guard: fmaxf(NaN, -88) = -88, so (-inf) - (-inf) merges stay finite
__device__ __forceinline__ float safe_exp(float x) {
    return __expf(fmaxf(x, -88.f));
}

// 16 contiguous elements -> 8 packed fp16 pairs
__device__ __forceinline__ void loadA16(const float* p, uint32_t* d) {
    const float4* q = (const float4*)p;
    #pragma unroll
    for (int i = 0; i < 4; i++) {
        float4 v = q[i];
        d[2 * i]     = pack2h(v.x, v.y);
        d[2 * i + 1] = pack2h(v.z, v.w);
    }
}
__device__ __forceinline__ void loadA16(const __half* p, uint32_t* d) {
    uint4 a = ((const uint4*)p)[0];
    uint4 b = ((const uint4*)p)[1];
    d[0] = a.x; d[1] = a.y; d[2] = a.z; d[3] = a.w;
    d[4] = b.x; d[5] = b.y; d[6] = b.z; d[7] = b.w;
}
__device__ __forceinline__ void zeroA16(uint32_t* d) {
    #pragma unroll
    for (int q = 0; q < 8; q++) d[q] = 0u;
}

// ---------------- W transpose to fp16 [outcol][k] ----------------
__global__ void wtrans_kernel(const float* __restrict__ W, __half* __restrict__ Wt) {
    int n = blockIdx.x;   // output column
    int k = threadIdx.x;  // input row
    Wt[n * FTOT + k] = __float2half(W[(size_t)k * FTOT + n]);
}

// ---------------- mma.sync fp16 GEMM: C[M x 256] = A[M x 256] * W[256 x 256]
// B pre-transposed fp16 [outcol][k] -> A and B loaders identical, coalesced uint4.
#define SP 40                      // smem row pitch in halfs
#define TILE_H (128 * SP)          // halfs per logical tile
#define BUF_H (2 * TILE_H)         // As | Bs
#define GEMM_SMEM (2 * BUF_H * 2)  // 40960 bytes

template <typename TA>
__global__ void __launch_bounds__(256, 2)
mma_gemm_kernel(const TA* __restrict__ A, const __half* __restrict__ Wt,
                __half* __restrict__ C, const float* __restrict__ al,
                const float* __restrict__ ar, float* __restrict__ el,
                float* __restrict__ er, int M) {
    extern __shared__ __half2 smem_raw[];
    uint16_t* smem = (uint16_t*)smem_raw;
    const int tid = threadIdx.x;
    const int wid = tid >> 5;
    const int lane = tid & 31;
    const int rowBase = blockIdx.y * 128;
    const int colBase = blockIdx.x * 128;
    const int mbase = (wid >> 2) * 64;   // warpM in {0,1}
    const int nbase = (wid & 3) * 32;    // warpN in {0..3} == head within tile

    float acc[4][4][4];
    #pragma unroll
    for (int i = 0; i < 4; i++)
        #pragma unroll
        for (int j = 0; j < 4; j++)
            #pragma unroll
            for (int q = 0; q < 4; q++) acc[i][j][q] = 0.f;

    const int arow = tid >> 1;            // tile row (A row / B outcol)
    const int akq  = (tid & 1) * 4;       // 16-half slice selector {0,16}
    const __half* Brow = Wt + (size_t)(colBase + arow) * FTOT;

    uint32_t prawA[8], prawB[8];
    {
        int gr = rowBase + arow;
        if (gr < M) loadA16(A + (size_t)gr * FTOT + akq * 4, prawA);
        else zeroA16(prawA);
        loadA16(Brow + akq * 4, prawB);
    }

    for (int c = 0; c < 8; c++) {
        const int b = c & 1;
        uint16_t* As = smem + b * BUF_H;
        uint16_t* Bs = As + TILE_H;

        {
            uint4* da = (uint4*)(As + arow * SP + akq * 4);
            da[0] = make_uint4(prawA[0], prawA[1], prawA[2], prawA[3]);
            da[1] = make_uint4(prawA[4], prawA[5], prawA[6], prawA[7]);
            uint4* db = (uint4*)(Bs + arow * SP + akq * 4);
            db[0] = make_uint4(prawB[0], prawB[1], prawB[2], prawB[3]);
            db[1] = make_uint4(prawB[4], prawB[5], prawB[6], prawB[7]);
        }

        if (c < 7) {
            int gr = rowBase + arow;
            if (gr < M) loadA16(A + (size_t)gr * FTOT + (c + 1) * 32 + akq * 4, prawA);
            else zeroA16(prawA);
            loadA16(Brow + (c + 1) * 32 + akq * 4, prawB);
        }
        __syncthreads();

        const uint32_t as = smem_u32(As);
        const uint32_t bs = smem_u32(Bs);
        const int t = lane >> 3, r = lane & 7;
        #pragma unroll
        for (int ks = 0; ks < 2; ks++) {
            uint32_t Ah[4][4], Bh[4][2];
            const int a_row_off = (t & 1) * 8 + r;
            const int a_col = ks * 16 + (t >> 1) * 8;
            #pragma unroll
            for (int f = 0; f < 4; f++) {
                uint32_t off = ((mbase + f * 16 + a_row_off) * SP + a_col) * 2;
                ldsm_x4(as + off, Ah[f][0], Ah[f][1], Ah[f][2], Ah[f][3]);
            }
            const int b_row_off = (t >> 1) * 8 + r;
            const int b_col = ks * 16 + (t & 1) * 8;
            #pragma unroll
            for (int g = 0; g < 2; g++) {
                uint32_t off = ((nbase + g * 16 + b_row_off) * SP + b_col) * 2;
                ldsm_x4(bs + off, Bh[2 * g][0], Bh[2 * g][1], Bh[2 * g + 1][0], Bh[2 * g + 1][1]);
            }
            #pragma unroll
            for (int i = 0; i < 4; i++)
                #pragma unroll
                for (int j = 0; j < 4; j++)
                    mma_f16(acc[i][j], Ah[i], Bh[j]);
        }
    }

    // epilogue: store C (fp16) + fused el/er for this warp's head
    const int rq = lane >> 2;
    const int cq = (lane & 3) * 2;
    const int hIdx = (colBase >> 5) + (wid & 3);
    float alv[4][2], arv[4][2];
    #pragma unroll
    for (int j = 0; j < 4; j++) {
        int d0 = hIdx * HIDD + j * 8 + cq;
        alv[j][0] = al[d0]; alv[j][1] = al[d0 + 1];
        arv[j][0] = ar[d0]; arv[j][1] = ar[d0 + 1];
    }
    #pragma unroll
    for (int i = 0; i < 4; i++) {
        int r0 = rowBase + mbase + i * 16 + rq;
        int r1 = r0 + 8;
        float sl0 = 0.f, sr0 = 0.f, sl1 = 0.f, sr1 = 0.f;
        #pragma unroll
        for (int j = 0; j < 4; j++) {
            int cc = colBase + nbase + j * 8 + cq;
            if (r0 < M) *(uint32_t*)(C + (size_t)r0 * FTOT + cc) = pack2h(acc[i][j][0], acc[i][j][1]);
            if (r1 < M) *(uint32_t*)(C + (size_t)r1 * FTOT + cc) = pack2h(acc[i][j][2], acc[i][j][3]);
            sl0 = fmaf(acc[i][j][0], alv[j][0], fmaf(acc[i][j][1], alv[j][1], sl0));
            sr0 = fmaf(acc[i][j][0], arv[j][0], fmaf(acc[i][j][1], arv[j][1], sr0));
            sl1 = fmaf(acc[i][j][2], alv[j][0], fmaf(acc[i][j][3], alv[j][1], sl1));
            sr1 = fmaf(acc[i][j][2], arv[j][0], fmaf(acc[i][j][3], arv[j][1], sr1));
        }
        #pragma unroll
        for (int d = 1; d <= 2; d <<= 1) {
            sl0 += __shfl_xor_sync(0xffffffffu, sl0, d);
            sr0 += __shfl_xor_sync(0xffffffffu, sr0, d);
            sl1 += __shfl_xor_sync(0xffffffffu, sl1, d);
            sr1 += __shfl_xor_sync(0xffffffffu, sr1, d);
        }
        if ((lane & 3) == 0) {
            if (r0 < M) { el[r0 * NHEADS + hIdx] = sl0; er[r0 * NHEADS + hIdx] = sr0; }
            if (r1 < M) { el[r1 * NHEADS + hIdx] = sl1; er[r1 * NHEADS + hIdx] = sr1; }
        }
    }
}

// ---------------- CSR build ----------------
__global__ void hist_kernel(const int* __restrict__ dst, int* __restrict__ count) {
    int e = blockIdx.x * blockDim.x + threadIdx.x;
    if (e < EE) atomicAdd(&count[dst[e]], 1);
}

// multi-block scan, stage 1: per-block exclusive scan + block totals
__global__ void scan1_kernel(const int* __restrict__ count, int* __restrict__ off,
                             int* __restrict__ bsum) {
    __shared__ int wsum[32];
    const int t = threadIdx.x;
    const int lane = t & 31, w = t >> 5;
    const int i = blockIdx.x * 1024 + t;
    int v = (i < NN) ? count[i] : 0;
    int incl = v;
    #pragma unroll
    for (int d = 1; d < 32; d <<= 1) {
        int x = __shfl_up_sync(0xffffffffu, incl, d);
        if (lane >= d) incl += x;
    }
    if (lane == 31) wsum[w] = incl;
    __syncthreads();
    if (w == 0) {
        int s = wsum[lane];
        #pragma unroll
        for (int d = 1; d < 32; d <<= 1) {
            int x = __shfl_up_sync(0xffffffffu, s, d);
            if (lane >= d) s += x;
        }
        wsum[lane] = s;
    }
    __syncthreads();
    int wpre = (w > 0) ? wsum[w - 1] : 0;
    if (i < NN) off[i] = wpre + incl - v;
    if (t == 0) bsum[blockIdx.x] = wsum[31];
}

// stage 2: scan the NB block totals (single block of 64)
__global__ void scan2_kernel(const int* __restrict__ bsum, int* __restrict__ boff,
                             int* __restrict__ off) {
    __shared__ int tmp[64];
    int t = threadIdx.x;
    int v = (t < NB) ? bsum[t] : 0;
    tmp[t] = v;
    __syncthreads();
    #pragma unroll
    for (int d = 1; d < 64; d <<= 1) {
        int x = (t >= d) ? tmp[t - d] : 0;
        __syncthreads();
        tmp[t] += x;
        __syncthreads();
    }
    if (t < NB) boff[t] = tmp[t] - v;
    if (t == 63) off[NN] = tmp[63];
}

// stage 3: add block offsets, init cursor
__global__ void scan3_kernel(int* __restrict__ off, const int* __restrict__ boff,
                             int* __restrict__ cursor) {
    const int i = blockIdx.x * 1024 + threadIdx.x;
    if (i < NN) {
        int o = off[i] + boff[blockIdx.x];
        off[i] = o;
        cursor[i] = o;
    }
}

__global__ void scatter_kernel(const int* __restrict__ dst, const int* __restrict__ srcArr,
                               int* __restrict__ cursor, int* __restrict__ srcs) {
    int e = blockIdx.x * blockDim.x + threadIdx.x;
    if (e < EE) {
        int pos = atomicAdd(&cursor[dst[e]], 1);
        srcs[pos] = srcArr[e];
    }
}

// ---------------- final-layer SGEMM (fp16 A, fp32 math) with fused el/er ----------------
__global__ void __launch_bounds__(128)
sgemm_final_kernel(const __half* __restrict__ A, const float* __restrict__ B,
                   float* __restrict__ C, const float* __restrict__ al,
                   const float* __restrict__ ar, float* __restrict__ el,
                   float* __restrict__ er, int M) {
    constexpr int BM = 128, BN = 32, BK = 32, TM = 8, TN = 4;
    constexpr int TCOLS = BN / TN;   // 8
    constexpr int NT = 128;
    __shared__ float As[BK][BM];
    __shared__ float Bs[BK][BN];
    const int tid = threadIdx.x;
    const int tr = tid / TCOLS;
    const int tc = tid % TCOLS;
    const int rowBase = blockIdx.y * BM;

    float acc[TM][TN];
    #pragma unroll
    for (int i = 0; i < TM; i++)
        #pragma unroll
        for (int j = 0; j < TN; j++) acc[i][j] = 0.f;

    for (int k0 = 0; k0 < FTOT; k0 += BK) {
        #pragma unroll
        for (int i = tid * 4; i < BM * BK; i += NT * 4) {
            int m = i / BK, kk = i % BK;
            int gr = rowBase + m;
            float4 v = make_float4(0.f, 0.f, 0.f, 0.f);
            if (gr < M) {
                uint2 hraw = *(const uint2*)(A + (size_t)gr * FTOT + k0 + kk);
                float2 f0 = __half22float2(*(const __half2*)&hraw.x);
                float2 f1 = __half22float2(*(const __half2*)&hraw.y);
                v = make_float4(f0.x, f0.y, f1.x, f1.y);
            }
            As[kk + 0][m] = v.x; As[kk + 1][m] = v.y;
            As[kk + 2][m] = v.z; As[kk + 3][m] = v.w;
        }
        #pragma unroll
        for (int i = tid * 4; i < BK * BN; i += NT * 4) {
            int kk = i / BN, nn = i % BN;
            float4 v = *(const float4*)(B + (size_t)(k0 + kk) * BN + nn);
            *(float4*)&Bs[kk][nn] = v;
        }
        __syncthreads();
        #pragma unroll
        for (int kk = 0; kk < BK; kk++) {
            float a[TM], b[TN];
            #pragma unroll
            for (int i = 0; i < TM / 4; i++)
                *(float4*)&a[i * 4] = *(const float4*)&As[kk][tr * TM + i * 4];
            *(float4*)&b[0] = *(const float4*)&Bs[kk][tc * TN];
            #pragma unroll
            for (int i = 0; i < TM; i++)
                #pragma unroll
                for (int j = 0; j < TN; j++) acc[i][j] = fmaf(a[i], b[j], acc[i][j]);
        }
        __syncthreads();
    }
    float alv[TN], arv[TN];
    #pragma unroll
    for (int j = 0; j < TN; j++) { alv[j] = al[tc * TN + j]; arv[j] = ar[tc * TN + j]; }
    #pragma unroll
    for (int i = 0; i < TM; i++) {
        int r = rowBase + tr * TM + i;
        float pl = 0.f, pr = 0.f;
        #pragma unroll
        for (int j = 0; j < TN; j++) {
            pl = fmaf(acc[i][j], alv[j], pl);
            pr = fmaf(acc[i][j], arv[j], pr);
        }
        #pragma unroll
        for (int d = 1; d <= 4; d <<= 1) {
            pl += __shfl_xor_sync(0xffffffffu, pl, d);
            pr += __shfl_xor_sync(0xffffffffu, pr, d);
        }
        if (r < M) {
            *(float4*)(C + (size_t)r * BN + tc * TN) = *(float4*)&acc[i][0];
            if (tc == 0) { el[r] = pl; er[r] = pr; }
        }
    }
}

// ---------------- per-node warp: SINGLE-PASS flash-style softmax + aggregate
// 8 edges per main-loop iteration (MLP 8 on the feat gather).
__global__ void __launch_bounds__(256)
agg8_kernel(const __half* __restrict__ feat, const float* __restrict__ el,
            const float* __restrict__ er, const float* __restrict__ bias,
            __half* __restrict__ out, const int* __restrict__ off,
            const int* __restrict__ srcs) {
    int warp = (blockIdx.x * blockDim.x + threadIdx.x) >> 5;
    if (warp >= NN) return;
    const int lane = threadIdx.x & 31;
    const int n = warp;
    const int s = off[n], epnd = off[n + 1];
    const int hl = lane & 7;
    const int eslot = lane >> 3;
    const int myh = lane >> 2;
    const float er_h = er[n * NHEADS + hl];
    const __half* fbase = feat + lane * 8;

    float mx = -INFINITY;
    float sm = 0.f;
    float acc[8];
    #pragma unroll
    for (int q = 0; q < 8; q++) acc[q] = 0.f;

    int i = s;
    // main loop: 8 edges per iteration
    for (; i + 8 <= epnd; i += 8) {
        int s0 = srcs[i + eslot];
        int s1 = srcs[i + 4 + eslot];
        float v0 = el[s0 * NHEADS + hl] + er_h;
        float v1 = el[s1 * NHEADS + hl] + er_h;
        v0 = v0 > 0.f ? v0 : 0.2f * v0;
        v1 = v1 > 0.f ? v1 : 0.2f * v1;
        float bm = fmaxf(v0, v1);
        bm = fmaxf(bm, __shfl_xor_sync(0xffffffffu, bm, 8));
        bm = fmaxf(bm, __shfl_xor_sync(0xffffffffu, bm, 16));
        float m2 = fmaxf(mx, bm);
        float scale = safe_exp(mx - m2);
        float c0 = safe_exp(v0 - m2);
        float c1 = safe_exp(v1 - m2);
        sm = sm * scale + c0 + c1;
        mx = m2;
        float cs = __shfl_sync(0xffffffffu, scale, myh);
        float c[8]; int se[8];
        #pragma unroll
        for (int e = 0; e < 4; e++) {
            c[e]      = __shfl_sync(0xffffffffu, c0, e * 8 + myh);
            c[e + 4]  = __shfl_sync(0xffffffffu, c1, e * 8 + myh);
            se[e]     = __shfl_sync(0xffffffffu, s0, e * 8);
            se[e + 4] = __shfl_sync(0xffffffffu, s1, e * 8);
        }
        uint4 raw[8];
        #pragma unroll
        for (int e = 0; e < 8; e++)
            raw[e] = *(const uint4*)(fbase + (size_t)se[e] * FTOT);
        #pragma unroll
        for (int q = 0; q < 8; q++) acc[q] *= cs;
        #pragma unroll
        for (int e = 0; e < 8; e++) {
            const __half2* hp = (const __half2*)&raw[e];
            #pragma unroll
            for (int q = 0; q < 4; q++) {
                float2 f = __half22float2(hp[q]);
                acc[q * 2]     = fmaf(c[e], f.x, acc[q * 2]);
                acc[q * 2 + 1] = fmaf(c[e], f.y, acc[q * 2 + 1]);
            }
        }
    }
    // 4-edge step
    for (; i + 4 <= epnd; i += 4) {
        int esrc = srcs[i + eslot];
        float v = el[esrc * NHEADS + hl] + er_h;
        v = v > 0.f ? v : 0.2f * v;
        float bm = v;
        bm = fmaxf(bm, __shfl_xor_sync(0xffffffffu, bm, 8));
        bm = fmaxf(bm, __shfl_xor_sync(0xffffffffu, bm, 16));
        float m2 = fmaxf(mx, bm);
        float scale = safe_exp(mx - m2);
        float coef = safe_exp(v - m2);
        sm = sm * scale + coef;
        mx = m2;
        float cs = __shfl_sync(0xffffffffu, scale, myh);
        float c[4]; int se[4];
        #pragma unroll
        for (int e = 0; e < 4; e++) {
            c[e]  = __shfl_sync(0xffffffffu, coef, e * 8 + myh);
            se[e] = __shfl_sync(0xffffffffu, esrc, e * 8);
        }
        uint4 raw[4];
        #pragma unroll
        for (int e = 0; e < 4; e++)
            raw[e] = *(const uint4*)(fbase + (size_t)se[e] * FTOT);
        #pragma unroll
        for (int q = 0; q < 8; q++) acc[q] *= cs;
        #pragma unroll
        for (int e = 0; e < 4; e++) {
            const __half2* hp = (const __half2*)&raw[e];
            #pragma unroll
            for (int q = 0; q < 4; q++) {
                float2 f = __half22float2(hp[q]);
                acc[q * 2]     = fmaf(c[e], f.x, acc[q * 2]);
                acc[q * 2 + 1] = fmaf(c[e], f.y, acc[q * 2 + 1]);
            }
        }
    }
    // single-edge tail
    for (; i < epnd; i++) {
        int srcT = srcs[i];
        float v = el[srcT * NHEADS + hl] + er_h;
        v = v > 0.f ? v : 0.2f * v;
        float m2 = fmaxf(mx, v);
        float scale = safe_exp(mx - m2);
        float coef = safe_exp(v - m2);
        sm = sm * scale + (eslot == 0 ? coef : 0.f);
        mx = m2;
        float cs = __shfl_sync(0xffffffffu, scale, myh);
        float c  = __shfl_sync(0xffffffffu, coef, myh);
        uint4 raw = *(const uint4*)(fbase + (size_t)srcT * FTOT);
        const __half2* hp = (const __half2*)&raw;
        #pragma unroll
        for (int q = 0; q < 8; q++) acc[q] *= cs;
        #pragma unroll
        for (int q = 0; q < 4; q++) {
            float2 f = __half22float2(hp[q]);
            acc[q * 2]     = fmaf(c, f.x, acc[q * 2]);
            acc[q * 2 + 1] = fmaf(c, f.y, acc[q * 2 + 1]);
        }
    }
    // finalize
    sm += __shfl_xor_sync(0xffffffffu, sm, 8);
    sm += __shfl_xor_sync(0xffffffffu, sm, 16);
    float inv = 1.0f / (sm + 1e-9f);
    float cinv = __shfl_sync(0xffffffffu, inv, myh);
    float4 b0 = *(const float4*)(bias + lane * 8);
    float4 b1 = *(const float4*)(bias + lane * 8 + 4);
    float o[8];
    o[0] = acc[0] * cinv + b0.x; o[1] = acc[1] * cinv + b0.y;
    o[2] = acc[2] * cinv + b0.z; o[3] = acc[3] * cinv + b0.w;
    o[4] = acc[4] * cinv + b1.x; o[5] = acc[5] * cinv + b1.y;
    o[6] = acc[6] * cinv + b1.z; o[7] = acc[7] * cinv + b1.w;
    #pragma unroll
    for (int q = 0; q < 8; q++) o[q] = o[q] > 0.f ? o[q] : expm1f(o[q]);
    uint4 packed = make_uint4(pack2h(o[0], o[1]), pack2h(o[2], o[3]),
                              pack2h(o[4], o[5]), pack2h(o[6], o[7]));
    *(uint4*)(out + (size_t)n * FTOT + lane * 8) = packed;
}

// ---------------- final layer aggregate (1 head, D=32) ----------------
__global__ void __launch_bounds__(256)
agg1_kernel(const float* __restrict__ feat2, const float* __restrict__ el,
            const float* __restrict__ er, const float* __restrict__ bias,
            float* __restrict__ out, const int* __restrict__ off,
            const int* __restrict__ srcs) {
    int warp = (blockIdx.x * blockDim.x + threadIdx.x) >> 5;
    if (warp >= NN) return;
    const int lane = threadIdx.x & 31;
    const int n = warp;
    const int s = off[n], epnd = off[n + 1];
    const float er_n = er[n];

    float mx = -INFINITY, sm = 0.f;
    for (int i = s + lane; i < epnd; i += 32) {
        int src = srcs[i];
        float v = el[src] + er_n;
        v = v > 0.f ? v : 0.2f * v;
        float m2 = fmaxf(mx, v);
        sm = sm * safe_exp(mx - m2) + safe_exp(v - m2);
        mx = m2;
    }
    #pragma unroll
    for (int d = 16; d >= 1; d >>= 1) {
        float om = __shfl_xor_sync(0xffffffffu, mx, d);
        float os = __shfl_xor_sync(0xffffffffu, sm, d);
        float m2 = fmaxf(mx, om);
        sm = sm * safe_exp(mx - m2) + os * safe_exp(om - m2);
        mx = m2;
    }
    const float inv = 1.0f / (sm + 1e-9f);

    float acc = 0.f;
    for (int i = s; i < epnd; i++) {
        int src = srcs[i];
        float v = el[src] + er_n;
        v = v > 0.f ? v : 0.2f * v;
        float coef = safe_exp(v - mx) * inv;
        acc = fmaf(coef, feat2[(size_t)src * HIDD + lane], acc);
    }
    out[(size_t)n * HIDD + lane] = acc + bias[lane];
}

// ---------------- launch ----------------
extern "C" void kernel_launch(void* const* d_in, const int* in_sizes, int n_in,
                              void* d_out, int out_size) {
    const float* features = (const float*)d_in[0];
    const int*   src      = (const int*)d_in[1];
    const int*   dst      = (const int*)d_in[2];
    const float* W0  = (const float*)d_in[3];
    const float* al0 = (const float*)d_in[4];
    const float* ar0 = (const float*)d_in[5];
    const float* b0  = (const float*)d_in[6];
    const float* W1  = (const float*)d_in[7];
    const float* al1 = (const float*)d_in[8];
    const float* ar1 = (const float*)d_in[9];
    const float* b1  = (const float*)d_in[10];
    const float* W2  = (const float*)d_in[11];
    const float* al2 = (const float*)d_in[12];
    const float* ar2 = (const float*)d_in[13];
    const float* b2  = (const float*)d_in[14];
    float* out = (float*)d_out;

    __half *featH, *hH, *WH;
    float *feat2, *el, *er;
    int *count, *off, *cursor, *srcs, *bsum, *boff;
    cudaGetSymbolAddress((void**)&featH,  g_featH);
    cudaGetSymbolAddress((void**)&hH,     g_hH);
    cudaGetSymbolAddress((void**)&WH,     g_WH);
    cudaGetSymbolAddress((void**)&feat2,  g_feat2);
    cudaGetSymbolAddress((void**)&el,     g_el);
    cudaGetSymbolAddress((void**)&er,     g_er);
    cudaGetSymbolAddress((void**)&count,  g_count);
    cudaGetSymbolAddress((void**)&off,    g_off);
    cudaGetSymbolAddress((void**)&cursor, g_cursor);
    cudaGetSymbolAddress((void**)&srcs,   g_srcs);
    cudaGetSymbolAddress((void**)&bsum,   g_bsum);
    cudaGetSymbolAddress((void**)&boff,   g_boff);
    __half* WH0 = WH;
    __half* WH1 = WH + FTOT * FTOT;

    cudaFuncSetAttribute(mma_gemm_kernel<float>,
                         cudaFuncAttributeMaxDynamicSharedMemorySize, GEMM_SMEM);
    cudaFuncSetAttribute(mma_gemm_kernel<__half>,
                         cudaFuncAttributeMaxDynamicSharedMemorySize, GEMM_SMEM);

    // weight prep (fp16 transpose)
    wtrans_kernel<<<FTOT, FTOT>>>(W0, WH0);
    wtrans_kernel<<<FTOT, FTOT>>>(W1, WH1);

    // CSR by dst (src values scattered directly)
    cudaMemsetAsync(count, 0, NN * sizeof(int));
    hist_kernel<<<(EE + 255) / 256, 256>>>(dst, count);
    scan1_kernel<<<NB, 1024>>>(count, off, bsum);
    scan2_kernel<<<1, 64>>>(bsum, boff, off);
    scan3_kernel<<<NB, 1024>>>(off, boff, cursor);
    scatter_kernel<<<(EE + 255) / 256, 256>>>(dst, src, cursor, srcs);

    const int aggBlocks = (NN * 32 + 255) / 256;
    dim3 gemmGrid(2, (NN + 127) / 128);
    dim3 gemmFinal(1, (NN + 127) / 128);

    // layer 0 (GEMM fp32-in + fused el/er, fp16 out)
    mma_gemm_kernel<float><<<gemmGrid, 256, GEMM_SMEM>>>(features, WH0, featH, al0, ar0, el, er, NN);
    agg8_kernel<<<aggBlocks, 256>>>(featH, el, er, b0, hH, off, srcs);

    // layer 1 (GEMM fp16-in)
    mma_gemm_kernel<__half><<<gemmGrid, 256, GEMM_SMEM>>>(hH, WH1, featH, al1, ar1, el, er, NN);
    agg8_kernel<<<aggBlocks, 256>>>(featH, el, er, b1, hH, off, srcs);

    // layer 2 (single head, D=32, no activation; fused el/er)
    sgemm_final_kernel<<<gemmFinal, 128>>>(hH, W2, feat2, al2, ar2, el, er, NN);
    agg1_kernel<<<aggBlocks, 256>>>(feat2, el, er, b2, out, off, srcs);
}

// round 13
// speedup vs baseline: 3.0506x; 1.0496x over previous
#include <cuda_runtime.h>
#include <cuda_fp16.h>
#include <math.h>
#include <stdint.h>

#define NN 50000
#define EE 800000
#define NHEADS 8
#define HIDD 32
#define FTOT 256   // NHEADS*HIDD, also IN_FEATS
#define NB 49      // scan blocks: 49*1024 >= NN

// ---------------- scratch (static device globals; no allocation) ----------------
__device__ __align__(16) __half g_featH[(size_t)NN * FTOT];  // 25.6 MB (GEMM out, fp16)
__device__ __align__(16) __half g_hH[(size_t)NN * FTOT];     // 25.6 MB (agg8 out, fp16)
__device__ __align__(16) __half g_WH[2][FTOT * FTOT];        // W0/W1 transposed fp16
__device__ __align__(16) float g_feat2[(size_t)NN * HIDD];   // 6.4 MB
__device__ __align__(16) float g_el[NN * NHEADS];
__device__ __align__(16) float g_er[NN * NHEADS];
__device__ int g_count[NN];
__device__ int g_off[NN + 1];
__device__ int g_cursor[NN];
__device__ int g_srcs[EE];    // src node of each edge, sorted by dst
__device__ int g_bsum[64];
__device__ int g_boff[64];

// ---------------- helpers ----------------
__device__ __forceinline__ uint32_t smem_u32(const void* p) {
    uint32_t a;
    asm("{ .reg .u64 t; cvta.to.shared.u64 t, %1; cvt.u32.u64 %0, t; }" : "=r"(a) : "l"(p));
    return a;
}
__device__ __forceinline__ void ldsm_x4(uint32_t addr, uint32_t& r0, uint32_t& r1,
                                        uint32_t& r2, uint32_t& r3) {
    asm volatile("ldmatrix.sync.aligned.m8n8.x4.shared.b16 {%0,%1,%2,%3}, [%4];"
                 : "=r"(r0), "=r"(r1), "=r"(r2), "=r"(r3) : "r"(addr));
}
__device__ __forceinline__ void mma_f16(float* d, const uint32_t* a, const uint32_t* b) {
    asm volatile(
        "mma.sync.aligned.m16n8k16.row.col.f32.f16.f16.f32 "
        "{%0,%1,%2,%3}, {%4,%5,%6,%7}, {%8,%9}, {%0,%1,%2,%3};"
        : "+f"(d[0]), "+f"(d[1]), "+f"(d[2]), "+f"(d[3])
        : "r"(a[0]), "r"(a[1]), "r"(a[2]), "r"(a[3]), "r"(b[0]), "r"(b[1]));
}
__device__ __forceinline__ uint32_t pack2h(float a, float b) {
    __half2 t = __floats2half2_rn(a, b);
    return *(uint32_t*)&t;
}
// exp argument guard: fmaxf(NaN, -88) = -88, so (-inf) - (-inf) merges stay finite
__device__ __forceinline__ float safe_exp(float x) {
    return __expf(fmaxf(x, -88.f));
}

// 16 contiguous elements -> 8 packed fp16 pairs
__device__ __forceinline__ void loadA16(const float* p, uint32_t* d) {
    const float4* q = (const float4*)p;
    #pragma unroll
    for (int i = 0; i < 4; i++) {
        float4 v = q[i];
        d[2 * i]     = pack2h(v.x, v.y);
        d[2 * i + 1] = pack2h(v.z, v.w);
    }
}
__device__ __forceinline__ void loadA16(const __half* p, uint32_t* d) {
    uint4 a = ((const uint4*)p)[0];
    uint4 b = ((const uint4*)p)[1];
    d[0] = a.x; d[1] = a.y; d[2] = a.z; d[3] = a.w;
    d[4] = b.x; d[5] = b.y; d[6] = b.z; d[7] = b.w;
}
__device__ __forceinline__ void zeroA16(uint32_t* d) {
    #pragma unroll
    for (int q = 0; q < 8; q++) d[q] = 0u;
}

// ---------------- W transpose to fp16 [outcol][k] ----------------
__global__ void wtrans_kernel(const float* __restrict__ W, __half* __restrict__ Wt) {
    int n = blockIdx.x;   // output column
    int k = threadIdx.x;  // input row
    Wt[n * FTOT + k] = __float2half(W[(size_t)k * FTOT + n]);
}

// ---------------- mma.sync fp16 GEMM: C[M x 256] = A[M x 256] * W[256 x 256]
#define SP 40                      // smem row pitch in halfs
#define TILE_H (128 * SP)          // halfs per logical tile
#define BUF_H (2 * TILE_H)         // As | Bs
#define GEMM_SMEM (2 * BUF_H * 2)  // 40960 bytes

template <typename TA>
__global__ void __launch_bounds__(256, 2)
mma_gemm_kernel(const TA* __restrict__ A, const __half* __restrict__ Wt,
                __half* __restrict__ C, const float* __restrict__ al,
                const float* __restrict__ ar, float* __restrict__ el,
                float* __restrict__ er, int M) {
    extern __shared__ __half2 smem_raw[];
    uint16_t* smem = (uint16_t*)smem_raw;
    const int tid = threadIdx.x;
    const int wid = tid >> 5;
    const int lane = tid & 31;
    const int rowBase = blockIdx.y * 128;
    const int colBase = blockIdx.x * 128;
    const int mbase = (wid >> 2) * 64;   // warpM in {0,1}
    const int nbase = (wid & 3) * 32;    // warpN in {0..3} == head within tile

    float acc[4][4][4];
    #pragma unroll
    for (int i = 0; i < 4; i++)
        #pragma unroll
        for (int j = 0; j < 4; j++)
            #pragma unroll
            for (int q = 0; q < 4; q++) acc[i][j][q] = 0.f;

    const int arow = tid >> 1;            // tile row (A row / B outcol)
    const int akq  = (tid & 1) * 4;       // 16-half slice selector {0,16}
    const __half* Brow = Wt + (size_t)(colBase + arow) * FTOT;

    uint32_t prawA[8], prawB[8];
    {
        int gr = rowBase + arow;
        if (gr < M) loadA16(A + (size_t)gr * FTOT + akq * 4, prawA);
        else zeroA16(prawA);
        loadA16(Brow + akq * 4, prawB);
    }

    for (int c = 0; c < 8; c++) {
        const int b = c & 1;
        uint16_t* As = smem + b * BUF_H;
        uint16_t* Bs = As + TILE_H;

        {
            uint4* da = (uint4*)(As + arow * SP + akq * 4);
            da[0] = make_uint4(prawA[0], prawA[1], prawA[2], prawA[3]);
            da[1] = make_uint4(prawA[4], prawA[5], prawA[6], prawA[7]);
            uint4* db = (uint4*)(Bs + arow * SP + akq * 4);
            db[0] = make_uint4(prawB[0], prawB[1], prawB[2], prawB[3]);
            db[1] = make_uint4(prawB[4], prawB[5], prawB[6], prawB[7]);
        }

        if (c < 7) {
            int gr = rowBase + arow;
            if (gr < M) loadA16(A + (size_t)gr * FTOT + (c + 1) * 32 + akq * 4, prawA);
            else zeroA16(prawA);
            loadA16(Brow + (c + 1) * 32 + akq * 4, prawB);
        }
        __syncthreads();

        const uint32_t as = smem_u32(As);
        const uint32_t bs = smem_u32(Bs);
        const int t = lane >> 3, r = lane & 7;
        #pragma unroll
        for (int ks = 0; ks < 2; ks++) {
            uint32_t Ah[4][4], Bh[4][2];
            const int a_row_off = (t & 1) * 8 + r;
            const int a_col = ks * 16 + (t >> 1) * 8;
            #pragma unroll
            for (int f = 0; f < 4; f++) {
                uint32_t off = ((mbase + f * 16 + a_row_off) * SP + a_col) * 2;
                ldsm_x4(as + off, Ah[f][0], Ah[f][1], Ah[f][2], Ah[f][3]);
            }
            const int b_row_off = (t >> 1) * 8 + r;
            const int b_col = ks * 16 + (t & 1) * 8;
            #pragma unroll
            for (int g = 0; g < 2; g++) {
                uint32_t off = ((nbase + g * 16 + b_row_off) * SP + b_col) * 2;
                ldsm_x4(bs + off, Bh[2 * g][0], Bh[2 * g][1], Bh[2 * g + 1][0], Bh[2 * g + 1][1]);
            }
            #pragma unroll
            for (int i = 0; i < 4; i++)
                #pragma unroll
                for (int j = 0; j < 4; j++)
                    mma_f16(acc[i][j], Ah[i], Bh[j]);
        }
    }

    // epilogue: store C (fp16) + fused el/er for this warp's head
    const int rq = lane >> 2;
    const int cq = (lane & 3) * 2;
    const int hIdx = (colBase >> 5) + (wid & 3);
    float alv[4][2], arv[4][2];
    #pragma unroll
    for (int j = 0; j < 4; j++) {
        int d0 = hIdx * HIDD + j * 8 + cq;
        alv[j][0] = al[d0]; alv[j][1] = al[d0 + 1];
        arv[j][0] = ar[d0]; arv[j][1] = ar[d0 + 1];
    }
    #pragma unroll
    for (int i = 0; i < 4; i++) {
        int r0 = rowBase + mbase + i * 16 + rq;
        int r1 = r0 + 8;
        float sl0 = 0.f, sr0 = 0.f, sl1 = 0.f, sr1 = 0.f;
        #pragma unroll
        for (int j = 0; j < 4; j++) {
            int cc = colBase + nbase + j * 8 + cq;
            if (r0 < M) *(uint32_t*)(C + (size_t)r0 * FTOT + cc) = pack2h(acc[i][j][0], acc[i][j][1]);
            if (r1 < M) *(uint32_t*)(C + (size_t)r1 * FTOT + cc) = pack2h(acc[i][j][2], acc[i][j][3]);
            sl0 = fmaf(acc[i][j][0], alv[j][0], fmaf(acc[i][j][1], alv[j][1], sl0));
            sr0 = fmaf(acc[i][j][0], arv[j][0], fmaf(acc[i][j][1], arv[j][1], sr0));
            sl1 = fmaf(acc[i][j][2], alv[j][0], fmaf(acc[i][j][3], alv[j][1], sl1));
            sr1 = fmaf(acc[i][j][2], arv[j][0], fmaf(acc[i][j][3], arv[j][1], sr1));
        }
        #pragma unroll
        for (int d = 1; d <= 2; d <<= 1) {
            sl0 += __shfl_xor_sync(0xffffffffu, sl0, d);
            sr0 += __shfl_xor_sync(0xffffffffu, sr0, d);
            sl1 += __shfl_xor_sync(0xffffffffu, sl1, d);
            sr1 += __shfl_xor_sync(0xffffffffu, sr1, d);
        }
        if ((lane & 3) == 0) {
            if (r0 < M) { el[r0 * NHEADS + hIdx] = sl0; er[r0 * NHEADS + hIdx] = sr0; }
            if (r1 < M) { el[r1 * NHEADS + hIdx] = sl1; er[r1 * NHEADS + hIdx] = sr1; }
        }
    }
}

// ---------------- CSR build ----------------
__global__ void hist_kernel(const int* __restrict__ dst, int* __restrict__ count) {
    int e = blockIdx.x * blockDim.x + threadIdx.x;
    if (e < EE) atomicAdd(&count[dst[e]], 1);
}

__global__ void scan1_kernel(const int* __restrict__ count, int* __restrict__ off,
                             int* __restrict__ bsum) {
    __shared__ int wsum[32];
    const int t = threadIdx.x;
    const int lane = t & 31, w = t >> 5;
    const int i = blockIdx.x * 1024 + t;
    int v = (i < NN) ? count[i] : 0;
    int incl = v;
    #pragma unroll
    for (int d = 1; d < 32; d <<= 1) {
        int x = __shfl_up_sync(0xffffffffu, incl, d);
        if (lane >= d) incl += x;
    }
    if (lane == 31) wsum[w] = incl;
    __syncthreads();
    if (w == 0) {
        int s = wsum[lane];
        #pragma unroll
        for (int d = 1; d < 32; d <<= 1) {
            int x = __shfl_up_sync(0xffffffffu, s, d);
            if (lane >= d) s += x;
        }
        wsum[lane] = s;
    }
    __syncthreads();
    int wpre = (w > 0) ? wsum[w - 1] : 0;
    if (i < NN) off[i] = wpre + incl - v;
    if (t == 0) bsum[blockIdx.x] = wsum[31];
}

__global__ void scan2_kernel(const int* __restrict__ bsum, int* __restrict__ boff,
                             int* __restrict__ off) {
    __shared__ int tmp[64];
    int t = threadIdx.x;
    int v = (t < NB) ? bsum[t] : 0;
    tmp[t] = v;
    __syncthreads();
    #pragma unroll
    for (int d = 1; d < 64; d <<= 1) {
        int x = (t >= d) ? tmp[t - d] : 0;
        __syncthreads();
        tmp[t] += x;
        __syncthreads();
    }
    if (t < NB) boff[t] = tmp[t] - v;
    if (t == 63) off[NN] = tmp[63];
}

__global__ void scan3_kernel(int* __restrict__ off, const int* __restrict__ boff,
                             int* __restrict__ cursor) {
    const int i = blockIdx.x * 1024 + threadIdx.x;
    if (i < NN) {
        int o = off[i] + boff[blockIdx.x];
        off[i] = o;
        cursor[i] = o;
    }
}

__global__ void scatter_kernel(const int* __restrict__ dst, const int* __restrict__ srcArr,
                               int* __restrict__ cursor, int* __restrict__ srcs) {
    int e = blockIdx.x * blockDim.x + threadIdx.x;
    if (e < EE) {
        int pos = atomicAdd(&cursor[dst[e]], 1);
        srcs[pos] = srcArr[e];
    }
}

// ---------------- final-layer SGEMM (fp16 A, fp32 math) with fused el/er ----------------
__global__ void __launch_bounds__(128)
sgemm_final_kernel(const __half* __restrict__ A, const float* __restrict__ B,
                   float* __restrict__ C, const float* __restrict__ al,
                   const float* __restrict__ ar, float* __restrict__ el,
                   float* __restrict__ er, int M) {
    constexpr int BM = 128, BN = 32, BK = 32, TM = 8, TN = 4;
    constexpr int TCOLS = BN / TN;   // 8
    constexpr int NT = 128;
    __shared__ float As[BK][BM];
    __shared__ float Bs[BK][BN];
    const int tid = threadIdx.x;
    const int tr = tid / TCOLS;
    const int tc = tid % TCOLS;
    const int rowBase = blockIdx.y * BM;

    float acc[TM][TN];
    #pragma unroll
    for (int i = 0; i < TM; i++)
        #pragma unroll
        for (int j = 0; j < TN; j++) acc[i][j] = 0.f;

    for (int k0 = 0; k0 < FTOT; k0 += BK) {
        #pragma unroll
        for (int i = tid * 4; i < BM * BK; i += NT * 4) {
            int m = i / BK, kk = i % BK;
            int gr = rowBase + m;
            float4 v = make_float4(0.f, 0.f, 0.f, 0.f);
            if (gr < M) {
                uint2 hraw = *(const uint2*)(A + (size_t)gr * FTOT + k0 + kk);
                float2 f0 = __half22float2(*(const __half2*)&hraw.x);
                float2 f1 = __half22float2(*(const __half2*)&hraw.y);
                v = make_float4(f0.x, f0.y, f1.x, f1.y);
            }
            As[kk + 0][m] = v.x; As[kk + 1][m] = v.y;
            As[kk + 2][m] = v.z; As[kk + 3][m] = v.w;
        }
        #pragma unroll
        for (int i = tid * 4; i < BK * BN; i += NT * 4) {
            int kk = i / BN, nn = i % BN;
            float4 v = *(const float4*)(B + (size_t)(k0 + kk) * BN + nn);
            *(float4*)&Bs[kk][nn] = v;
        }
        __syncthreads();
        #pragma unroll
        for (int kk = 0; kk < BK; kk++) {
            float a[TM], b[TN];
            #pragma unroll
            for (int i = 0; i < TM / 4; i++)
                *(float4*)&a[i * 4] = *(const float4*)&As[kk][tr * TM + i * 4];
            *(float4*)&b[0] = *(const float4*)&Bs[kk][tc * TN];
            #pragma unroll
            for (int i = 0; i < TM; i++)
                #pragma unroll
                for (int j = 0; j < TN; j++) acc[i][j] = fmaf(a[i], b[j], acc[i][j]);
        }
        __syncthreads();
    }
    float alv[TN], arv[TN];
    #pragma unroll
    for (int j = 0; j < TN; j++) { alv[j] = al[tc * TN + j]; arv[j] = ar[tc * TN + j]; }
    #pragma unroll
    for (int i = 0; i < TM; i++) {
        int r = rowBase + tr * TM + i;
        float pl = 0.f, pr = 0.f;
        #pragma unroll
        for (int j = 0; j < TN; j++) {
            pl = fmaf(acc[i][j], alv[j], pl);
            pr = fmaf(acc[i][j], arv[j], pr);
        }
        #pragma unroll
        for (int d = 1; d <= 4; d <<= 1) {
            pl += __shfl_xor_sync(0xffffffffu, pl, d);
            pr += __shfl_xor_sync(0xffffffffu, pr, d);
        }
        if (r < M) {
            *(float4*)(C + (size_t)r * BN + tc * TN) = *(float4*)&acc[i][0];
            if (tc == 0) { el[r] = pl; er[r] = pr; }
        }
    }
}

// ---------------- per-node warp: SINGLE-PASS flash-style softmax + aggregate
__global__ void __launch_bounds__(256)
agg8_kernel(const __half* __restrict__ feat, const float* __restrict__ el,
            const float* __restrict__ er, const float* __restrict__ bias,
            __half* __restrict__ out, const int* __restrict__ off,
            const int* __restrict__ srcs) {
    int warp = (blockIdx.x * blockDim.x + threadIdx.x) >> 5;
    if (warp >= NN) return;
    const int lane = threadIdx.x & 31;
    const int n = warp;
    const int s = off[n], epnd = off[n + 1];
    const int hl = lane & 7;
    const int eslot = lane >> 3;
    const int myh = lane >> 2;
    const float er_h = er[n * NHEADS + hl];
    const __half* fbase = feat + lane * 8;

    float mx = -INFINITY;
    float sm = 0.f;
    float acc[8];
    #pragma unroll
    for (int q = 0; q < 8; q++) acc[q] = 0.f;

    int i = s;
    for (; i + 8 <= epnd; i += 8) {
        int s0 = srcs[i + eslot];
        int s1 = srcs[i + 4 + eslot];
        float v0 = el[s0 * NHEADS + hl] + er_h;
        float v1 = el[s1 * NHEADS + hl] + er_h;
        v0 = v0 > 0.f ? v0 : 0.2f * v0;
        v1 = v1 > 0.f ? v1 : 0.2f * v1;
        float bm = fmaxf(v0, v1);
        bm = fmaxf(bm, __shfl_xor_sync(0xffffffffu, bm, 8));
        bm = fmaxf(bm, __shfl_xor_sync(0xffffffffu, bm, 16));
        float m2 = fmaxf(mx, bm);
        float scale = safe_exp(mx - m2);
        float c0 = safe_exp(v0 - m2);
        float c1 = safe_exp(v1 - m2);
        sm = sm * scale + c0 + c1;
        mx = m2;
        float cs = __shfl_sync(0xffffffffu, scale, myh);
        float c[8]; int se[8];
        #pragma unroll
        for (int e = 0; e < 4; e++) {
            c[e]      = __shfl_sync(0xffffffffu, c0, e * 8 + myh);
            c[e + 4]  = __shfl_sync(0xffffffffu, c1, e * 8 + myh);
            se[e]     = __shfl_sync(0xffffffffu, s0, e * 8);
            se[e + 4] = __shfl_sync(0xffffffffu, s1, e * 8);
        }
        uint4 raw[8];
        #pragma unroll
        for (int e = 0; e < 8; e++)
            raw[e] = *(const uint4*)(fbase + (size_t)se[e] * FTOT);
        #pragma unroll
        for (int q = 0; q < 8; q++) acc[q] *= cs;
        #pragma unroll
        for (int e = 0; e < 8; e++) {
            const __half2* hp = (const __half2*)&raw[e];
            #pragma unroll
            for (int q = 0; q < 4; q++) {
                float2 f = __half22float2(hp[q]);
                acc[q * 2]     = fmaf(c[e], f.x, acc[q * 2]);
                acc[q * 2 + 1] = fmaf(c[e], f.y, acc[q * 2 + 1]);
            }
        }
    }
    for (; i + 4 <= epnd; i += 4) {
        int esrc = srcs[i + eslot];
        float v = el[esrc * NHEADS + hl] + er_h;
        v = v > 0.f ? v : 0.2f * v;
        float bm = v;
        bm = fmaxf(bm, __shfl_xor_sync(0xffffffffu, bm, 8));
        bm = fmaxf(bm, __shfl_xor_sync(0xffffffffu, bm, 16));
        float m2 = fmaxf(mx, bm);
        float scale = safe_exp(mx - m2);
        float coef = safe_exp(v - m2);
        sm = sm * scale + coef;
        mx = m2;
        float cs = __shfl_sync(0xffffffffu, scale, myh);
        float c[4]; int se[4];
        #pragma unroll
        for (int e = 0; e < 4; e++) {
            c[e]  = __shfl_sync(0xffffffffu, coef, e * 8 + myh);
            se[e] = __shfl_sync(0xffffffffu, esrc, e * 8);
        }
        uint4 raw[4];
        #pragma unroll
        for (int e = 0; e < 4; e++)
            raw[e] = *(const uint4*)(fbase + (size_t)se[e] * FTOT);
        #pragma unroll
        for (int q = 0; q < 8; q++) acc[q] *= cs;
        #pragma unroll
        for (int e = 0; e < 4; e++) {
            const __half2* hp = (const __half2*)&raw[e];
            #pragma unroll
            for (int q = 0; q < 4; q++) {
                float2 f = __half22float2(hp[q]);
                acc[q * 2]     = fmaf(c[e], f.x, acc[q * 2]);
                acc[q * 2 + 1] = fmaf(c[e], f.y, acc[q * 2 + 1]);
            }
        }
    }
    for (; i < epnd; i++) {
        int srcT = srcs[i];
        float v = el[srcT * NHEADS + hl] + er_h;
        v = v > 0.f ? v : 0.2f * v;
        float m2 = fmaxf(mx, v);
        float scale = safe_exp(mx - m2);
        float coef = safe_exp(v - m2);
        sm = sm * scale + (eslot == 0 ? coef : 0.f);
        mx = m2;
        float cs = __shfl_sync(0xffffffffu, scale, myh);
        float c  = __shfl_sync(0xffffffffu, coef, myh);
        uint4 raw = *(const uint4*)(fbase + (size_t)srcT * FTOT);
        const __half2* hp = (const __half2*)&raw;
        #pragma unroll
        for (int q = 0; q < 8; q++) acc[q] *= cs;
        #pragma unroll
        for (int q = 0; q < 4; q++) {
            float2 f = __half22float2(hp[q]);
            acc[q * 2]     = fmaf(c, f.x, acc[q * 2]);
            acc[q * 2 + 1] = fmaf(c, f.y, acc[q * 2 + 1]);
        }
    }
    sm += __shfl_xor_sync(0xffffffffu, sm, 8);
    sm += __shfl_xor_sync(0xffffffffu, sm, 16);
    float inv = 1.0f / (sm + 1e-9f);
    float cinv = __shfl_sync(0xffffffffu, inv, myh);
    float4 b0 = *(const float4*)(bias + lane * 8);
    float4 b1 = *(const float4*)(bias + lane * 8 + 4);
    float o[8];
    o[0] = acc[0] * cinv + b0.x; o[1] = acc[1] * cinv + b0.y;
    o[2] = acc[2] * cinv + b0.z; o[3] = acc[3] * cinv + b0.w;
    o[4] = acc[4] * cinv + b1.x; o[5] = acc[5] * cinv + b1.y;
    o[6] = acc[6] * cinv + b1.z; o[7] = acc[7] * cinv + b1.w;
    #pragma unroll
    for (int q = 0; q < 8; q++) o[q] = o[q] > 0.f ? o[q] : expm1f(o[q]);
    uint4 packed = make_uint4(pack2h(o[0], o[1]), pack2h(o[2], o[3]),
                              pack2h(o[4], o[5]), pack2h(o[6], o[7]));
    *(uint4*)(out + (size_t)n * FTOT + lane * 8) = packed;
}

// ---------------- final layer aggregate (1 head, D=32) ----------------
__global__ void __launch_bounds__(256)
agg1_kernel(const float* __restrict__ feat2, const float* __restrict__ el,
            const float* __restrict__ er, const float* __restrict__ bias,
            float* __restrict__ out, const int* __restrict__ off,
            const int* __restrict__ srcs) {
    int warp = (blockIdx.x * blockDim.x + threadIdx.x) >> 5;
    if (warp >= NN) return;
    const int lane = threadIdx.x & 31;
    const int n = warp;
    const int s = off[n], epnd = off[n + 1];
    const float er_n = er[n];

    float mx = -INFINITY, sm = 0.f;
    for (int i = s + lane; i < epnd; i += 32) {
        int src = srcs[i];
        float v = el[src] + er_n;
        v = v > 0.f ? v : 0.2f * v;
        float m2 = fmaxf(mx, v);
        sm = sm * safe_exp(mx - m2) + safe_exp(v - m2);
        mx = m2;
    }
    #pragma unroll
    for (int d = 16; d >= 1; d >>= 1) {
        float om = __shfl_xor_sync(0xffffffffu, mx, d);
        float os = __shfl_xor_sync(0xffffffffu, sm, d);
        float m2 = fmaxf(mx, om);
        sm = sm * safe_exp(mx - m2) + os * safe_exp(om - m2);
        mx = m2;
    }
    const float inv = 1.0f / (sm + 1e-9f);

    float acc = 0.f;
    for (int i = s; i < epnd; i++) {
        int src = srcs[i];
        float v = el[src] + er_n;
        v = v > 0.f ? v : 0.2f * v;
        float coef = safe_exp(v - mx) * inv;
        acc = fmaf(coef, feat2[(size_t)src * HIDD + lane], acc);
    }
    out[(size_t)n * HIDD + lane] = acc + bias[lane];
}

// ---------------- launch ----------------
extern "C" void kernel_launch(void* const* d_in, const int* in_sizes, int n_in,
                              void* d_out, int out_size) {
    const float* features = (const float*)d_in[0];
    const int*   src      = (const int*)d_in[1];
    const int*   dst      = (const int*)d_in[2];
    const float* W0  = (const float*)d_in[3];
    const float* al0 = (const float*)d_in[4];
    const float* ar0 = (const float*)d_in[5];
    const float* b0  = (const float*)d_in[6];
    const float* W1  = (const float*)d_in[7];
    const float* al1 = (const float*)d_in[8];
    const float* ar1 = (const float*)d_in[9];
    const float* b1  = (const float*)d_in[10];
    const float* W2  = (const float*)d_in[11];
    const float* al2 = (const float*)d_in[12];
    const float* ar2 = (const float*)d_in[13];
    const float* b2  = (const float*)d_in[14];
    float* out = (float*)d_out;

    __half *featH, *hH, *WH;
    float *feat2, *el, *er;
    int *count, *off, *cursor, *srcs, *bsum, *boff;
    cudaGetSymbolAddress((void**)&featH,  g_featH);
    cudaGetSymbolAddress((void**)&hH,     g_hH);
    cudaGetSymbolAddress((void**)&WH,     g_WH);
    cudaGetSymbolAddress((void**)&feat2,  g_feat2);
    cudaGetSymbolAddress((void**)&el,     g_el);
    cudaGetSymbolAddress((void**)&er,     g_er);
    cudaGetSymbolAddress((void**)&count,  g_count);
    cudaGetSymbolAddress((void**)&off,    g_off);
    cudaGetSymbolAddress((void**)&cursor, g_cursor);
    cudaGetSymbolAddress((void**)&srcs,   g_srcs);
    cudaGetSymbolAddress((void**)&bsum,   g_bsum);
    cudaGetSymbolAddress((void**)&boff,   g_boff);
    __half* WH0 = WH;
    __half* WH1 = WH + FTOT * FTOT;

    cudaFuncSetAttribute(mma_gemm_kernel<float>,
                         cudaFuncAttributeMaxDynamicSharedMemorySize, GEMM_SMEM);
    cudaFuncSetAttribute(mma_gemm_kernel<__half>,
                         cudaFuncAttributeMaxDynamicSharedMemorySize, GEMM_SMEM);

    // lazy one-time stream/event setup (first call is the uncaptured correctness
    // run, so creation never happens during graph capture; no device memory)
    static cudaStream_t s2 = nullptr;
    static cudaEvent_t evFork = nullptr, evJoin = nullptr;
    if (s2 == nullptr) {
        cudaStreamCreateWithFlags(&s2, cudaStreamNonBlocking);
        cudaEventCreateWithFlags(&evFork, cudaEventDisableTiming);
        cudaEventCreateWithFlags(&evJoin, cudaEventDisableTiming);
    }

    // fork: CSR build on s2 runs concurrently with wtrans + GEMM0 on stream 0
    cudaEventRecord(evFork, 0);
    cudaStreamWaitEvent(s2, evFork, 0);
    cudaMemsetAsync(count, 0, NN * sizeof(int), s2);
    hist_kernel<<<(EE + 255) / 256, 256, 0, s2>>>(dst, count);
    scan1_kernel<<<NB, 1024, 0, s2>>>(count, off, bsum);
    scan2_kernel<<<1, 64, 0, s2>>>(bsum, boff, off);
    scan3_kernel<<<NB, 1024, 0, s2>>>(off, boff, cursor);
    scatter_kernel<<<(EE + 255) / 256, 256, 0, s2>>>(dst, src, cursor, srcs);
    cudaEventRecord(evJoin, s2);

    const int aggBlocks = (NN * 32 + 255) / 256;
    dim3 gemmGrid(2, (NN + 127) / 128);
    dim3 gemmFinal(1, (NN + 127) / 128);

    // stream 0: weight prep + GEMM0 (independent of CSR)
    wtrans_kernel<<<FTOT, FTOT>>>(W0, WH0);
    wtrans_kernel<<<FTOT, FTOT>>>(W1, WH1);
    mma_gemm_kernel<float><<<gemmGrid, 256, GEMM_SMEM>>>(features, WH0, featH, al0, ar0, el, er, NN);

    // join: agg8 needs the CSR
    cudaStreamWaitEvent(0, evJoin, 0);
    agg8_kernel<<<aggBlocks, 256>>>(featH, el, er, b0, hH, off, srcs);

    // layer 1
    mma_gemm_kernel<__half><<<gemmGrid, 256, GEMM_SMEM>>>(hH, WH1, featH, al1, ar1, el, er, NN);
    agg8_kernel<<<aggBlocks, 256>>>(featH, el, er, b1, hH, off, srcs);

    // layer 2 (single head, D=32, no activation; fused el/er)
    sgemm_final_kernel<<<gemmFinal, 128>>>(hH, W2, feat2, al2, ar2, el, er, NN);
    agg1_kernel<<<aggBlocks, 256>>>(feat2, el, er, b2, out, off, srcs);
}

// round 14
// speedup vs baseline: 3.2765x; 1.0740x over previous
#include <cuda_runtime.h>
#include <cuda_fp16.h>
#include <math.h>
#include <stdint.h>

#define NN 50000
#define EE 800000
#define NHEADS 8
#define HIDD 32
#define FTOT 256   // NHEADS*HIDD, also IN_FEATS
#define NB 49      // scan blocks: 49*1024 >= NN

// ---------------- scratch (static device globals; no allocation) ----------------
__device__ __align__(16) __half g_featH[(size_t)NN * FTOT];  // 25.6 MB (GEMM out, fp16)
__device__ __align__(16) __half g_hH[(size_t)NN * FTOT];     // 25.6 MB (agg8 out, fp16)
__device__ __align__(16) __half g_WH[2][FTOT * FTOT];        // W0/W1 transposed fp16
__device__ __align__(16) __half g_W2H[HIDD * FTOT];          // W2 transposed fp16 [32][256]
__device__ __align__(16) float g_feat2[(size_t)NN * HIDD];   // 6.4 MB
__device__ __align__(16) float g_el[NN * NHEADS];
__device__ __align__(16) float g_er[NN * NHEADS];
__device__ int g_count[NN];
__device__ int g_off[NN + 1];
__device__ int g_cursor[NN];
__device__ int g_srcs[EE];    // src node of each edge, sorted by dst
__device__ int g_bsum[64];
__device__ int g_boff[64];

// ---------------- helpers ----------------
__device__ __forceinline__ uint32_t smem_u32(const void* p) {
    uint32_t a;
    asm("{ .reg .u64 t; cvta.to.shared.u64 t, %1; cvt.u32.u64 %0, t; }" : "=r"(a) : "l"(p));
    return a;
}
__device__ __forceinline__ void ldsm_x4(uint32_t addr, uint32_t& r0, uint32_t& r1,
                                        uint32_t& r2, uint32_t& r3) {
    asm volatile("ldmatrix.sync.aligned.m8n8.x4.shared.b16 {%0,%1,%2,%3}, [%4];"
                 : "=r"(r0), "=r"(r1), "=r"(r2), "=r"(r3) : "r"(addr));
}
__device__ __forceinline__ void mma_f16(float* d, const uint32_t* a, const uint32_t* b) {
    asm volatile(
        "mma.sync.aligned.m16n8k16.row.col.f32.f16.f16.f32 "
        "{%0,%1,%2,%3}, {%4,%5,%6,%7}, {%8,%9}, {%0,%1,%2,%3};"
        : "+f"(d[0]), "+f"(d[1]), "+f"(d[2]), "+f"(d[3])
        : "r"(a[0]), "r"(a[1]), "r"(a[2]), "r"(a[3]), "r"(b[0]), "r"(b[1]));
}
__device__ __forceinline__ uint32_t pack2h(float a, float b) {
    __half2 t = __floats2half2_rn(a, b);
    return *(uint32_t*)&t;
}
// exp argument guard: fmaxf(NaN, -88) = -88, so (-inf) - (-inf) merges stay finite
__device__ __forceinline__ float safe_exp(float x) {
    return __expf(fmaxf(x, -88.f));
}

// 16 contiguous elements -> 8 packed fp16 pairs
__device__ __forceinline__ void loadA16(const float* p, uint32_t* d) {
    const float4* q = (const float4*)p;
    #pragma unroll
    for (int i = 0; i < 4; i++) {
        float4 v = q[i];
        d[2 * i]     = pack2h(v.x, v.y);
        d[2 * i + 1] = pack2h(v.z, v.w);
    }
}
__device__ __forceinline__ void loadA16(const __half* p, uint32_t* d) {
    uint4 a = ((const uint4*)p)[0];
    uint4 b = ((const uint4*)p)[1];
    d[0] = a.x; d[1] = a.y; d[2] = a.z; d[3] = a.w;
    d[4] = b.x; d[5] = b.y; d[6] = b.z; d[7] = b.w;
}
__device__ __forceinline__ void zeroA16(uint32_t* d) {
    #pragma unroll
    for (int q = 0; q < 8; q++) d[q] = 0u;
}

// ---------------- W transposes ----------------
__global__ void wtrans_kernel(const float* __restrict__ W, __half* __restrict__ Wt) {
    int n = blockIdx.x;   // output column
    int k = threadIdx.x;  // input row
    Wt[n * FTOT + k] = __float2half(W[(size_t)k * FTOT + n]);
}
__global__ void wtrans2_kernel(const float* __restrict__ W2, __half* __restrict__ W2t) {
    int n = blockIdx.x;   // output column (0..31)
    int k = threadIdx.x;  // input row (0..255)
    W2t[n * FTOT + k] = __float2half(W2[(size_t)k * HIDD + n]);
}

// ---------------- mma.sync fp16 GEMM: C[M x 256] = A[M x 256] * W[256 x 256]
#define SP 40                      // smem row pitch in halfs
#define TILE_H (128 * SP)          // halfs per logical tile
#define BUF_H (2 * TILE_H)         // As | Bs
#define GEMM_SMEM (2 * BUF_H * 2)  // 40960 bytes

template <typename TA>
__global__ void __launch_bounds__(256, 2)
mma_gemm_kernel(const TA* __restrict__ A, const __half* __restrict__ Wt,
                __half* __restrict__ C, const float* __restrict__ al,
                const float* __restrict__ ar, float* __restrict__ el,
                float* __restrict__ er, int M) {
    extern __shared__ __half2 smem_raw[];
    uint16_t* smem = (uint16_t*)smem_raw;
    const int tid = threadIdx.x;
    const int wid = tid >> 5;
    const int lane = tid & 31;
    const int rowBase = blockIdx.y * 128;
    const int colBase = blockIdx.x * 128;
    const int mbase = (wid >> 2) * 64;
    const int nbase = (wid & 3) * 32;

    float acc[4][4][4];
    #pragma unroll
    for (int i = 0; i < 4; i++)
        #pragma unroll
        for (int j = 0; j < 4; j++)
            #pragma unroll
            for (int q = 0; q < 4; q++) acc[i][j][q] = 0.f;

    const int arow = tid >> 1;
    const int akq  = (tid & 1) * 4;
    const __half* Brow = Wt + (size_t)(colBase + arow) * FTOT;

    uint32_t prawA[8], prawB[8];
    {
        int gr = rowBase + arow;
        if (gr < M) loadA16(A + (size_t)gr * FTOT + akq * 4, prawA);
        else zeroA16(prawA);
        loadA16(Brow + akq * 4, prawB);
    }

    for (int c = 0; c < 8; c++) {
        const int b = c & 1;
        uint16_t* As = smem + b * BUF_H;
        uint16_t* Bs = As + TILE_H;

        {
            uint4* da = (uint4*)(As + arow * SP + akq * 4);
            da[0] = make_uint4(prawA[0], prawA[1], prawA[2], prawA[3]);
            da[1] = make_uint4(prawA[4], prawA[5], prawA[6], prawA[7]);
            uint4* db = (uint4*)(Bs + arow * SP + akq * 4);
            db[0] = make_uint4(prawB[0], prawB[1], prawB[2], prawB[3]);
            db[1] = make_uint4(prawB[4], prawB[5], prawB[6], prawB[7]);
        }

        if (c < 7) {
            int gr = rowBase + arow;
            if (gr < M) loadA16(A + (size_t)gr * FTOT + (c + 1) * 32 + akq * 4, prawA);
            else zeroA16(prawA);
            loadA16(Brow + (c + 1) * 32 + akq * 4, prawB);
        }
        __syncthreads();

        const uint32_t as = smem_u32(As);
        const uint32_t bs = smem_u32(Bs);
        const int t = lane >> 3, r = lane & 7;
        #pragma unroll
        for (int ks = 0; ks < 2; ks++) {
            uint32_t Ah[4][4], Bh[4][2];
            const int a_row_off = (t & 1) * 8 + r;
            const int a_col = ks * 16 + (t >> 1) * 8;
            #pragma unroll
            for (int f = 0; f < 4; f++) {
                uint32_t off = ((mbase + f * 16 + a_row_off) * SP + a_col) * 2;
                ldsm_x4(as + off, Ah[f][0], Ah[f][1], Ah[f][2], Ah[f][3]);
            }
            const int b_row_off = (t >> 1) * 8 + r;
            const int b_col = ks * 16 + (t & 1) * 8;
            #pragma unroll
            for (int g = 0; g < 2; g++) {
                uint32_t off = ((nbase + g * 16 + b_row_off) * SP + b_col) * 2;
                ldsm_x4(bs + off, Bh[2 * g][0], Bh[2 * g][1], Bh[2 * g + 1][0], Bh[2 * g + 1][1]);
            }
            #pragma unroll
            for (int i = 0; i < 4; i++)
                #pragma unroll
                for (int j = 0; j < 4; j++)
                    mma_f16(acc[i][j], Ah[i], Bh[j]);
        }
    }

    const int rq = lane >> 2;
    const int cq = (lane & 3) * 2;
    const int hIdx = (colBase >> 5) + (wid & 3);
    float alv[4][2], arv[4][2];
    #pragma unroll
    for (int j = 0; j < 4; j++) {
        int d0 = hIdx * HIDD + j * 8 + cq;
        alv[j][0] = al[d0]; alv[j][1] = al[d0 + 1];
        arv[j][0] = ar[d0]; arv[j][1] = ar[d0 + 1];
    }
    #pragma unroll
    for (int i = 0; i < 4; i++) {
        int r0 = rowBase + mbase + i * 16 + rq;
        int r1 = r0 + 8;
        float sl0 = 0.f, sr0 = 0.f, sl1 = 0.f, sr1 = 0.f;
        #pragma unroll
        for (int j = 0; j < 4; j++) {
            int cc = colBase + nbase + j * 8 + cq;
            if (r0 < M) *(uint32_t*)(C + (size_t)r0 * FTOT + cc) = pack2h(acc[i][j][0], acc[i][j][1]);
            if (r1 < M) *(uint32_t*)(C + (size_t)r1 * FTOT + cc) = pack2h(acc[i][j][2], acc[i][j][3]);
            sl0 = fmaf(acc[i][j][0], alv[j][0], fmaf(acc[i][j][1], alv[j][1], sl0));
            sr0 = fmaf(acc[i][j][0], arv[j][0], fmaf(acc[i][j][1], arv[j][1], sr0));
            sl1 = fmaf(acc[i][j][2], alv[j][0], fmaf(acc[i][j][3], alv[j][1], sl1));
            sr1 = fmaf(acc[i][j][2], arv[j][0], fmaf(acc[i][j][3], arv[j][1], sr1));
        }
        #pragma unroll
        for (int d = 1; d <= 2; d <<= 1) {
            sl0 += __shfl_xor_sync(0xffffffffu, sl0, d);
            sr0 += __shfl_xor_sync(0xffffffffu, sr0, d);
            sl1 += __shfl_xor_sync(0xffffffffu, sl1, d);
            sr1 += __shfl_xor_sync(0xffffffffu, sr1, d);
        }
        if ((lane & 3) == 0) {
            if (r0 < M) { el[r0 * NHEADS + hIdx] = sl0; er[r0 * NHEADS + hIdx] = sr0; }
            if (r1 < M) { el[r1 * NHEADS + hIdx] = sl1; er[r1 * NHEADS + hIdx] = sr1; }
        }
    }
}

// ---------------- final-layer mma GEMM: C[M x 32] = A[M x 256] (fp16) * W2t^T
// CTA tile 256 rows x 32 cols, 8 warps (warp tile 32x32), BK=32 double-buffered.
// Fused el/er (single head). C stored fp32.
#define FSP 40
#define FA_H (256 * FSP)            // A tile halfs
#define FB_H (32 * FSP)             // B tile halfs
#define FBUF_H (FA_H + FB_H)
#define FGEMM_SMEM (2 * FBUF_H * 2) // 46080 bytes

__global__ void __launch_bounds__(256, 2)
mma_final_kernel(const __half* __restrict__ A, const __half* __restrict__ W2t,
                 float* __restrict__ C, const float* __restrict__ al,
                 const float* __restrict__ ar, float* __restrict__ el,
                 float* __restrict__ er, int M) {
    extern __shared__ __half2 smem_raw[];
    uint16_t* smem = (uint16_t*)smem_raw;
    const int tid = threadIdx.x;
    const int wid = tid >> 5;
    const int lane = tid & 31;
    const int rowBase = blockIdx.y * 256;
    const int mbase = wid * 32;        // 8 warps x 32 rows

    float acc[2][4][4];
    #pragma unroll
    for (int i = 0; i < 2; i++)
        #pragma unroll
        for (int j = 0; j < 4; j++)
            #pragma unroll
            for (int q = 0; q < 4; q++) acc[i][j][q] = 0.f;

    // A loader: 1 thread per row, 32 halfs (2x loadA16)
    // B loader: threads 0..63, row = tid>>1, 16 halfs each
    const int brow = tid >> 1;
    const int bsl  = (tid & 1) * 16;

    uint32_t prawA[16], prawB[8];
    {
        int gr = rowBase + tid;
        if (gr < M) {
            loadA16(A + (size_t)gr * FTOT, prawA);
            loadA16(A + (size_t)gr * FTOT + 16, prawA + 8);
        } else { zeroA16(prawA); zeroA16(prawA + 8); }
        if (tid < 64) loadA16(W2t + (size_t)brow * FTOT + bsl, prawB);
    }

    for (int c = 0; c < 8; c++) {
        const int b = c & 1;
        uint16_t* As = smem + b * FBUF_H;
        uint16_t* Bs = As + FA_H;

        {
            uint4* da = (uint4*)(As + tid * FSP);
            da[0] = make_uint4(prawA[0], prawA[1], prawA[2], prawA[3]);
            da[1] = make_uint4(prawA[4], prawA[5], prawA[6], prawA[7]);
            da[2] = make_uint4(prawA[8], prawA[9], prawA[10], prawA[11]);
            da[3] = make_uint4(prawA[12], prawA[13], prawA[14], prawA[15]);
            if (tid < 64) {
                uint4* db = (uint4*)(Bs + brow * FSP + bsl);
                db[0] = make_uint4(prawB[0], prawB[1], prawB[2], prawB[3]);
                db[1] = make_uint4(prawB[4], prawB[5], prawB[6], prawB[7]);
            }
        }

        if (c < 7) {
            int gr = rowBase + tid;
            const __half* Ab = A + (size_t)gr * FTOT + (c + 1) * 32;
            if (gr < M) { loadA16(Ab, prawA); loadA16(Ab + 16, prawA + 8); }
            else { zeroA16(prawA); zeroA16(prawA + 8); }
            if (tid < 64) loadA16(W2t + (size_t)brow * FTOT + (c + 1) * 32 + bsl, prawB);
        }
        __syncthreads();

        const uint32_t as = smem_u32(As);
        const uint32_t bs = smem_u32(Bs);
        const int t = lane >> 3, r = lane & 7;
        #pragma unroll
        for (int ks = 0; ks < 2; ks++) {
            uint32_t Ah[2][4], Bh[4][2];
            const int a_row_off = (t & 1) * 8 + r;
            const int a_col = ks * 16 + (t >> 1) * 8;
            #pragma unroll
            for (int f = 0; f < 2; f++) {
                uint32_t off = ((mbase + f * 16 + a_row_off) * FSP + a_col) * 2;
                ldsm_x4(as + off, Ah[f][0], Ah[f][1], Ah[f][2], Ah[f][3]);
            }
            const int b_row_off = (t >> 1) * 8 + r;
            const int b_col = ks * 16 + (t & 1) * 8;
            #pragma unroll
            for (int g = 0; g < 2; g++) {
                uint32_t off = ((g * 16 + b_row_off) * FSP + b_col) * 2;
                ldsm_x4(bs + off, Bh[2 * g][0], Bh[2 * g][1], Bh[2 * g + 1][0], Bh[2 * g + 1][1]);
            }
            #pragma unroll
            for (int i = 0; i < 2; i++)
                #pragma unroll
                for (int j = 0; j < 4; j++)
                    mma_f16(acc[i][j], Ah[i], Bh[j]);
        }
    }

    // epilogue: store C fp32 + fused el/er (single head)
    const int rq = lane >> 2;
    const int cq = (lane & 3) * 2;
    float alv[4][2], arv[4][2];
    #pragma unroll
    for (int j = 0; j < 4; j++) {
        int d0 = j * 8 + cq;
        alv[j][0] = al[d0]; alv[j][1] = al[d0 + 1];
        arv[j][0] = ar[d0]; arv[j][1] = ar[d0 + 1];
    }
    #pragma unroll
    for (int i = 0; i < 2; i++) {
        int r0 = rowBase + mbase + i * 16 + rq;
        int r1 = r0 + 8;
        float sl0 = 0.f, sr0 = 0.f, sl1 = 0.f, sr1 = 0.f;
        #pragma unroll
        for (int j = 0; j < 4; j++) {
            int cc = j * 8 + cq;
            if (r0 < M) *(float2*)(C + (size_t)r0 * HIDD + cc) = make_float2(acc[i][j][0], acc[i][j][1]);
            if (r1 < M) *(float2*)(C + (size_t)r1 * HIDD + cc) = make_float2(acc[i][j][2], acc[i][j][3]);
            sl0 = fmaf(acc[i][j][0], alv[j][0], fmaf(acc[i][j][1], alv[j][1], sl0));
            sr0 = fmaf(acc[i][j][0], arv[j][0], fmaf(acc[i][j][1], arv[j][1], sr0));
            sl1 = fmaf(acc[i][j][2], alv[j][0], fmaf(acc[i][j][3], alv[j][1], sl1));
            sr1 = fmaf(acc[i][j][2], arv[j][0], fmaf(acc[i][j][3], arv[j][1], sr1));
        }
        #pragma unroll
        for (int d = 1; d <= 2; d <<= 1) {
            sl0 += __shfl_xor_sync(0xffffffffu, sl0, d);
            sr0 += __shfl_xor_sync(0xffffffffu, sr0, d);
            sl1 += __shfl_xor_sync(0xffffffffu, sl1, d);
            sr1 += __shfl_xor_sync(0xffffffffu, sr1, d);
        }
        if ((lane & 3) == 0) {
            if (r0 < M) { el[r0] = sl0; er[r0] = sr0; }
            if (r1 < M) { el[r1] = sl1; er[r1] = sr1; }
        }
    }
}

// ---------------- CSR build ----------------
__global__ void hist_kernel(const int* __restrict__ dst, int* __restrict__ count) {
    int e = blockIdx.x * blockDim.x + threadIdx.x;
    if (e < EE) atomicAdd(&count[dst[e]], 1);
}

__global__ void scan1_kernel(const int* __restrict__ count, int* __restrict__ off,
                             int* __restrict__ bsum) {
    __shared__ int wsum[32];
    const int t = threadIdx.x;
    const int lane = t & 31, w = t >> 5;
    const int i = blockIdx.x * 1024 + t;
    int v = (i < NN) ? count[i] : 0;
    int incl = v;
    #pragma unroll
    for (int d = 1; d < 32; d <<= 1) {
        int x = __shfl_up_sync(0xffffffffu, incl, d);
        if (lane >= d) incl += x;
    }
    if (lane == 31) wsum[w] = incl;
    __syncthreads();
    if (w == 0) {
        int s = wsum[lane];
        #pragma unroll
        for (int d = 1; d < 32; d <<= 1) {
            int x = __shfl_up_sync(0xffffffffu, s, d);
            if (lane >= d) s += x;
        }
        wsum[lane] = s;
    }
    __syncthreads();
    int wpre = (w > 0) ? wsum[w - 1] : 0;
    if (i < NN) off[i] = wpre + incl - v;
    if (t == 0) bsum[blockIdx.x] = wsum[31];
}

__global__ void scan2_kernel(const int* __restrict__ bsum, int* __restrict__ boff,
                             int* __restrict__ off) {
    __shared__ int tmp[64];
    int t = threadIdx.x;
    int v = (t < NB) ? bsum[t] : 0;
    tmp[t] = v;
    __syncthreads();
    #pragma unroll
    for (int d = 1; d < 64; d <<= 1) {
        int x = (t >= d) ? tmp[t - d] : 0;
        __syncthreads();
        tmp[t] += x;
        __syncthreads();
    }
    if (t < NB) boff[t] = tmp[t] - v;
    if (t == 63) off[NN] = tmp[63];
}

__global__ void scan3_kernel(int* __restrict__ off, const int* __restrict__ boff,
                             int* __restrict__ cursor) {
    const int i = blockIdx.x * 1024 + threadIdx.x;
    if (i < NN) {
        int o = off[i] + boff[blockIdx.x];
        off[i] = o;
        cursor[i] = o;
    }
}

__global__ void scatter_kernel(const int* __restrict__ dst, const int* __restrict__ srcArr,
                               int* __restrict__ cursor, int* __restrict__ srcs) {
    int e = blockIdx.x * blockDim.x + threadIdx.x;
    if (e < EE) {
        int pos = atomicAdd(&cursor[dst[e]], 1);
        srcs[pos] = srcArr[e];
    }
}

// ---------------- per-node warp: SINGLE-PASS flash-style softmax + aggregate
__global__ void __launch_bounds__(256)
agg8_kernel(const __half* __restrict__ feat, const float* __restrict__ el,
            const float* __restrict__ er, const float* __restrict__ bias,
            __half* __restrict__ out, const int* __restrict__ off,
            const int* __restrict__ srcs) {
    int warp = (blockIdx.x * blockDim.x + threadIdx.x) >> 5;
    if (warp >= NN) return;
    const int lane = threadIdx.x & 31;
    const int n = warp;
    const int s = off[n], epnd = off[n + 1];
    const int hl = lane & 7;
    const int eslot = lane >> 3;
    const int myh = lane >> 2;
    const float er_h = er[n * NHEADS + hl];
    const __half* fbase = feat + lane * 8;

    float mx = -INFINITY;
    float sm = 0.f;
    float acc[8];
    #pragma unroll
    for (int q = 0; q < 8; q++) acc[q] = 0.f;

    int i = s;
    for (; i + 8 <= epnd; i += 8) {
        int s0 = srcs[i + eslot];
        int s1 = srcs[i + 4 + eslot];
        float v0 = el[s0 * NHEADS + hl] + er_h;
        float v1 = el[s1 * NHEADS + hl] + er_h;
        v0 = v0 > 0.f ? v0 : 0.2f * v0;
        v1 = v1 > 0.f ? v1 : 0.2f * v1;
        float bm = fmaxf(v0, v1);
        bm = fmaxf(bm, __shfl_xor_sync(0xffffffffu, bm, 8));
        bm = fmaxf(bm, __shfl_xor_sync(0xffffffffu, bm, 16));
        float m2 = fmaxf(mx, bm);
        float scale = safe_exp(mx - m2);
        float c0 = safe_exp(v0 - m2);
        float c1 = safe_exp(v1 - m2);
        sm = sm * scale + c0 + c1;
        mx = m2;
        float cs = __shfl_sync(0xffffffffu, scale, myh);
        float c[8]; int se[8];
        #pragma unroll
        for (int e = 0; e < 4; e++) {
            c[e]      = __shfl_sync(0xffffffffu, c0, e * 8 + myh);
            c[e + 4]  = __shfl_sync(0xffffffffu, c1, e * 8 + myh);
            se[e]     = __shfl_sync(0xffffffffu, s0, e * 8);
            se[e + 4] = __shfl_sync(0xffffffffu, s1, e * 8);
        }
        uint4 raw[8];
        #pragma unroll
        for (int e = 0; e < 8; e++)
            raw[e] = *(const uint4*)(fbase + (size_t)se[e] * FTOT);
        #pragma unroll
        for (int q = 0; q < 8; q++) acc[q] *= cs;
        #pragma unroll
        for (int e = 0; e < 8; e++) {
            const __half2* hp = (const __half2*)&raw[e];
            #pragma unroll
            for (int q = 0; q < 4; q++) {
                float2 f = __half22float2(hp[q]);
                acc[q * 2]     = fmaf(c[e], f.x, acc[q * 2]);
                acc[q * 2 + 1] = fmaf(c[e], f.y, acc[q * 2 + 1]);
            }
        }
    }
    for (; i + 4 <= epnd; i += 4) {
        int esrc = srcs[i + eslot];
        float v = el[esrc * NHEADS + hl] + er_h;
        v = v > 0.f ? v : 0.2f * v;
        float bm = v;
        bm = fmaxf(bm, __shfl_xor_sync(0xffffffffu, bm, 8));
        bm = fmaxf(bm, __shfl_xor_sync(0xffffffffu, bm, 16));
        float m2 = fmaxf(mx, bm);
        float scale = safe_exp(mx - m2);
        float coef = safe_exp(v - m2);
        sm = sm * scale + coef;
        mx = m2;
        float cs = __shfl_sync(0xffffffffu, scale, myh);
        float c[4]; int se[4];
        #pragma unroll
        for (int e = 0; e < 4; e++) {
            c[e]  = __shfl_sync(0xffffffffu, coef, e * 8 + myh);
            se[e] = __shfl_sync(0xffffffffu, esrc, e * 8);
        }
        uint4 raw[4];
        #pragma unroll
        for (int e = 0; e < 4; e++)
            raw[e] = *(const uint4*)(fbase + (size_t)se[e] * FTOT);
        #pragma unroll
        for (int q = 0; q < 8; q++) acc[q] *= cs;
        #pragma unroll
        for (int e = 0; e < 4; e++) {
            const __half2* hp = (const __half2*)&raw[e];
            #pragma unroll
            for (int q = 0; q < 4; q++) {
                float2 f = __half22float2(hp[q]);
                acc[q * 2]     = fmaf(c[e], f.x, acc[q * 2]);
                acc[q * 2 + 1] = fmaf(c[e], f.y, acc[q * 2 + 1]);
            }
        }
    }
    for (; i < epnd; i++) {
        int srcT = srcs[i];
        float v = el[srcT * NHEADS + hl] + er_h;
        v = v > 0.f ? v : 0.2f * v;
        float m2 = fmaxf(mx, v);
        float scale = safe_exp(mx - m2);
        float coef = safe_exp(v - m2);
        sm = sm * scale + (eslot == 0 ? coef : 0.f);
        mx = m2;
        float cs = __shfl_sync(0xffffffffu, scale, myh);
        float c  = __shfl_sync(0xffffffffu, coef, myh);
        uint4 raw = *(const uint4*)(fbase + (size_t)srcT * FTOT);
        const __half2* hp = (const __half2*)&raw;
        #pragma unroll
        for (int q = 0; q < 8; q++) acc[q] *= cs;
        #pragma unroll
        for (int q = 0; q < 4; q++) {
            float2 f = __half22float2(hp[q]);
            acc[q * 2]     = fmaf(c, f.x, acc[q * 2]);
            acc[q * 2 + 1] = fmaf(c, f.y, acc[q * 2 + 1]);
        }
    }
    sm += __shfl_xor_sync(0xffffffffu, sm, 8);
    sm += __shfl_xor_sync(0xffffffffu, sm, 16);
    float inv = 1.0f / (sm + 1e-9f);
    float cinv = __shfl_sync(0xffffffffu, inv, myh);
    float4 b0 = *(const float4*)(bias + lane * 8);
    float4 b1 = *(const float4*)(bias + lane * 8 + 4);
    float o[8];
    o[0] = acc[0] * cinv + b0.x; o[1] = acc[1] * cinv + b0.y;
    o[2] = acc[2] * cinv + b0.z; o[3] = acc[3] * cinv + b0.w;
    o[4] = acc[4] * cinv + b1.x; o[5] = acc[5] * cinv + b1.y;
    o[6] = acc[6] * cinv + b1.z; o[7] = acc[7] * cinv + b1.w;
    #pragma unroll
    for (int q = 0; q < 8; q++) o[q] = o[q] > 0.f ? o[q] : expm1f(o[q]);
    uint4 packed = make_uint4(pack2h(o[0], o[1]), pack2h(o[2], o[3]),
                              pack2h(o[4], o[5]), pack2h(o[6], o[7]));
    *(uint4*)(out + (size_t)n * FTOT + lane * 8) = packed;
}

// ---------------- final layer aggregate (1 head, D=32) ----------------
__global__ void __launch_bounds__(256)
agg1_kernel(const float* __restrict__ feat2, const float* __restrict__ el,
            const float* __restrict__ er, const float* __restrict__ bias,
            float* __restrict__ out, const int* __restrict__ off,
            const int* __restrict__ srcs) {
    int warp = (blockIdx.x * blockDim.x + threadIdx.x) >> 5;
    if (warp >= NN) return;
    const int lane = threadIdx.x & 31;
    const int n = warp;
    const int s = off[n], epnd = off[n + 1];
    const float er_n = er[n];

    float mx = -INFINITY, sm = 0.f;
    for (int i = s + lane; i < epnd; i += 32) {
        int src = srcs[i];
        float v = el[src] + er_n;
        v = v > 0.f ? v : 0.2f * v;
        float m2 = fmaxf(mx, v);
        sm = sm * safe_exp(mx - m2) + safe_exp(v - m2);
        mx = m2;
    }
    #pragma unroll
    for (int d = 16; d >= 1; d >>= 1) {
        float om = __shfl_xor_sync(0xffffffffu, mx, d);
        float os = __shfl_xor_sync(0xffffffffu, sm, d);
        float m2 = fmaxf(mx, om);
        sm = sm * safe_exp(mx - m2) + os * safe_exp(om - m2);
        mx = m2;
    }
    const float inv = 1.0f / (sm + 1e-9f);

    float acc = 0.f;
    for (int i = s; i < epnd; i++) {
        int src = srcs[i];
        float v = el[src] + er_n;
        v = v > 0.f ? v : 0.2f * v;
        float coef = safe_exp(v - mx) * inv;
        acc = fmaf(coef, feat2[(size_t)src * HIDD + lane], acc);
    }
    out[(size_t)n * HIDD + lane] = acc + bias[lane];
}

// ---------------- launch ----------------
extern "C" void kernel_launch(void* const* d_in, const int* in_sizes, int n_in,
                              void* d_out, int out_size) {
    const float* features = (const float*)d_in[0];
    const int*   src      = (const int*)d_in[1];
    const int*   dst      = (const int*)d_in[2];
    const float* W0  = (const float*)d_in[3];
    const float* al0 = (const float*)d_in[4];
    const float* ar0 = (const float*)d_in[5];
    const float* b0  = (const float*)d_in[6];
    const float* W1  = (const float*)d_in[7];
    const float* al1 = (const float*)d_in[8];
    const float* ar1 = (const float*)d_in[9];
    const float* b1  = (const float*)d_in[10];
    const float* W2  = (const float*)d_in[11];
    const float* al2 = (const float*)d_in[12];
    const float* ar2 = (const float*)d_in[13];
    const float* b2  = (const float*)d_in[14];
    float* out = (float*)d_out;

    __half *featH, *hH, *WH, *W2H;
    float *feat2, *el, *er;
    int *count, *off, *cursor, *srcs, *bsum, *boff;
    cudaGetSymbolAddress((void**)&featH,  g_featH);
    cudaGetSymbolAddress((void**)&hH,     g_hH);
    cudaGetSymbolAddress((void**)&WH,     g_WH);
    cudaGetSymbolAddress((void**)&W2H,    g_W2H);
    cudaGetSymbolAddress((void**)&feat2,  g_feat2);
    cudaGetSymbolAddress((void**)&el,     g_el);
    cudaGetSymbolAddress((void**)&er,     g_er);
    cudaGetSymbolAddress((void**)&count,  g_count);
    cudaGetSymbolAddress((void**)&off,    g_off);
    cudaGetSymbolAddress((void**)&cursor, g_cursor);
    cudaGetSymbolAddress((void**)&srcs,   g_srcs);
    cudaGetSymbolAddress((void**)&bsum,   g_bsum);
    cudaGetSymbolAddress((void**)&boff,   g_boff);
    __half* WH0 = WH;
    __half* WH1 = WH + FTOT * FTOT;

    cudaFuncSetAttribute(mma_gemm_kernel<float>,
                         cudaFuncAttributeMaxDynamicSharedMemorySize, GEMM_SMEM);
    cudaFuncSetAttribute(mma_gemm_kernel<__half>,
                         cudaFuncAttributeMaxDynamicSharedMemorySize, GEMM_SMEM);
    cudaFuncSetAttribute(mma_final_kernel,
                         cudaFuncAttributeMaxDynamicSharedMemorySize, FGEMM_SMEM);

    static cudaStream_t s2 = nullptr;
    static cudaEvent_t evFork = nullptr, evJoin = nullptr;
    if (s2 == nullptr) {
        cudaStreamCreateWithFlags(&s2, cudaStreamNonBlocking);
        cudaEventCreateWithFlags(&evFork, cudaEventDisableTiming);
        cudaEventCreateWithFlags(&evJoin, cudaEventDisableTiming);
    }

    // fork: CSR build on s2 runs concurrently with weight prep + GEMM0 on stream 0
    cudaEventRecord(evFork, 0);
    cudaStreamWaitEvent(s2, evFork, 0);
    cudaMemsetAsync(count, 0, NN * sizeof(int), s2);
    hist_kernel<<<(EE + 255) / 256, 256, 0, s2>>>(dst, count);
    scan1_kernel<<<NB, 1024, 0, s2>>>(count, off, bsum);
    scan2_kernel<<<1, 64, 0, s2>>>(bsum, boff, off);
    scan3_kernel<<<NB, 1024, 0, s2>>>(off, boff, cursor);
    scatter_kernel<<<(EE + 255) / 256, 256, 0, s2>>>(dst, src, cursor, srcs);
    cudaEventRecord(evJoin, s2);

    const int aggBlocks = (NN * 32 + 255) / 256;
    dim3 gemmGrid(2, (NN + 127) / 128);
    dim3 finalGrid(1, (NN + 255) / 256);

    // stream 0: weight prep + GEMM0
    wtrans_kernel<<<FTOT, FTOT>>>(W0, WH0);
    wtrans_kernel<<<FTOT, FTOT>>>(W1, WH1);
    wtrans2_kernel<<<HIDD, FTOT>>>(W2, W2H);
    mma_gemm_kernel<float><<<gemmGrid, 256, GEMM_SMEM>>>(features, WH0, featH, al0, ar0, el, er, NN);

    // join: agg8 needs the CSR
    cudaStreamWaitEvent(0, evJoin, 0);
    agg8_kernel<<<aggBlocks, 256>>>(featH, el, er, b0, hH, off, srcs);

    // layer 1
    mma_gemm_kernel<__half><<<gemmGrid, 256, GEMM_SMEM>>>(hH, WH1, featH, al1, ar1, el, er, NN);
    agg8_kernel<<<aggBlocks, 256>>>(featH, el, er, b1, hH, off, srcs);

    // layer 2 (mma, fused el/er)
    mma_final_kernel<<<finalGrid, 256, FGEMM_SMEM>>>(hH, W2H, feat2, al2, ar2, el, er, NN);
    agg1_kernel<<<aggBlocks, 256>>>(feat2, el, er, b2, out, off, srcs);
}